// round 1
// baseline (speedup 1.0000x reference)
#include <cuda_runtime.h>

// Problem shape (fixed): B=2, S=2048, D=2048, H=16, DK=128
constexpr int BATCH = 2;
constexpr int SEQ   = 2048;
constexpr int DMODEL= 2048;
constexpr int NH    = 16;
constexpr int HD    = 128;           // head dim
constexpr int QKVW  = 3 * DMODEL;    // 6144

// Scratch (static device globals: allocation-free per harness rules)
__device__ float g_qkv   [(long)BATCH * SEQ * QKVW];        // [B,S,6144]
__device__ float g_scores[(long)BATCH * NH * SEQ * SEQ];    // [B*H,S,S]
__device__ float g_attn  [(long)BATCH * SEQ * DMODEL];      // [B,S,D]

// ---------------------------------------------------------------------------
// Batched strided GEMM: C[m,n] = alpha * sum_k A[m,k]*B'[k,n]  (+ bias[n])
//   A is row-major [M,K] with leading dim lda.
//   If B_KMAJOR: B is [N,K] row-major (ldb = stride between n rows)  -> NT
//   else:       B is [K,N] row-major (ldb = stride between k rows)  -> NN
// Batch z decomposed as (zb = z/Hdiv, zh = z%Hdiv); each operand offset by
// zb*Out + zh*In. Tiles: BM=BN=128, BK=16, 256 threads, 8x8 per thread.
// ---------------------------------------------------------------------------
template<bool B_KMAJOR, bool HAS_BIAS>
__global__ void __launch_bounds__(256)
gemm_kernel(const float* __restrict__ A, const float* __restrict__ Bp,
            const float* __restrict__ bias, float* __restrict__ C,
            int K,
            int lda, int ldb, int ldc,
            long aOut, long aIn, long bOut, long bIn, long cOut, long cIn,
            int Hdiv, float alpha)
{
    __shared__ float As[16][132];
    __shared__ float Bs[16][132];

    const int z  = blockIdx.z;
    const int zb = z / Hdiv;
    const int zh = z % Hdiv;
    A  += zb * aOut + zh * aIn;
    Bp += zb * bOut + zh * bIn;
    C  += zb * cOut + zh * cIn;

    const int tid = threadIdx.x;
    const int tx  = tid & 15;     // n direction
    const int ty  = tid >> 4;     // m direction

    const float* Abase = A + (long)blockIdx.y * 128 * lda;

    float acc[8][8];
    #pragma unroll
    for (int i = 0; i < 8; i++)
        #pragma unroll
        for (int j = 0; j < 8; j++)
            acc[i][j] = 0.f;

    for (int kt = 0; kt < K; kt += 16) {
        // ---- load A tile [128 rows x 16 k] transposed into As[k][m] ----
        #pragma unroll
        for (int it = 0; it < 2; it++) {
            int f   = tid + it * 256;          // 512 float4s
            int row = f >> 2;
            int k4  = (f & 3) << 2;
            float4 v = *(const float4*)(Abase + (long)row * lda + kt + k4);
            As[k4 + 0][row] = v.x;
            As[k4 + 1][row] = v.y;
            As[k4 + 2][row] = v.z;
            As[k4 + 3][row] = v.w;
        }
        // ---- load B tile into Bs[k][n] ----
        if (B_KMAJOR) {
            const float* Bbase = Bp + (long)blockIdx.x * 128 * ldb;
            #pragma unroll
            for (int it = 0; it < 2; it++) {
                int f   = tid + it * 256;
                int row = f >> 2;              // n within tile
                int k4  = (f & 3) << 2;
                float4 v = *(const float4*)(Bbase + (long)row * ldb + kt + k4);
                Bs[k4 + 0][row] = v.x;
                Bs[k4 + 1][row] = v.y;
                Bs[k4 + 2][row] = v.z;
                Bs[k4 + 3][row] = v.w;
            }
        } else {
            #pragma unroll
            for (int it = 0; it < 2; it++) {
                int f  = tid + it * 256;
                int kr = f >> 5;               // k within tile
                int n4 = (f & 31) << 2;
                float4 v = *(const float4*)(Bp + (long)(kt + kr) * ldb
                                            + (long)blockIdx.x * 128 + n4);
                *(float4*)&Bs[kr][n4] = v;
            }
        }
        __syncthreads();

        #pragma unroll
        for (int k = 0; k < 16; k++) {
            float a[8], b[8];
            *(float4*)&a[0] = *(const float4*)&As[k][ty * 8];
            *(float4*)&a[4] = *(const float4*)&As[k][ty * 8 + 4];
            *(float4*)&b[0] = *(const float4*)&Bs[k][tx * 8];
            *(float4*)&b[4] = *(const float4*)&Bs[k][tx * 8 + 4];
            #pragma unroll
            for (int i = 0; i < 8; i++)
                #pragma unroll
                for (int j = 0; j < 8; j++)
                    acc[i][j] += a[i] * b[j];
        }
        __syncthreads();
    }

    const int m0 = blockIdx.y * 128 + ty * 8;
    const int n0 = blockIdx.x * 128 + tx * 8;

    float bv[8];
    #pragma unroll
    for (int j = 0; j < 8; j++)
        bv[j] = HAS_BIAS ? bias[n0 + j] : 0.f;

    #pragma unroll
    for (int i = 0; i < 8; i++) {
        float* crow = C + (long)(m0 + i) * ldc + n0;
        float4 o0, o1;
        o0.x = acc[i][0] * alpha + bv[0];
        o0.y = acc[i][1] * alpha + bv[1];
        o0.z = acc[i][2] * alpha + bv[2];
        o0.w = acc[i][3] * alpha + bv[3];
        o1.x = acc[i][4] * alpha + bv[4];
        o1.y = acc[i][5] * alpha + bv[5];
        o1.z = acc[i][6] * alpha + bv[6];
        o1.w = acc[i][7] * alpha + bv[7];
        *(float4*)(crow)     = o0;
        *(float4*)(crow + 4) = o1;
    }
}

// ---------------------------------------------------------------------------
// Row softmax over n columns, in place. One block (256 thr) per row.
// ---------------------------------------------------------------------------
__global__ void __launch_bounds__(256)
softmax_kernel(float* __restrict__ P, int n)
{
    const long row = blockIdx.x;
    float* p = P + row * (long)n;
    const int tid = threadIdx.x;
    __shared__ float red[8];

    // max
    float m = -3.0e38f;
    for (int i = tid; i < n; i += 256) m = fmaxf(m, p[i]);
    #pragma unroll
    for (int o = 16; o > 0; o >>= 1)
        m = fmaxf(m, __shfl_xor_sync(0xffffffffu, m, o));
    if ((tid & 31) == 0) red[tid >> 5] = m;
    __syncthreads();
    float mm = red[0];
    #pragma unroll
    for (int i = 1; i < 8; i++) mm = fmaxf(mm, red[i]);
    __syncthreads();

    // exp + sum
    float s = 0.f;
    for (int i = tid; i < n; i += 256) {
        float e = __expf(p[i] - mm);
        p[i] = e;
        s += e;
    }
    #pragma unroll
    for (int o = 16; o > 0; o >>= 1)
        s += __shfl_xor_sync(0xffffffffu, s, o);
    if ((tid & 31) == 0) red[tid >> 5] = s;
    __syncthreads();
    float tot = 0.f;
    #pragma unroll
    for (int i = 0; i < 8; i++) tot += red[i];

    const float inv = 1.f / tot;
    for (int i = tid; i < n; i += 256) p[i] *= inv;
}

// ---------------------------------------------------------------------------
extern "C" void kernel_launch(void* const* d_in, const int* in_sizes, int n_in,
                              void* d_out, int out_size)
{
    const float* x     = (const float*)d_in[0];
    // d_in[1] = mask (int32) — unused by the reference
    const float* w_qkv = (const float*)d_in[2];
    const float* b_qkv = (const float*)d_in[3];
    const float* w_o   = (const float*)d_in[4];
    const float* b_o   = (const float*)d_in[5];
    float* out = (float*)d_out;

    float *qkv, *scores, *attn;
    cudaGetSymbolAddress((void**)&qkv,    g_qkv);
    cudaGetSymbolAddress((void**)&scores, g_scores);
    cudaGetSymbolAddress((void**)&attn,   g_attn);

    const float inv_sqrt_dk = 0.08838834764831845f;  // 1/sqrt(128)

    // 1) QKV projection: [4096,2048] x [6144,2048]^T + b -> g_qkv [4096,6144]
    {
        dim3 grid(QKVW / 128, (BATCH * SEQ) / 128, 1);
        gemm_kernel<true, true><<<grid, 256>>>(
            x, w_qkv, b_qkv, qkv,
            DMODEL, DMODEL, DMODEL, QKVW,
            0, 0, 0, 0, 0, 0, 1, 1.0f);
    }

    // 2) scores = Q K^T / sqrt(dk): per (b,h)  M=N=2048, K=128
    {
        dim3 grid(SEQ / 128, SEQ / 128, BATCH * NH);
        gemm_kernel<true, false><<<grid, 256>>>(
            qkv /*Q base*/, qkv + HD /*K base*/, nullptr, scores,
            HD, QKVW, QKVW, SEQ,
            (long)SEQ * QKVW, 3 * HD,           // A: per-b, per-h
            (long)SEQ * QKVW, 3 * HD,           // B: per-b, per-h
            (long)NH * SEQ * SEQ, (long)SEQ * SEQ,
            NH, inv_sqrt_dk);
    }

    // 3) softmax rows
    softmax_kernel<<<BATCH * NH * SEQ, 256>>>(scores, SEQ);

    // 4) O = A V: per (b,h)  M=2048, N=128, K=2048  (B is K-row-major -> NN)
    {
        dim3 grid(1, SEQ / 128, BATCH * NH);
        gemm_kernel<false, false><<<grid, 256>>>(
            scores, qkv + 2 * HD /*V base*/, nullptr, attn,
            SEQ, SEQ, QKVW, DMODEL,
            (long)NH * SEQ * SEQ, (long)SEQ * SEQ,
            (long)SEQ * QKVW, 3 * HD,
            (long)SEQ * DMODEL, HD,
            NH, 1.0f);
    }

    // 5) output projection: [4096,2048] x [2048,2048]^T + b -> out
    {
        dim3 grid(DMODEL / 128, (BATCH * SEQ) / 128, 1);
        gemm_kernel<true, true><<<grid, 256>>>(
            attn, w_o, b_o, out,
            DMODEL, DMODEL, DMODEL, DMODEL,
            0, 0, 0, 0, 0, 0, 1, 1.0f);
    }
}

// round 2
// speedup vs baseline: 1.0005x; 1.0005x over previous
#include <cuda_runtime.h>

// Problem shape (fixed): B=2, S=2048, D=2048, H=16, DK=128
constexpr int BATCH = 2;
constexpr int SEQ   = 2048;
constexpr int DMODEL= 2048;
constexpr int NH    = 16;
constexpr int HD    = 128;           // head dim
constexpr int QKVW  = 3 * DMODEL;    // 6144

// Scratch (static device globals: allocation-free per harness rules)
__device__ float g_qkv   [(long)BATCH * SEQ * QKVW];        // [B,S,6144]
__device__ float g_scores[(long)BATCH * NH * SEQ * SEQ];    // [B*H,S,S]
__device__ float g_attn  [(long)BATCH * SEQ * DMODEL];      // [B,S,D]

// ---------------------------------------------------------------------------
// Batched strided GEMM: C[m,n] = alpha * sum_k A[m,k]*B'[k,n]  (+ bias[n])
//   A is row-major [M,K] with leading dim lda.
//   If B_KMAJOR: B is [N,K] row-major (ldb = stride between n rows)  -> NT
//   else:       B is [K,N] row-major (ldb = stride between k rows)  -> NN
// Batch z decomposed as (zb = z/Hdiv, zh = z%Hdiv); each operand offset by
// zb*Out + zh*In. Tiles: BM=BN=128, BK=16, 256 threads, 8x8 per thread.
// ---------------------------------------------------------------------------
template<bool B_KMAJOR, bool HAS_BIAS>
__global__ void __launch_bounds__(256)
gemm_kernel(const float* __restrict__ A, const float* __restrict__ Bp,
            const float* __restrict__ bias, float* __restrict__ C,
            int K,
            int lda, int ldb, int ldc,
            long aOut, long aIn, long bOut, long bIn, long cOut, long cIn,
            int Hdiv, float alpha)
{
    __shared__ float As[16][132];
    __shared__ float Bs[16][132];

    const int z  = blockIdx.z;
    const int zb = z / Hdiv;
    const int zh = z % Hdiv;
    A  += zb * aOut + zh * aIn;
    Bp += zb * bOut + zh * bIn;
    C  += zb * cOut + zh * cIn;

    const int tid = threadIdx.x;
    const int tx  = tid & 15;     // n direction
    const int ty  = tid >> 4;     // m direction

    const float* Abase = A + (long)blockIdx.y * 128 * lda;

    float acc[8][8];
    #pragma unroll
    for (int i = 0; i < 8; i++)
        #pragma unroll
        for (int j = 0; j < 8; j++)
            acc[i][j] = 0.f;

    for (int kt = 0; kt < K; kt += 16) {
        // ---- load A tile [128 rows x 16 k] transposed into As[k][m] ----
        #pragma unroll
        for (int it = 0; it < 2; it++) {
            int f   = tid + it * 256;          // 512 float4s
            int row = f >> 2;
            int k4  = (f & 3) << 2;
            float4 v = *(const float4*)(Abase + (long)row * lda + kt + k4);
            As[k4 + 0][row] = v.x;
            As[k4 + 1][row] = v.y;
            As[k4 + 2][row] = v.z;
            As[k4 + 3][row] = v.w;
        }
        // ---- load B tile into Bs[k][n] ----
        if (B_KMAJOR) {
            const float* Bbase = Bp + (long)blockIdx.x * 128 * ldb;
            #pragma unroll
            for (int it = 0; it < 2; it++) {
                int f   = tid + it * 256;
                int row = f >> 2;              // n within tile
                int k4  = (f & 3) << 2;
                float4 v = *(const float4*)(Bbase + (long)row * ldb + kt + k4);
                Bs[k4 + 0][row] = v.x;
                Bs[k4 + 1][row] = v.y;
                Bs[k4 + 2][row] = v.z;
                Bs[k4 + 3][row] = v.w;
            }
        } else {
            #pragma unroll
            for (int it = 0; it < 2; it++) {
                int f  = tid + it * 256;
                int kr = f >> 5;               // k within tile
                int n4 = (f & 31) << 2;
                float4 v = *(const float4*)(Bp + (long)(kt + kr) * ldb
                                            + (long)blockIdx.x * 128 + n4);
                *(float4*)&Bs[kr][n4] = v;
            }
        }
        __syncthreads();

        #pragma unroll
        for (int k = 0; k < 16; k++) {
            float a[8], b[8];
            *(float4*)&a[0] = *(const float4*)&As[k][ty * 8];
            *(float4*)&a[4] = *(const float4*)&As[k][ty * 8 + 4];
            *(float4*)&b[0] = *(const float4*)&Bs[k][tx * 8];
            *(float4*)&b[4] = *(const float4*)&Bs[k][tx * 8 + 4];
            #pragma unroll
            for (int i = 0; i < 8; i++)
                #pragma unroll
                for (int j = 0; j < 8; j++)
                    acc[i][j] += a[i] * b[j];
        }
        __syncthreads();
    }

    const int m0 = blockIdx.y * 128 + ty * 8;
    const int n0 = blockIdx.x * 128 + tx * 8;

    float bv[8];
    #pragma unroll
    for (int j = 0; j < 8; j++)
        bv[j] = HAS_BIAS ? bias[n0 + j] : 0.f;

    #pragma unroll
    for (int i = 0; i < 8; i++) {
        float* crow = C + (long)(m0 + i) * ldc + n0;
        float4 o0, o1;
        o0.x = acc[i][0] * alpha + bv[0];
        o0.y = acc[i][1] * alpha + bv[1];
        o0.z = acc[i][2] * alpha + bv[2];
        o0.w = acc[i][3] * alpha + bv[3];
        o1.x = acc[i][4] * alpha + bv[4];
        o1.y = acc[i][5] * alpha + bv[5];
        o1.z = acc[i][6] * alpha + bv[6];
        o1.w = acc[i][7] * alpha + bv[7];
        *(float4*)(crow)     = o0;
        *(float4*)(crow + 4) = o1;
    }
}

// ---------------------------------------------------------------------------
// Row softmax over n columns, in place. One block (256 thr) per row.
// ---------------------------------------------------------------------------
__global__ void __launch_bounds__(256)
softmax_kernel(float* __restrict__ P, int n)
{
    const long row = blockIdx.x;
    float* p = P + row * (long)n;
    const int tid = threadIdx.x;
    __shared__ float red[8];

    // max
    float m = -3.0e38f;
    for (int i = tid; i < n; i += 256) m = fmaxf(m, p[i]);
    #pragma unroll
    for (int o = 16; o > 0; o >>= 1)
        m = fmaxf(m, __shfl_xor_sync(0xffffffffu, m, o));
    if ((tid & 31) == 0) red[tid >> 5] = m;
    __syncthreads();
    float mm = red[0];
    #pragma unroll
    for (int i = 1; i < 8; i++) mm = fmaxf(mm, red[i]);
    __syncthreads();

    // exp + sum
    float s = 0.f;
    for (int i = tid; i < n; i += 256) {
        float e = __expf(p[i] - mm);
        p[i] = e;
        s += e;
    }
    #pragma unroll
    for (int o = 16; o > 0; o >>= 1)
        s += __shfl_xor_sync(0xffffffffu, s, o);
    if ((tid & 31) == 0) red[tid >> 5] = s;
    __syncthreads();
    float tot = 0.f;
    #pragma unroll
    for (int i = 0; i < 8; i++) tot += red[i];

    const float inv = 1.f / tot;
    for (int i = tid; i < n; i += 256) p[i] *= inv;
}

// ---------------------------------------------------------------------------
extern "C" void kernel_launch(void* const* d_in, const int* in_sizes, int n_in,
                              void* d_out, int out_size)
{
    const float* x     = (const float*)d_in[0];
    // d_in[1] = mask (int32) — unused by the reference
    const float* w_qkv = (const float*)d_in[2];
    const float* b_qkv = (const float*)d_in[3];
    const float* w_o   = (const float*)d_in[4];
    const float* b_o   = (const float*)d_in[5];
    float* out = (float*)d_out;

    float *qkv, *scores, *attn;
    cudaGetSymbolAddress((void**)&qkv,    g_qkv);
    cudaGetSymbolAddress((void**)&scores, g_scores);
    cudaGetSymbolAddress((void**)&attn,   g_attn);

    const float inv_sqrt_dk = 0.08838834764831845f;  // 1/sqrt(128)

    // 1) QKV projection: [4096,2048] x [6144,2048]^T + b -> g_qkv [4096,6144]
    {
        dim3 grid(QKVW / 128, (BATCH * SEQ) / 128, 1);
        gemm_kernel<true, true><<<grid, 256>>>(
            x, w_qkv, b_qkv, qkv,
            DMODEL, DMODEL, DMODEL, QKVW,
            0, 0, 0, 0, 0, 0, 1, 1.0f);
    }

    // 2) scores = Q K^T / sqrt(dk): per (b,h)  M=N=2048, K=128
    {
        dim3 grid(SEQ / 128, SEQ / 128, BATCH * NH);
        gemm_kernel<true, false><<<grid, 256>>>(
            qkv /*Q base*/, qkv + HD /*K base*/, nullptr, scores,
            HD, QKVW, QKVW, SEQ,
            (long)SEQ * QKVW, 3 * HD,           // A: per-b, per-h
            (long)SEQ * QKVW, 3 * HD,           // B: per-b, per-h
            (long)NH * SEQ * SEQ, (long)SEQ * SEQ,
            NH, inv_sqrt_dk);
    }

    // 3) softmax rows
    softmax_kernel<<<BATCH * NH * SEQ, 256>>>(scores, SEQ);

    // 4) O = A V: per (b,h)  M=2048, N=128, K=2048  (B is K-row-major -> NN)
    {
        dim3 grid(1, SEQ / 128, BATCH * NH);
        gemm_kernel<false, false><<<grid, 256>>>(
            scores, qkv + 2 * HD /*V base*/, nullptr, attn,
            SEQ, SEQ, QKVW, DMODEL,
            (long)NH * SEQ * SEQ, (long)SEQ * SEQ,
            (long)SEQ * QKVW, 3 * HD,
            (long)SEQ * DMODEL, HD,
            NH, 1.0f);
    }

    // 5) output projection: [4096,2048] x [2048,2048]^T + b -> out
    {
        dim3 grid(DMODEL / 128, (BATCH * SEQ) / 128, 1);
        gemm_kernel<true, true><<<grid, 256>>>(
            attn, w_o, b_o, out,
            DMODEL, DMODEL, DMODEL, DMODEL,
            0, 0, 0, 0, 0, 0, 1, 1.0f);
    }
}

// round 4
// speedup vs baseline: 2.2524x; 2.2512x over previous
#include <cuda_runtime.h>
#include <cuda_bf16.h>
#include <cstdint>

// Problem shape (fixed): B=2, S=2048, D=2048, H=16, DK=128
constexpr int BATCH  = 2;
constexpr int SEQ    = 2048;
constexpr int DMODEL = 2048;
constexpr int NH     = 16;
constexpr int HD     = 128;
constexpr int QKVW   = 3 * DMODEL;   // 6144
constexpr int BH     = BATCH * NH;   // 32

// ---------------------------------------------------------------------------
// Scratch (device globals — allocation-free per harness rules)
// ---------------------------------------------------------------------------
__device__ __nv_bfloat16 g_xsHi [(long)BATCH * SEQ * DMODEL];
__device__ __nv_bfloat16 g_xsLo [(long)BATCH * SEQ * DMODEL];
__device__ __nv_bfloat16 g_wqHi [(long)QKVW * DMODEL];
__device__ __nv_bfloat16 g_wqLo [(long)QKVW * DMODEL];
__device__ __nv_bfloat16 g_woHi [(long)DMODEL * DMODEL];
__device__ __nv_bfloat16 g_woLo [(long)DMODEL * DMODEL];
__device__ __nv_bfloat16 g_qkvHi[(long)BATCH * SEQ * QKVW];
__device__ __nv_bfloat16 g_qkvLo[(long)BATCH * SEQ * QKVW];
__device__ __nv_bfloat16 g_vtHi [(long)BH * HD * SEQ];
__device__ __nv_bfloat16 g_vtLo [(long)BH * HD * SEQ];
__device__ float         g_scores[(long)BH * SEQ * SEQ];
__device__ __nv_bfloat16 g_pHi [(long)BH * SEQ * SEQ];
__device__ __nv_bfloat16 g_pLo [(long)BH * SEQ * SEQ];
__device__ __nv_bfloat16 g_atHi[(long)BATCH * SEQ * DMODEL];
__device__ __nv_bfloat16 g_atLo[(long)BATCH * SEQ * DMODEL];

// ---------------------------------------------------------------------------
// helpers
// ---------------------------------------------------------------------------
__device__ __forceinline__ uint32_t smem_u32(const void* p) {
    uint32_t a;
    asm("{ .reg .u64 t; cvta.to.shared.u64 t, %1; cvt.u32.u64 %0, t; }"
        : "=r"(a) : "l"(p));
    return a;
}
__device__ __forceinline__ void cp16(uint32_t saddr, const void* g) {
    asm volatile("cp.async.cg.shared.global [%0], [%1], 16;" :: "r"(saddr), "l"(g));
}
#define CP_COMMIT() asm volatile("cp.async.commit_group;" ::: "memory")
#define CP_WAIT1()  asm volatile("cp.async.wait_group 1;" ::: "memory")

__device__ __forceinline__ void ldsm_x4(uint32_t addr, uint32_t& r0, uint32_t& r1,
                                        uint32_t& r2, uint32_t& r3) {
    asm volatile("ldmatrix.sync.aligned.m8n8.x4.shared.b16 {%0,%1,%2,%3}, [%4];"
                 : "=r"(r0), "=r"(r1), "=r"(r2), "=r"(r3) : "r"(addr));
}
__device__ __forceinline__ void mma_bf16(float* c, const uint32_t* a, const uint32_t* b) {
    asm volatile(
        "mma.sync.aligned.m16n8k16.row.col.f32.bf16.bf16.f32 "
        "{%0,%1,%2,%3}, {%4,%5,%6,%7}, {%8,%9}, {%0,%1,%2,%3};"
        : "+f"(c[0]), "+f"(c[1]), "+f"(c[2]), "+f"(c[3])
        : "r"(a[0]), "r"(a[1]), "r"(a[2]), "r"(a[3]), "r"(b[0]), "r"(b[1]));
}

// ---------------------------------------------------------------------------
// HMMA GEMM: C[m,n] = sum_k (Ahi+Alo)[m,k]*(Bhi+Blo)[n,k]  (bf16x3 split)
// A row-major [M,K] (lda), B row-major [N,K] (ldb)  -> NT
// CTA tile 128x128, BK=32, 3-stage cp.async, 8 warps (2x4), warp tile 64x32.
// SMEM rows padded to 80B -> conflict-free ldmatrix.
// ---------------------------------------------------------------------------
constexpr int ROWB    = 80;            // 32 bf16 = 64B data + 16B pad
constexpr int MAT_B   = 128 * ROWB;    // 10240
constexpr int STAGE_B = 4 * MAT_B;     // Ahi, Alo, Bhi, Blo = 40960
constexpr int SMEM_TOTAL = 3 * STAGE_B; // 122880

template<bool HILO, bool BIAS>
__global__ void __launch_bounds__(256)
tc_gemm(const __nv_bfloat16* __restrict__ aHi, const __nv_bfloat16* __restrict__ aLo,
        const __nv_bfloat16* __restrict__ bHi, const __nv_bfloat16* __restrict__ bLo,
        const float* __restrict__ bias,
        float* __restrict__ cF,
        __nv_bfloat16* __restrict__ cHi, __nv_bfloat16* __restrict__ cLo,
        int K, int lda, int ldb, int ldc,
        long aOut, long aIn, long bOut, long bIn, long cOut, long cIn,
        int Hdiv, float alpha)
{
    extern __shared__ __align__(128) char smem[];
    const uint32_t sb = smem_u32(smem);
    const int tid  = threadIdx.x;
    const int wid  = tid >> 5, lane = tid & 31;

    const int z  = blockIdx.z;
    const int zb = z / Hdiv, zh = z % Hdiv;
    const size_t aoff = (size_t)zb * aOut + (size_t)zh * aIn + (size_t)blockIdx.y * 128 * lda;
    const size_t boff = (size_t)zb * bOut + (size_t)zh * bIn + (size_t)blockIdx.x * 128 * ldb;
    aHi += aoff; aLo += aoff; bHi += boff; bLo += boff;

    // loader mapping: 2 chunks per matrix per thread
    const int l_row0 = tid >> 2;          // chunk idx = tid -> row tid/4, c tid%4
    const int l_c0   = tid & 3;
    const int l_row1 = (tid + 256) >> 2;
    const int l_c1   = tid & 3;           // (tid+256)&3 == tid&3

    #define LOAD_STAGE(kt, slot)                                                  \
    do {                                                                          \
        const uint32_t s_ = sb + (slot) * STAGE_B;                                \
        const int kb_ = (kt) * 32;                                                \
        cp16(s_ + l_row0*ROWB + l_c0*16,           aHi + (size_t)l_row0*lda + kb_ + l_c0*8); \
        cp16(s_ + l_row1*ROWB + l_c1*16,           aHi + (size_t)l_row1*lda + kb_ + l_c1*8); \
        cp16(s_ + MAT_B + l_row0*ROWB + l_c0*16,   aLo + (size_t)l_row0*lda + kb_ + l_c0*8); \
        cp16(s_ + MAT_B + l_row1*ROWB + l_c1*16,   aLo + (size_t)l_row1*lda + kb_ + l_c1*8); \
        cp16(s_ + 2*MAT_B + l_row0*ROWB + l_c0*16, bHi + (size_t)l_row0*ldb + kb_ + l_c0*8); \
        cp16(s_ + 2*MAT_B + l_row1*ROWB + l_c1*16, bHi + (size_t)l_row1*ldb + kb_ + l_c1*8); \
        cp16(s_ + 3*MAT_B + l_row0*ROWB + l_c0*16, bLo + (size_t)l_row0*ldb + kb_ + l_c0*8); \
        cp16(s_ + 3*MAT_B + l_row1*ROWB + l_c1*16, bLo + (size_t)l_row1*ldb + kb_ + l_c1*8); \
    } while (0)

    // warp tile offsets
    const int wm = (wid >> 2) * 64;       // m offset in CTA tile
    const int wn = (wid & 3) * 32;        // n offset

    // ldmatrix per-thread base offsets (within a stage)
    const int sel    = lane >> 3;
    const int within = lane & 7;
    const uint32_t aBase = (uint32_t)((wm + within + (sel & 1) * 8) * ROWB + (sel >> 1) * 16);
    const uint32_t bBase = (uint32_t)(2 * MAT_B + (wn + within + (sel >> 1) * 8) * ROWB + (sel & 1) * 16);

    float acc[4][4][4];
    #pragma unroll
    for (int i = 0; i < 4; i++)
        #pragma unroll
        for (int j = 0; j < 4; j++)
            #pragma unroll
            for (int r = 0; r < 4; r++)
                acc[i][j][r] = 0.f;

    const int nk = K >> 5;

    LOAD_STAGE(0, 0); CP_COMMIT();
    if (nk > 1) LOAD_STAGE(1, 1);
    CP_COMMIT();
    CP_WAIT1();
    __syncthreads();

    for (int kt = 0; kt < nk; ++kt) {
        const uint32_t sS = sb + (kt % 3) * STAGE_B;
        #pragma unroll
        for (int ks = 0; ks < 2; ks++) {
            uint32_t aH[4][4], aL[4][4], bH[4][2], bL[4][2];
            #pragma unroll
            for (int mt = 0; mt < 4; mt++) {
                uint32_t ad = sS + aBase + mt * (16 * ROWB) + ks * 32;
                ldsm_x4(ad,         aH[mt][0], aH[mt][1], aH[mt][2], aH[mt][3]);
                ldsm_x4(ad + MAT_B, aL[mt][0], aL[mt][1], aL[mt][2], aL[mt][3]);
            }
            #pragma unroll
            for (int p = 0; p < 2; p++) {
                uint32_t bd = sS + bBase + p * (16 * ROWB) + ks * 32;
                ldsm_x4(bd,         bH[2*p][0], bH[2*p][1], bH[2*p+1][0], bH[2*p+1][1]);
                ldsm_x4(bd + MAT_B, bL[2*p][0], bL[2*p][1], bL[2*p+1][0], bL[2*p+1][1]);
            }
            #pragma unroll
            for (int mt = 0; mt < 4; mt++)
                #pragma unroll
                for (int nt = 0; nt < 4; nt++) {
                    mma_bf16(acc[mt][nt], aH[mt], bH[nt]);
                    mma_bf16(acc[mt][nt], aH[mt], bL[nt]);
                    mma_bf16(acc[mt][nt], aL[mt], bH[nt]);
                }
        }
        if (kt + 2 < nk) LOAD_STAGE(kt + 2, (kt + 2) % 3);
        CP_COMMIT();
        CP_WAIT1();
        __syncthreads();
    }

    // epilogue
    const size_t coff = (size_t)zb * cOut + (size_t)zh * cIn;
    const int gr = blockIdx.y * 128 + wm + (lane >> 2);
    const int gc = blockIdx.x * 128 + wn + (lane & 3) * 2;

    #pragma unroll
    for (int mt = 0; mt < 4; mt++) {
        #pragma unroll
        for (int nt = 0; nt < 4; nt++) {
            const int col = gc + nt * 8;
            float b0 = 0.f, b1 = 0.f;
            if (BIAS) { b0 = bias[col]; b1 = bias[col + 1]; }
            #pragma unroll
            for (int half = 0; half < 2; half++) {
                const int row = gr + mt * 16 + half * 8;
                float v0 = acc[mt][nt][half * 2]     * alpha + b0;
                float v1 = acc[mt][nt][half * 2 + 1] * alpha + b1;
                if (HILO) {
                    __nv_bfloat16 h0 = __float2bfloat16(v0);
                    __nv_bfloat16 h1 = __float2bfloat16(v1);
                    __nv_bfloat16 l0 = __float2bfloat16(v0 - __bfloat162float(h0));
                    __nv_bfloat16 l1 = __float2bfloat16(v1 - __bfloat162float(h1));
                    *(__nv_bfloat162*)(cHi + coff + (size_t)row * ldc + col) =
                        __halves2bfloat162(h0, h1);
                    *(__nv_bfloat162*)(cLo + coff + (size_t)row * ldc + col) =
                        __halves2bfloat162(l0, l1);
                } else {
                    float2 v; v.x = v0; v.y = v1;
                    *(float2*)(cF + coff + (size_t)row * ldc + col) = v;
                }
            }
        }
    }
    #undef LOAD_STAGE
}

// ---------------------------------------------------------------------------
// fp32 -> bf16 hi/lo split (elementwise, float4)
// ---------------------------------------------------------------------------
__global__ void __launch_bounds__(256)
split_kernel(const float* __restrict__ in, __nv_bfloat16* __restrict__ hi,
             __nv_bfloat16* __restrict__ lo)
{
    const long i = (long)blockIdx.x * 256 + threadIdx.x;   // float4 index
    float4 v = ((const float4*)in)[i];
    __nv_bfloat16 h0 = __float2bfloat16(v.x), h1 = __float2bfloat16(v.y);
    __nv_bfloat16 h2 = __float2bfloat16(v.z), h3 = __float2bfloat16(v.w);
    __nv_bfloat16 l0 = __float2bfloat16(v.x - __bfloat162float(h0));
    __nv_bfloat16 l1 = __float2bfloat16(v.y - __bfloat162float(h1));
    __nv_bfloat16 l2 = __float2bfloat16(v.z - __bfloat162float(h2));
    __nv_bfloat16 l3 = __float2bfloat16(v.w - __bfloat162float(h3));
    ((__nv_bfloat162*)hi)[i * 2]     = __halves2bfloat162(h0, h1);
    ((__nv_bfloat162*)hi)[i * 2 + 1] = __halves2bfloat162(h2, h3);
    ((__nv_bfloat162*)lo)[i * 2]     = __halves2bfloat162(l0, l1);
    ((__nv_bfloat162*)lo)[i * 2 + 1] = __halves2bfloat162(l2, l3);
}

// ---------------------------------------------------------------------------
// V transpose: qkv hi/lo (v slice) -> Vt hi/lo [z=bh][d][s]
// ---------------------------------------------------------------------------
__global__ void __launch_bounds__(256)
transpose_v(const __nv_bfloat16* __restrict__ qH, const __nv_bfloat16* __restrict__ qL,
            __nv_bfloat16* __restrict__ vH, __nv_bfloat16* __restrict__ vL)
{
    __shared__ __nv_bfloat16 tH[32][33], tL[32][33];
    const int z = blockIdx.z, b = z >> 4, h = z & 15;
    const int s0 = blockIdx.x * 32, d0 = blockIdx.y * 32;
    const int tx = threadIdx.x & 31, ty = threadIdx.x >> 5;   // 32 x 8
    const size_t ibase = (size_t)b * SEQ * QKVW + (size_t)h * 384 + 256;
    #pragma unroll
    for (int i = 0; i < 4; i++) {
        int s = s0 + ty + i * 8;
        tH[ty + i * 8][tx] = qH[ibase + (size_t)s * QKVW + d0 + tx];
        tL[ty + i * 8][tx] = qL[ibase + (size_t)s * QKVW + d0 + tx];
    }
    __syncthreads();
    const size_t obase = (size_t)z * HD * SEQ;
    #pragma unroll
    for (int i = 0; i < 4; i++) {
        int d = d0 + ty + i * 8;
        vH[obase + (size_t)d * SEQ + s0 + tx] = tH[tx][ty + i * 8];
        vL[obase + (size_t)d * SEQ + s0 + tx] = tL[tx][ty + i * 8];
    }
}

// ---------------------------------------------------------------------------
// scaled softmax: P = softmax(alpha * scores_row) -> bf16 hi/lo
// ---------------------------------------------------------------------------
__global__ void __launch_bounds__(256)
softmax_split(const float* __restrict__ S_, __nv_bfloat16* __restrict__ PH,
              __nv_bfloat16* __restrict__ PL)
{
    const size_t row = blockIdx.x;
    const float4* p4 = (const float4*)(S_ + row * SEQ);
    const int tid = threadIdx.x;
    __shared__ float red[8];
    const float alpha = 0.08838834764831845f;   // 1/sqrt(128)

    float4 a = p4[tid], b = p4[tid + 256];
    float m = fmaxf(fmaxf(fmaxf(a.x, a.y), fmaxf(a.z, a.w)),
                    fmaxf(fmaxf(b.x, b.y), fmaxf(b.z, b.w)));
    #pragma unroll
    for (int o = 16; o > 0; o >>= 1) m = fmaxf(m, __shfl_xor_sync(~0u, m, o));
    if ((tid & 31) == 0) red[tid >> 5] = m;
    __syncthreads();
    float mm = red[0];
    #pragma unroll
    for (int i = 1; i < 8; i++) mm = fmaxf(mm, red[i]);
    __syncthreads();

    float e[8];
    e[0] = __expf(alpha * (a.x - mm)); e[1] = __expf(alpha * (a.y - mm));
    e[2] = __expf(alpha * (a.z - mm)); e[3] = __expf(alpha * (a.w - mm));
    e[4] = __expf(alpha * (b.x - mm)); e[5] = __expf(alpha * (b.y - mm));
    e[6] = __expf(alpha * (b.z - mm)); e[7] = __expf(alpha * (b.w - mm));
    float s = e[0] + e[1] + e[2] + e[3] + e[4] + e[5] + e[6] + e[7];
    #pragma unroll
    for (int o = 16; o > 0; o >>= 1) s += __shfl_xor_sync(~0u, s, o);
    if ((tid & 31) == 0) red[tid >> 5] = s;
    __syncthreads();
    float tot = 0.f;
    #pragma unroll
    for (int i = 0; i < 8; i++) tot += red[i];
    const float inv = 1.f / tot;

    __nv_bfloat162* ph2 = (__nv_bfloat162*)(PH + row * SEQ);
    __nv_bfloat162* pl2 = (__nv_bfloat162*)(PL + row * SEQ);
    #pragma unroll
    for (int g = 0; g < 2; g++) {
        int base = (tid + g * 256) * 4;
        #pragma unroll
        for (int j = 0; j < 4; j += 2) {
            float v0 = e[g * 4 + j] * inv, v1 = e[g * 4 + j + 1] * inv;
            __nv_bfloat16 h0 = __float2bfloat16(v0), h1 = __float2bfloat16(v1);
            __nv_bfloat16 l0 = __float2bfloat16(v0 - __bfloat162float(h0));
            __nv_bfloat16 l1 = __float2bfloat16(v1 - __bfloat162float(h1));
            ph2[(base + j) >> 1] = __halves2bfloat162(h0, h1);
            pl2[(base + j) >> 1] = __halves2bfloat162(l0, l1);
        }
    }
}

// ---------------------------------------------------------------------------
extern "C" void kernel_launch(void* const* d_in, const int* in_sizes, int n_in,
                              void* d_out, int out_size)
{
    const float* x     = (const float*)d_in[0];
    const float* w_qkv = (const float*)d_in[2];
    const float* b_qkv = (const float*)d_in[3];
    const float* w_o   = (const float*)d_in[4];
    const float* b_o   = (const float*)d_in[5];
    float* out = (float*)d_out;

    __nv_bfloat16 *xsH, *xsL, *wqH, *wqL, *woH, *woL, *qkH, *qkL;
    __nv_bfloat16 *vtH, *vtL, *pH, *pL, *atH, *atL;
    float* scores;
    cudaGetSymbolAddress((void**)&xsH, g_xsHi);  cudaGetSymbolAddress((void**)&xsL, g_xsLo);
    cudaGetSymbolAddress((void**)&wqH, g_wqHi);  cudaGetSymbolAddress((void**)&wqL, g_wqLo);
    cudaGetSymbolAddress((void**)&woH, g_woHi);  cudaGetSymbolAddress((void**)&woL, g_woLo);
    cudaGetSymbolAddress((void**)&qkH, g_qkvHi); cudaGetSymbolAddress((void**)&qkL, g_qkvLo);
    cudaGetSymbolAddress((void**)&vtH, g_vtHi);  cudaGetSymbolAddress((void**)&vtL, g_vtLo);
    cudaGetSymbolAddress((void**)&pH,  g_pHi);   cudaGetSymbolAddress((void**)&pL,  g_pLo);
    cudaGetSymbolAddress((void**)&atH, g_atHi);  cudaGetSymbolAddress((void**)&atL, g_atLo);
    cudaGetSymbolAddress((void**)&scores, g_scores);

    cudaFuncSetAttribute(tc_gemm<true,  true >, cudaFuncAttributeMaxDynamicSharedMemorySize, SMEM_TOTAL);
    cudaFuncSetAttribute(tc_gemm<false, false>, cudaFuncAttributeMaxDynamicSharedMemorySize, SMEM_TOTAL);
    cudaFuncSetAttribute(tc_gemm<true,  false>, cudaFuncAttributeMaxDynamicSharedMemorySize, SMEM_TOTAL);
    cudaFuncSetAttribute(tc_gemm<false, true >, cudaFuncAttributeMaxDynamicSharedMemorySize, SMEM_TOTAL);

    // 0) split inputs
    split_kernel<<<(long)BATCH*SEQ*DMODEL/1024, 256>>>(x,     xsH, xsL);
    split_kernel<<<(long)QKVW*DMODEL/1024,      256>>>(w_qkv, wqH, wqL);
    split_kernel<<<(long)DMODEL*DMODEL/1024,    256>>>(w_o,   woH, woL);

    // 1) QKV projection -> qkv hi/lo (bias fused)
    {
        dim3 grid(QKVW / 128, (BATCH * SEQ) / 128, 1);
        tc_gemm<true, true><<<grid, 256, SMEM_TOTAL>>>(
            xsH, xsL, wqH, wqL, b_qkv, nullptr, qkH, qkL,
            DMODEL, DMODEL, DMODEL, QKVW,
            0, 0, 0, 0, 0, 0, 1, 1.0f);
    }

    // 2) V transpose -> Vt hi/lo
    transpose_v<<<dim3(SEQ / 32, HD / 32, BH), 256>>>(qkH, qkL, vtH, vtL);

    // 3) scores = Q K^T (raw; scale folded into softmax)
    {
        dim3 grid(SEQ / 128, SEQ / 128, BH);
        tc_gemm<false, false><<<grid, 256, SMEM_TOTAL>>>(
            qkH, qkL, qkH + HD, qkL + HD, nullptr, scores, nullptr, nullptr,
            HD, QKVW, QKVW, SEQ,
            (long)SEQ * QKVW, 384, (long)SEQ * QKVW, 384,
            (long)NH * SEQ * SEQ, (long)SEQ * SEQ,
            NH, 1.0f);
    }

    // 4) softmax(alpha * s) -> P hi/lo
    softmax_split<<<(long)BH * SEQ, 256>>>(scores, pH, pL);

    // 5) O = P V -> attn hi/lo
    {
        dim3 grid(1, SEQ / 128, BH);
        tc_gemm<true, false><<<grid, 256, SMEM_TOTAL>>>(
            pH, pL, vtH, vtL, nullptr, nullptr, atH, atL,
            SEQ, SEQ, SEQ, DMODEL,
            (long)NH * SEQ * SEQ, (long)SEQ * SEQ,
            (long)NH * HD * SEQ, (long)HD * SEQ,
            (long)SEQ * DMODEL, HD,
            NH, 1.0f);
    }

    // 6) output projection (bias fused) -> out fp32
    {
        dim3 grid(DMODEL / 128, (BATCH * SEQ) / 128, 1);
        tc_gemm<false, true><<<grid, 256, SMEM_TOTAL>>>(
            atH, atL, woH, woL, b_o, out, nullptr, nullptr,
            DMODEL, DMODEL, DMODEL, DMODEL,
            0, 0, 0, 0, 0, 0, 1, 1.0f);
    }
}

// round 5
// speedup vs baseline: 2.6286x; 1.1670x over previous
#include <cuda_runtime.h>
#include <cuda_bf16.h>
#include <cstdint>

// Problem shape (fixed): B=2, S=2048, D=2048, H=16, DK=128
constexpr int BATCH  = 2;
constexpr int SEQ    = 2048;
constexpr int DMODEL = 2048;
constexpr int NH     = 16;
constexpr int HD     = 128;
constexpr int QKVW   = 3 * DMODEL;   // 6144
constexpr int BH     = BATCH * NH;   // 32

// ---------------------------------------------------------------------------
// Scratch (device globals — allocation-free per harness rules)
// ---------------------------------------------------------------------------
__device__ __nv_bfloat16 g_xsHi [(long)BATCH * SEQ * DMODEL];
__device__ __nv_bfloat16 g_xsLo [(long)BATCH * SEQ * DMODEL];
__device__ __nv_bfloat16 g_wqHi [(long)QKVW * DMODEL];
__device__ __nv_bfloat16 g_wqLo [(long)QKVW * DMODEL];
__device__ __nv_bfloat16 g_woHi [(long)DMODEL * DMODEL];
__device__ __nv_bfloat16 g_woLo [(long)DMODEL * DMODEL];
__device__ __nv_bfloat16 g_qkvHi[(long)BATCH * SEQ * QKVW];
__device__ __nv_bfloat16 g_qkvLo[(long)BATCH * SEQ * QKVW];
__device__ __nv_bfloat16 g_vtHi [(long)BH * HD * SEQ];
__device__ __nv_bfloat16 g_vtLo [(long)BH * HD * SEQ];
__device__ float         g_scores[(long)BH * SEQ * SEQ];
__device__ __nv_bfloat16 g_pHi [(long)BH * SEQ * SEQ];
__device__ __nv_bfloat16 g_pLo [(long)BH * SEQ * SEQ];
__device__ __nv_bfloat16 g_atHi[(long)BATCH * SEQ * DMODEL];
__device__ __nv_bfloat16 g_atLo[(long)BATCH * SEQ * DMODEL];

// ---------------------------------------------------------------------------
// helpers
// ---------------------------------------------------------------------------
__device__ __forceinline__ uint32_t smem_u32(const void* p) {
    uint32_t a;
    asm("{ .reg .u64 t; cvta.to.shared.u64 t, %1; cvt.u32.u64 %0, t; }"
        : "=r"(a) : "l"(p));
    return a;
}
__device__ __forceinline__ void cp16(uint32_t saddr, const void* g) {
    asm volatile("cp.async.cg.shared.global [%0], [%1], 16;" :: "r"(saddr), "l"(g));
}
#define CP_COMMIT() asm volatile("cp.async.commit_group;" ::: "memory")
#define CP_WAIT1()  asm volatile("cp.async.wait_group 1;" ::: "memory")

__device__ __forceinline__ void ldsm_x4(uint32_t addr, uint32_t& r0, uint32_t& r1,
                                        uint32_t& r2, uint32_t& r3) {
    asm volatile("ldmatrix.sync.aligned.m8n8.x4.shared.b16 {%0,%1,%2,%3}, [%4];"
                 : "=r"(r0), "=r"(r1), "=r"(r2), "=r"(r3) : "r"(addr));
}
__device__ __forceinline__ void mma_bf16(float* c, const uint32_t* a, const uint32_t* b) {
    asm volatile(
        "mma.sync.aligned.m16n8k16.row.col.f32.bf16.bf16.f32 "
        "{%0,%1,%2,%3}, {%4,%5,%6,%7}, {%8,%9}, {%0,%1,%2,%3};"
        : "+f"(c[0]), "+f"(c[1]), "+f"(c[2]), "+f"(c[3])
        : "r"(a[0]), "r"(a[1]), "r"(a[2]), "r"(a[3]), "r"(b[0]), "r"(b[1]));
}

// ---------------------------------------------------------------------------
// HMMA GEMM: C[m,n] = sum_k (Ahi+Alo)[m,k]*(Bhi+Blo)[n,k]  (bf16x3 split)
// A row-major [M,K] (lda), B row-major [N,K] (ldb)  -> NT
// CTA tile 128x128, BK=32, 2-stage cp.async double buffer, 8 warps (2x4),
// warp tile 64x32. SMEM rows padded to 80B -> conflict-free ldmatrix.
// 2 CTAs/SM (smem 81920, regs capped at 128 via launch_bounds).
// ---------------------------------------------------------------------------
constexpr int ROWB    = 80;             // 32 bf16 = 64B data + 16B pad
constexpr int MAT_B   = 128 * ROWB;     // 10240
constexpr int STAGE_B = 4 * MAT_B;      // Ahi, Alo, Bhi, Blo = 40960
constexpr int SMEM_TOTAL = 2 * STAGE_B; // 81920 -> 2 CTAs/SM

template<bool HILO, bool BIAS>
__global__ void __launch_bounds__(256, 2)
tc_gemm(const __nv_bfloat16* __restrict__ aHi, const __nv_bfloat16* __restrict__ aLo,
        const __nv_bfloat16* __restrict__ bHi, const __nv_bfloat16* __restrict__ bLo,
        const float* __restrict__ bias,
        float* __restrict__ cF,
        __nv_bfloat16* __restrict__ cHi, __nv_bfloat16* __restrict__ cLo,
        int K, int lda, int ldb, int ldc,
        long aOut, long aIn, long bOut, long bIn, long cOut, long cIn,
        int Hdiv, float alpha)
{
    extern __shared__ __align__(128) char smem[];
    const uint32_t sb = smem_u32(smem);
    const int tid  = threadIdx.x;
    const int wid  = tid >> 5, lane = tid & 31;

    const int z  = blockIdx.z;
    const int zb = z / Hdiv, zh = z % Hdiv;
    const size_t aoff = (size_t)zb * aOut + (size_t)zh * aIn + (size_t)blockIdx.y * 128 * lda;
    const size_t boff = (size_t)zb * bOut + (size_t)zh * bIn + (size_t)blockIdx.x * 128 * ldb;
    aHi += aoff; aLo += aoff; bHi += boff; bLo += boff;

    // loader mapping: 2 chunks per matrix per thread
    const int l_row0 = tid >> 2;
    const int l_c0   = tid & 3;
    const int l_row1 = (tid + 256) >> 2;
    const int l_c1   = tid & 3;

    #define LOAD_STAGE(kt, slot)                                                  \
    do {                                                                          \
        const uint32_t s_ = sb + (slot) * STAGE_B;                                \
        const int kb_ = (kt) * 32;                                                \
        cp16(s_ + l_row0*ROWB + l_c0*16,           aHi + (size_t)l_row0*lda + kb_ + l_c0*8); \
        cp16(s_ + l_row1*ROWB + l_c1*16,           aHi + (size_t)l_row1*lda + kb_ + l_c1*8); \
        cp16(s_ + MAT_B + l_row0*ROWB + l_c0*16,   aLo + (size_t)l_row0*lda + kb_ + l_c0*8); \
        cp16(s_ + MAT_B + l_row1*ROWB + l_c1*16,   aLo + (size_t)l_row1*lda + kb_ + l_c1*8); \
        cp16(s_ + 2*MAT_B + l_row0*ROWB + l_c0*16, bHi + (size_t)l_row0*ldb + kb_ + l_c0*8); \
        cp16(s_ + 2*MAT_B + l_row1*ROWB + l_c1*16, bHi + (size_t)l_row1*ldb + kb_ + l_c1*8); \
        cp16(s_ + 3*MAT_B + l_row0*ROWB + l_c0*16, bLo + (size_t)l_row0*ldb + kb_ + l_c0*8); \
        cp16(s_ + 3*MAT_B + l_row1*ROWB + l_c1*16, bLo + (size_t)l_row1*ldb + kb_ + l_c1*8); \
    } while (0)

    // warp tile offsets
    const int wm = (wid >> 2) * 64;
    const int wn = (wid & 3) * 32;

    const int sel    = lane >> 3;
    const int within = lane & 7;
    const uint32_t aBase = (uint32_t)((wm + within + (sel & 1) * 8) * ROWB + (sel >> 1) * 16);
    const uint32_t bBase = (uint32_t)(2 * MAT_B + (wn + within + (sel >> 1) * 8) * ROWB + (sel & 1) * 16);

    float acc[4][4][4];
    #pragma unroll
    for (int i = 0; i < 4; i++)
        #pragma unroll
        for (int j = 0; j < 4; j++)
            #pragma unroll
            for (int r = 0; r < 4; r++)
                acc[i][j][r] = 0.f;

    const int nk = K >> 5;

    LOAD_STAGE(0, 0); CP_COMMIT();
    if (nk > 1) LOAD_STAGE(1, 1);
    CP_COMMIT();
    CP_WAIT1();
    __syncthreads();

    for (int kt = 0; kt < nk; ++kt) {
        const uint32_t sS = sb + (kt & 1) * STAGE_B;
        #pragma unroll
        for (int ks = 0; ks < 2; ks++) {
            uint32_t aH[4][4], aL[4][4], bH[4][2], bL[4][2];
            #pragma unroll
            for (int mt = 0; mt < 4; mt++) {
                uint32_t ad = sS + aBase + mt * (16 * ROWB) + ks * 32;
                ldsm_x4(ad,         aH[mt][0], aH[mt][1], aH[mt][2], aH[mt][3]);
                ldsm_x4(ad + MAT_B, aL[mt][0], aL[mt][1], aL[mt][2], aL[mt][3]);
            }
            #pragma unroll
            for (int p = 0; p < 2; p++) {
                uint32_t bd = sS + bBase + p * (16 * ROWB) + ks * 32;
                ldsm_x4(bd,         bH[2*p][0], bH[2*p][1], bH[2*p+1][0], bH[2*p+1][1]);
                ldsm_x4(bd + MAT_B, bL[2*p][0], bL[2*p][1], bL[2*p+1][0], bL[2*p+1][1]);
            }
            #pragma unroll
            for (int mt = 0; mt < 4; mt++)
                #pragma unroll
                for (int nt = 0; nt < 4; nt++) {
                    mma_bf16(acc[mt][nt], aH[mt], bH[nt]);
                    mma_bf16(acc[mt][nt], aH[mt], bL[nt]);
                    mma_bf16(acc[mt][nt], aL[mt], bH[nt]);
                }
        }
        // all warps finished reading slot (kt&1) before it is overwritten
        __syncthreads();
        if (kt + 2 < nk) LOAD_STAGE(kt + 2, kt & 1);
        CP_COMMIT();
        CP_WAIT1();        // stage kt+1 resident
        __syncthreads();
    }

    // epilogue
    const size_t coff = (size_t)zb * cOut + (size_t)zh * cIn;
    const int gr = blockIdx.y * 128 + wm + (lane >> 2);
    const int gc = blockIdx.x * 128 + wn + (lane & 3) * 2;

    #pragma unroll
    for (int mt = 0; mt < 4; mt++) {
        #pragma unroll
        for (int nt = 0; nt < 4; nt++) {
            const int col = gc + nt * 8;
            float b0 = 0.f, b1 = 0.f;
            if (BIAS) { b0 = bias[col]; b1 = bias[col + 1]; }
            #pragma unroll
            for (int half = 0; half < 2; half++) {
                const int row = gr + mt * 16 + half * 8;
                float v0 = acc[mt][nt][half * 2]     * alpha + b0;
                float v1 = acc[mt][nt][half * 2 + 1] * alpha + b1;
                if (HILO) {
                    __nv_bfloat16 h0 = __float2bfloat16(v0);
                    __nv_bfloat16 h1 = __float2bfloat16(v1);
                    __nv_bfloat16 l0 = __float2bfloat16(v0 - __bfloat162float(h0));
                    __nv_bfloat16 l1 = __float2bfloat16(v1 - __bfloat162float(h1));
                    *(__nv_bfloat162*)(cHi + coff + (size_t)row * ldc + col) =
                        __halves2bfloat162(h0, h1);
                    *(__nv_bfloat162*)(cLo + coff + (size_t)row * ldc + col) =
                        __halves2bfloat162(l0, l1);
                } else {
                    float2 v; v.x = v0; v.y = v1;
                    *(float2*)(cF + coff + (size_t)row * ldc + col) = v;
                }
            }
        }
    }
    #undef LOAD_STAGE
}

// ---------------------------------------------------------------------------
// fp32 -> bf16 hi/lo split (elementwise, float4)
// ---------------------------------------------------------------------------
__global__ void __launch_bounds__(256)
split_kernel(const float* __restrict__ in, __nv_bfloat16* __restrict__ hi,
             __nv_bfloat16* __restrict__ lo)
{
    const long i = (long)blockIdx.x * 256 + threadIdx.x;   // float4 index
    float4 v = ((const float4*)in)[i];
    __nv_bfloat16 h0 = __float2bfloat16(v.x), h1 = __float2bfloat16(v.y);
    __nv_bfloat16 h2 = __float2bfloat16(v.z), h3 = __float2bfloat16(v.w);
    __nv_bfloat16 l0 = __float2bfloat16(v.x - __bfloat162float(h0));
    __nv_bfloat16 l1 = __float2bfloat16(v.y - __bfloat162float(h1));
    __nv_bfloat16 l2 = __float2bfloat16(v.z - __bfloat162float(h2));
    __nv_bfloat16 l3 = __float2bfloat16(v.w - __bfloat162float(h3));
    ((__nv_bfloat162*)hi)[i * 2]     = __halves2bfloat162(h0, h1);
    ((__nv_bfloat162*)hi)[i * 2 + 1] = __halves2bfloat162(h2, h3);
    ((__nv_bfloat162*)lo)[i * 2]     = __halves2bfloat162(l0, l1);
    ((__nv_bfloat162*)lo)[i * 2 + 1] = __halves2bfloat162(l2, l3);
}

// ---------------------------------------------------------------------------
// V transpose: qkv hi/lo (v slice) -> Vt hi/lo [z=bh][d][s]
// ---------------------------------------------------------------------------
__global__ void __launch_bounds__(256)
transpose_v(const __nv_bfloat16* __restrict__ qH, const __nv_bfloat16* __restrict__ qL,
            __nv_bfloat16* __restrict__ vH, __nv_bfloat16* __restrict__ vL)
{
    __shared__ __nv_bfloat16 tH[32][33], tL[32][33];
    const int z = blockIdx.z, b = z >> 4, h = z & 15;
    const int s0 = blockIdx.x * 32, d0 = blockIdx.y * 32;
    const int tx = threadIdx.x & 31, ty = threadIdx.x >> 5;   // 32 x 8
    const size_t ibase = (size_t)b * SEQ * QKVW + (size_t)h * 384 + 256;
    #pragma unroll
    for (int i = 0; i < 4; i++) {
        int s = s0 + ty + i * 8;
        tH[ty + i * 8][tx] = qH[ibase + (size_t)s * QKVW + d0 + tx];
        tL[ty + i * 8][tx] = qL[ibase + (size_t)s * QKVW + d0 + tx];
    }
    __syncthreads();
    const size_t obase = (size_t)z * HD * SEQ;
    #pragma unroll
    for (int i = 0; i < 4; i++) {
        int d = d0 + ty + i * 8;
        vH[obase + (size_t)d * SEQ + s0 + tx] = tH[tx][ty + i * 8];
        vL[obase + (size_t)d * SEQ + s0 + tx] = tL[tx][ty + i * 8];
    }
}

// ---------------------------------------------------------------------------
// scaled softmax: P = softmax(alpha * scores_row) -> bf16 hi/lo
// ---------------------------------------------------------------------------
__global__ void __launch_bounds__(256)
softmax_split(const float* __restrict__ S_, __nv_bfloat16* __restrict__ PH,
              __nv_bfloat16* __restrict__ PL)
{
    const size_t row = blockIdx.x;
    const float4* p4 = (const float4*)(S_ + row * SEQ);
    const int tid = threadIdx.x;
    __shared__ float red[8];
    const float alpha = 0.08838834764831845f;   // 1/sqrt(128)

    float4 a = p4[tid], b = p4[tid + 256];
    float m = fmaxf(fmaxf(fmaxf(a.x, a.y), fmaxf(a.z, a.w)),
                    fmaxf(fmaxf(b.x, b.y), fmaxf(b.z, b.w)));
    #pragma unroll
    for (int o = 16; o > 0; o >>= 1) m = fmaxf(m, __shfl_xor_sync(~0u, m, o));
    if ((tid & 31) == 0) red[tid >> 5] = m;
    __syncthreads();
    float mm = red[0];
    #pragma unroll
    for (int i = 1; i < 8; i++) mm = fmaxf(mm, red[i]);
    __syncthreads();

    float e[8];
    e[0] = __expf(alpha * (a.x - mm)); e[1] = __expf(alpha * (a.y - mm));
    e[2] = __expf(alpha * (a.z - mm)); e[3] = __expf(alpha * (a.w - mm));
    e[4] = __expf(alpha * (b.x - mm)); e[5] = __expf(alpha * (b.y - mm));
    e[6] = __expf(alpha * (b.z - mm)); e[7] = __expf(alpha * (b.w - mm));
    float s = e[0] + e[1] + e[2] + e[3] + e[4] + e[5] + e[6] + e[7];
    #pragma unroll
    for (int o = 16; o > 0; o >>= 1) s += __shfl_xor_sync(~0u, s, o);
    if ((tid & 31) == 0) red[tid >> 5] = s;
    __syncthreads();
    float tot = 0.f;
    #pragma unroll
    for (int i = 0; i < 8; i++) tot += red[i];
    const float inv = 1.f / tot;

    __nv_bfloat162* ph2 = (__nv_bfloat162*)(PH + row * SEQ);
    __nv_bfloat162* pl2 = (__nv_bfloat162*)(PL + row * SEQ);
    #pragma unroll
    for (int g = 0; g < 2; g++) {
        int base = (tid + g * 256) * 4;
        #pragma unroll
        for (int j = 0; j < 4; j += 2) {
            float v0 = e[g * 4 + j] * inv, v1 = e[g * 4 + j + 1] * inv;
            __nv_bfloat16 h0 = __float2bfloat16(v0), h1 = __float2bfloat16(v1);
            __nv_bfloat16 l0 = __float2bfloat16(v0 - __bfloat162float(h0));
            __nv_bfloat16 l1 = __float2bfloat16(v1 - __bfloat162float(h1));
            ph2[(base + j) >> 1] = __halves2bfloat162(h0, h1);
            pl2[(base + j) >> 1] = __halves2bfloat162(l0, l1);
        }
    }
}

// ---------------------------------------------------------------------------
extern "C" void kernel_launch(void* const* d_in, const int* in_sizes, int n_in,
                              void* d_out, int out_size)
{
    const float* x     = (const float*)d_in[0];
    const float* w_qkv = (const float*)d_in[2];
    const float* b_qkv = (const float*)d_in[3];
    const float* w_o   = (const float*)d_in[4];
    const float* b_o   = (const float*)d_in[5];
    float* out = (float*)d_out;

    __nv_bfloat16 *xsH, *xsL, *wqH, *wqL, *woH, *woL, *qkH, *qkL;
    __nv_bfloat16 *vtH, *vtL, *pH, *pL, *atH, *atL;
    float* scores;
    cudaGetSymbolAddress((void**)&xsH, g_xsHi);  cudaGetSymbolAddress((void**)&xsL, g_xsLo);
    cudaGetSymbolAddress((void**)&wqH, g_wqHi);  cudaGetSymbolAddress((void**)&wqL, g_wqLo);
    cudaGetSymbolAddress((void**)&woH, g_woHi);  cudaGetSymbolAddress((void**)&woL, g_woLo);
    cudaGetSymbolAddress((void**)&qkH, g_qkvHi); cudaGetSymbolAddress((void**)&qkL, g_qkvLo);
    cudaGetSymbolAddress((void**)&vtH, g_vtHi);  cudaGetSymbolAddress((void**)&vtL, g_vtLo);
    cudaGetSymbolAddress((void**)&pH,  g_pHi);   cudaGetSymbolAddress((void**)&pL,  g_pLo);
    cudaGetSymbolAddress((void**)&atH, g_atHi);  cudaGetSymbolAddress((void**)&atL, g_atLo);
    cudaGetSymbolAddress((void**)&scores, g_scores);

    cudaFuncSetAttribute(tc_gemm<true,  true >, cudaFuncAttributeMaxDynamicSharedMemorySize, SMEM_TOTAL);
    cudaFuncSetAttribute(tc_gemm<false, false>, cudaFuncAttributeMaxDynamicSharedMemorySize, SMEM_TOTAL);
    cudaFuncSetAttribute(tc_gemm<true,  false>, cudaFuncAttributeMaxDynamicSharedMemorySize, SMEM_TOTAL);
    cudaFuncSetAttribute(tc_gemm<false, true >, cudaFuncAttributeMaxDynamicSharedMemorySize, SMEM_TOTAL);

    // 0) split inputs
    split_kernel<<<(long)BATCH*SEQ*DMODEL/1024, 256>>>(x,     xsH, xsL);
    split_kernel<<<(long)QKVW*DMODEL/1024,      256>>>(w_qkv, wqH, wqL);
    split_kernel<<<(long)DMODEL*DMODEL/1024,    256>>>(w_o,   woH, woL);

    // 1) QKV projection -> qkv hi/lo (bias fused)
    {
        dim3 grid(QKVW / 128, (BATCH * SEQ) / 128, 1);
        tc_gemm<true, true><<<grid, 256, SMEM_TOTAL>>>(
            xsH, xsL, wqH, wqL, b_qkv, nullptr, qkH, qkL,
            DMODEL, DMODEL, DMODEL, QKVW,
            0, 0, 0, 0, 0, 0, 1, 1.0f);
    }

    // 2) V transpose -> Vt hi/lo
    transpose_v<<<dim3(SEQ / 32, HD / 32, BH), 256>>>(qkH, qkL, vtH, vtL);

    // 3) scores = Q K^T (raw; scale folded into softmax)
    {
        dim3 grid(SEQ / 128, SEQ / 128, BH);
        tc_gemm<false, false><<<grid, 256, SMEM_TOTAL>>>(
            qkH, qkL, qkH + HD, qkL + HD, nullptr, scores, nullptr, nullptr,
            HD, QKVW, QKVW, SEQ,
            (long)SEQ * QKVW, 384, (long)SEQ * QKVW, 384,
            (long)NH * SEQ * SEQ, (long)SEQ * SEQ,
            NH, 1.0f);
    }

    // 4) softmax(alpha * s) -> P hi/lo
    softmax_split<<<(long)BH * SEQ, 256>>>(scores, pH, pL);

    // 5) O = P V -> attn hi/lo
    {
        dim3 grid(1, SEQ / 128, BH);
        tc_gemm<true, false><<<grid, 256, SMEM_TOTAL>>>(
            pH, pL, vtH, vtL, nullptr, nullptr, atH, atL,
            SEQ, SEQ, SEQ, DMODEL,
            (long)NH * SEQ * SEQ, (long)SEQ * SEQ,
            (long)NH * HD * SEQ, (long)HD * SEQ,
            (long)SEQ * DMODEL, HD,
            NH, 1.0f);
    }

    // 6) output projection (bias fused) -> out fp32
    {
        dim3 grid(DMODEL / 128, (BATCH * SEQ) / 128, 1);
        tc_gemm<false, true><<<grid, 256, SMEM_TOTAL>>>(
            atH, atL, woH, woL, b_o, out, nullptr, nullptr,
            DMODEL, DMODEL, DMODEL, DMODEL,
            0, 0, 0, 0, 0, 0, 1, 1.0f);
    }
}

// round 6
// speedup vs baseline: 2.7797x; 1.0575x over previous
#include <cuda_runtime.h>
#include <cuda_bf16.h>
#include <cstdint>

// Problem shape (fixed): B=2, S=2048, D=2048, H=16, DK=128
constexpr int BATCH  = 2;
constexpr int SEQ    = 2048;
constexpr int DMODEL = 2048;
constexpr int NH     = 16;
constexpr int HD     = 128;
constexpr int QKVW   = 3 * DMODEL;   // 6144
constexpr int BH     = BATCH * NH;   // 32

// ---------------------------------------------------------------------------
// Scratch (device globals — allocation-free per harness rules)
// ---------------------------------------------------------------------------
__device__ __nv_bfloat16 g_xsHi [(long)BATCH * SEQ * DMODEL];
__device__ __nv_bfloat16 g_xsLo [(long)BATCH * SEQ * DMODEL];
__device__ __nv_bfloat16 g_wqHi [(long)QKVW * DMODEL];
__device__ __nv_bfloat16 g_wqLo [(long)QKVW * DMODEL];
__device__ __nv_bfloat16 g_woHi [(long)DMODEL * DMODEL];
__device__ __nv_bfloat16 g_woLo [(long)DMODEL * DMODEL];
__device__ __nv_bfloat16 g_qkvHi[(long)BATCH * SEQ * QKVW];
__device__ __nv_bfloat16 g_qkvLo[(long)BATCH * SEQ * QKVW];
__device__ __nv_bfloat16 g_vtHi [(long)BH * HD * SEQ];
__device__ __nv_bfloat16 g_vtLo [(long)BH * HD * SEQ];
__device__ __nv_bfloat16 g_atHi[(long)BATCH * SEQ * DMODEL];
__device__ __nv_bfloat16 g_atLo[(long)BATCH * SEQ * DMODEL];

// ---------------------------------------------------------------------------
// helpers
// ---------------------------------------------------------------------------
__device__ __forceinline__ uint32_t smem_u32(const void* p) {
    uint32_t a;
    asm("{ .reg .u64 t; cvta.to.shared.u64 t, %1; cvt.u32.u64 %0, t; }"
        : "=r"(a) : "l"(p));
    return a;
}
__device__ __forceinline__ void cp16(uint32_t saddr, const void* g) {
    asm volatile("cp.async.cg.shared.global [%0], [%1], 16;" :: "r"(saddr), "l"(g));
}
#define CP_COMMIT() asm volatile("cp.async.commit_group;" ::: "memory")
#define CP_WAIT1()  asm volatile("cp.async.wait_group 1;" ::: "memory")
#define CP_WAIT0()  asm volatile("cp.async.wait_group 0;" ::: "memory")

__device__ __forceinline__ void ldsm_x4(uint32_t addr, uint32_t& r0, uint32_t& r1,
                                        uint32_t& r2, uint32_t& r3) {
    asm volatile("ldmatrix.sync.aligned.m8n8.x4.shared.b16 {%0,%1,%2,%3}, [%4];"
                 : "=r"(r0), "=r"(r1), "=r"(r2), "=r"(r3) : "r"(addr));
}
__device__ __forceinline__ void mma_bf16(float* c, const uint32_t* a, const uint32_t* b) {
    asm volatile(
        "mma.sync.aligned.m16n8k16.row.col.f32.bf16.bf16.f32 "
        "{%0,%1,%2,%3}, {%4,%5,%6,%7}, {%8,%9}, {%0,%1,%2,%3};"
        : "+f"(c[0]), "+f"(c[1]), "+f"(c[2]), "+f"(c[3])
        : "r"(a[0]), "r"(a[1]), "r"(a[2]), "r"(a[3]), "r"(b[0]), "r"(b[1]));
}
__device__ __forceinline__ uint32_t pack_bf2(__nv_bfloat16 a, __nv_bfloat16 b) {
    __nv_bfloat162 t = __halves2bfloat162(a, b);
    return *(uint32_t*)&t;
}
__device__ __forceinline__ void split2(float v0, float v1, uint32_t& hi, uint32_t& lo) {
    __nv_bfloat16 h0 = __float2bfloat16(v0), h1 = __float2bfloat16(v1);
    __nv_bfloat16 l0 = __float2bfloat16(v0 - __bfloat162float(h0));
    __nv_bfloat16 l1 = __float2bfloat16(v1 - __bfloat162float(h1));
    hi = pack_bf2(h0, h1);
    lo = pack_bf2(l0, l1);
}

// ---------------------------------------------------------------------------
// HMMA GEMM (unchanged from R5): bf16x3 split, 2-stage, 2 CTAs/SM
// ---------------------------------------------------------------------------
constexpr int ROWB    = 80;
constexpr int MAT_B   = 128 * ROWB;     // 10240
constexpr int STAGE_B = 4 * MAT_B;      // 40960
constexpr int SMEM_TOTAL = 2 * STAGE_B; // 81920

template<bool HILO, bool BIAS>
__global__ void __launch_bounds__(256, 2)
tc_gemm(const __nv_bfloat16* __restrict__ aHi, const __nv_bfloat16* __restrict__ aLo,
        const __nv_bfloat16* __restrict__ bHi, const __nv_bfloat16* __restrict__ bLo,
        const float* __restrict__ bias,
        float* __restrict__ cF,
        __nv_bfloat16* __restrict__ cHi, __nv_bfloat16* __restrict__ cLo,
        int K, int lda, int ldb, int ldc,
        long aOut, long aIn, long bOut, long bIn, long cOut, long cIn,
        int Hdiv, float alpha)
{
    extern __shared__ __align__(128) char smem[];
    const uint32_t sb = smem_u32(smem);
    const int tid  = threadIdx.x;
    const int wid  = tid >> 5, lane = tid & 31;

    const int z  = blockIdx.z;
    const int zb = z / Hdiv, zh = z % Hdiv;
    const size_t aoff = (size_t)zb * aOut + (size_t)zh * aIn + (size_t)blockIdx.y * 128 * lda;
    const size_t boff = (size_t)zb * bOut + (size_t)zh * bIn + (size_t)blockIdx.x * 128 * ldb;
    aHi += aoff; aLo += aoff; bHi += boff; bLo += boff;

    const int l_row0 = tid >> 2;
    const int l_c0   = tid & 3;
    const int l_row1 = (tid + 256) >> 2;
    const int l_c1   = tid & 3;

    #define LOAD_STAGE(kt, slot)                                                  \
    do {                                                                          \
        const uint32_t s_ = sb + (slot) * STAGE_B;                                \
        const int kb_ = (kt) * 32;                                                \
        cp16(s_ + l_row0*ROWB + l_c0*16,           aHi + (size_t)l_row0*lda + kb_ + l_c0*8); \
        cp16(s_ + l_row1*ROWB + l_c1*16,           aHi + (size_t)l_row1*lda + kb_ + l_c1*8); \
        cp16(s_ + MAT_B + l_row0*ROWB + l_c0*16,   aLo + (size_t)l_row0*lda + kb_ + l_c0*8); \
        cp16(s_ + MAT_B + l_row1*ROWB + l_c1*16,   aLo + (size_t)l_row1*lda + kb_ + l_c1*8); \
        cp16(s_ + 2*MAT_B + l_row0*ROWB + l_c0*16, bHi + (size_t)l_row0*ldb + kb_ + l_c0*8); \
        cp16(s_ + 2*MAT_B + l_row1*ROWB + l_c1*16, bHi + (size_t)l_row1*ldb + kb_ + l_c1*8); \
        cp16(s_ + 3*MAT_B + l_row0*ROWB + l_c0*16, bLo + (size_t)l_row0*ldb + kb_ + l_c0*8); \
        cp16(s_ + 3*MAT_B + l_row1*ROWB + l_c1*16, bLo + (size_t)l_row1*ldb + kb_ + l_c1*8); \
    } while (0)

    const int wm = (wid >> 2) * 64;
    const int wn = (wid & 3) * 32;

    const int sel    = lane >> 3;
    const int within = lane & 7;
    const uint32_t aBase = (uint32_t)((wm + within + (sel & 1) * 8) * ROWB + (sel >> 1) * 16);
    const uint32_t bBase = (uint32_t)(2 * MAT_B + (wn + within + (sel >> 1) * 8) * ROWB + (sel & 1) * 16);

    float acc[4][4][4];
    #pragma unroll
    for (int i = 0; i < 4; i++)
        #pragma unroll
        for (int j = 0; j < 4; j++)
            #pragma unroll
            for (int r = 0; r < 4; r++)
                acc[i][j][r] = 0.f;

    const int nk = K >> 5;

    LOAD_STAGE(0, 0); CP_COMMIT();
    if (nk > 1) LOAD_STAGE(1, 1);
    CP_COMMIT();
    CP_WAIT1();
    __syncthreads();

    for (int kt = 0; kt < nk; ++kt) {
        const uint32_t sS = sb + (kt & 1) * STAGE_B;
        #pragma unroll
        for (int ks = 0; ks < 2; ks++) {
            uint32_t aH[4][4], aL[4][4], bH[4][2], bL[4][2];
            #pragma unroll
            for (int mt = 0; mt < 4; mt++) {
                uint32_t ad = sS + aBase + mt * (16 * ROWB) + ks * 32;
                ldsm_x4(ad,         aH[mt][0], aH[mt][1], aH[mt][2], aH[mt][3]);
                ldsm_x4(ad + MAT_B, aL[mt][0], aL[mt][1], aL[mt][2], aL[mt][3]);
            }
            #pragma unroll
            for (int p = 0; p < 2; p++) {
                uint32_t bd = sS + bBase + p * (16 * ROWB) + ks * 32;
                ldsm_x4(bd,         bH[2*p][0], bH[2*p][1], bH[2*p+1][0], bH[2*p+1][1]);
                ldsm_x4(bd + MAT_B, bL[2*p][0], bL[2*p][1], bL[2*p+1][0], bL[2*p+1][1]);
            }
            #pragma unroll
            for (int mt = 0; mt < 4; mt++)
                #pragma unroll
                for (int nt = 0; nt < 4; nt++) {
                    mma_bf16(acc[mt][nt], aH[mt], bH[nt]);
                    mma_bf16(acc[mt][nt], aH[mt], bL[nt]);
                    mma_bf16(acc[mt][nt], aL[mt], bH[nt]);
                }
        }
        __syncthreads();
        if (kt + 2 < nk) LOAD_STAGE(kt + 2, kt & 1);
        CP_COMMIT();
        CP_WAIT1();
        __syncthreads();
    }

    const size_t coff = (size_t)zb * cOut + (size_t)zh * cIn;
    const int gr = blockIdx.y * 128 + wm + (lane >> 2);
    const int gc = blockIdx.x * 128 + wn + (lane & 3) * 2;

    #pragma unroll
    for (int mt = 0; mt < 4; mt++) {
        #pragma unroll
        for (int nt = 0; nt < 4; nt++) {
            const int col = gc + nt * 8;
            float b0 = 0.f, b1 = 0.f;
            if (BIAS) { b0 = bias[col]; b1 = bias[col + 1]; }
            #pragma unroll
            for (int half = 0; half < 2; half++) {
                const int row = gr + mt * 16 + half * 8;
                float v0 = acc[mt][nt][half * 2]     * alpha + b0;
                float v1 = acc[mt][nt][half * 2 + 1] * alpha + b1;
                if (HILO) {
                    uint32_t hi, lo;
                    split2(v0, v1, hi, lo);
                    *(uint32_t*)(cHi + coff + (size_t)row * ldc + col) = hi;
                    *(uint32_t*)(cLo + coff + (size_t)row * ldc + col) = lo;
                } else {
                    float2 v; v.x = v0; v.y = v1;
                    *(float2*)(cF + coff + (size_t)row * ldc + col) = v;
                }
            }
        }
    }
    #undef LOAD_STAGE
}

// ---------------------------------------------------------------------------
// Flash attention: per CTA = (head z, 128 q-rows). 8 warps, warp = 16 rows.
// SMEM: Q hi/lo (4 d-chunks, 80B rows) + 3-slot K/Vt chunk ring.
// S and O in registers; online softmax; P split hi/lo in registers.
// ---------------------------------------------------------------------------
constexpr int FQ_CH   = 2 * MAT_B;                 // 20480: one chunk hi+lo
constexpr int FQ_SZ   = 4 * FQ_CH;                 // 81920: Q (4 d-chunks)
constexpr int FSMEM   = FQ_SZ + 3 * FQ_CH;         // 143360
constexpr float ALPHA = 0.08838834764831845f;      // 1/sqrt(128)

__device__ __forceinline__ void flash_issue_chunk(
    int g, uint32_t sbKV, int lr0, int lp0,
    const __nv_bfloat16* kH, const __nv_bfloat16* kL,
    const __nv_bfloat16* vH, const __nv_bfloat16* vL)
{
    const int kt = g >> 3, sub = g & 7;
    const uint32_t dst = sbKV + (g % 3) * FQ_CH;
    if (sub < 4) {
        const size_t r0 = (size_t)(kt * 128 + lr0);
        const int colb = sub * 32 + lp0 * 8;
        cp16(dst + lr0*ROWB + lp0*16,              kH + r0 * QKVW + colb);
        cp16(dst + (lr0+64)*ROWB + lp0*16,         kH + (r0+64) * QKVW + colb);
        cp16(dst + MAT_B + lr0*ROWB + lp0*16,      kL + r0 * QKVW + colb);
        cp16(dst + MAT_B + (lr0+64)*ROWB + lp0*16, kL + (r0+64) * QKVW + colb);
    } else {
        const int colb = kt * 128 + (sub - 4) * 32 + lp0 * 8;
        cp16(dst + lr0*ROWB + lp0*16,              vH + (size_t)lr0 * SEQ + colb);
        cp16(dst + (lr0+64)*ROWB + lp0*16,         vH + (size_t)(lr0+64) * SEQ + colb);
        cp16(dst + MAT_B + lr0*ROWB + lp0*16,      vL + (size_t)lr0 * SEQ + colb);
        cp16(dst + MAT_B + (lr0+64)*ROWB + lp0*16, vL + (size_t)(lr0+64) * SEQ + colb);
    }
}

__global__ void __launch_bounds__(256, 1)
flash_kernel(const __nv_bfloat16* __restrict__ qkH, const __nv_bfloat16* __restrict__ qkL,
             const __nv_bfloat16* __restrict__ vtH, const __nv_bfloat16* __restrict__ vtL,
             __nv_bfloat16* __restrict__ oH, __nv_bfloat16* __restrict__ oL)
{
    extern __shared__ __align__(128) char smem[];
    const uint32_t sb = smem_u32(smem);
    const int tid  = threadIdx.x;
    const int wid  = tid >> 5, lane = tid & 31;
    const int qt   = blockIdx.x;
    const int z    = blockIdx.y;
    const int b    = z >> 4, h = z & 15;

    const __nv_bfloat16* qH = qkH + (size_t)b * SEQ * QKVW + h * 384;
    const __nv_bfloat16* qL = qkL + (size_t)b * SEQ * QKVW + h * 384;
    const __nv_bfloat16* kH = qH + 128;
    const __nv_bfloat16* kL = qL + 128;
    const __nv_bfloat16* vH = vtH + (size_t)z * HD * SEQ;
    const __nv_bfloat16* vL = vtL + (size_t)z * HD * SEQ;

    const int lr0 = tid >> 2;      // chunk-loader row (and +64)
    const int lp0 = tid & 3;       // 16B piece

    // ---- load Q (4 d-chunks, hi+lo) as one commit group ----
    const int q0 = qt * 128;
    #pragma unroll
    for (int c = 0; c < 4; c++) {
        const uint32_t d0 = sb + c * FQ_CH;
        const int colb = c * 32 + lp0 * 8;
        cp16(d0 + lr0*ROWB + lp0*16,              qH + (size_t)(q0+lr0) * QKVW + colb);
        cp16(d0 + (lr0+64)*ROWB + lp0*16,         qH + (size_t)(q0+lr0+64) * QKVW + colb);
        cp16(d0 + MAT_B + lr0*ROWB + lp0*16,      qL + (size_t)(q0+lr0) * QKVW + colb);
        cp16(d0 + MAT_B + (lr0+64)*ROWB + lp0*16, qL + (size_t)(q0+lr0+64) * QKVW + colb);
    }
    CP_COMMIT();
    flash_issue_chunk(0, sb + FQ_SZ, lr0, lp0, kH, kL, vH, vL); CP_COMMIT();
    flash_issue_chunk(1, sb + FQ_SZ, lr0, lp0, kH, kL, vH, vL); CP_COMMIT();

    // fragment addressing (identical formulas to tc_gemm)
    const int sel    = lane >> 3;
    const int within = lane & 7;
    const uint32_t aOff    = (uint32_t)((wid * 16 + within + (sel & 1) * 8) * ROWB + (sel >> 1) * 16);
    const uint32_t bOffB   = (uint32_t)((within + (sel >> 1) * 8) * ROWB + (sel & 1) * 16);

    float o[16][4];
    #pragma unroll
    for (int i = 0; i < 16; i++)
        #pragma unroll
        for (int j = 0; j < 4; j++) o[i][j] = 0.f;
    float s[16][4];
    uint32_t pfH[8][4], pfL[8][4];
    float mA = -1e30f, mB = -1e30f, lA = 0.f, lB = 0.f;

    for (int kt = 0; kt < 16; ++kt) {
        #pragma unroll
        for (int sub = 0; sub < 8; ++sub) {
            const int g = kt * 8 + sub;
            if (g + 1 < 128) { CP_WAIT1(); } else { CP_WAIT0(); }
            __syncthreads();
            if (g + 2 < 128) {
                flash_issue_chunk(g + 2, sb + FQ_SZ, lr0, lp0, kH, kL, vH, vL);
                CP_COMMIT();
            }
            const uint32_t slotB = sb + FQ_SZ + (g % 3) * FQ_CH;

            if (sub < 4) {
                // ---- S-phase: d-chunk = sub ----
                if (sub == 0) {
                    #pragma unroll
                    for (int i = 0; i < 16; i++)
                        #pragma unroll
                        for (int j = 0; j < 4; j++) s[i][j] = 0.f;
                }
                const uint32_t qc = sb + sub * FQ_CH;
                #pragma unroll
                for (int ks = 0; ks < 2; ks++) {
                    uint32_t aH4[4], aL4[4];
                    ldsm_x4(qc + aOff + ks*32,          aH4[0], aH4[1], aH4[2], aH4[3]);
                    ldsm_x4(qc + MAT_B + aOff + ks*32,  aL4[0], aL4[1], aL4[2], aL4[3]);
                    #pragma unroll
                    for (int p = 0; p < 8; p++) {
                        uint32_t bh[4], bl[4];
                        ldsm_x4(slotB + bOffB + p*(16*ROWB) + ks*32,
                                bh[0], bh[1], bh[2], bh[3]);
                        ldsm_x4(slotB + MAT_B + bOffB + p*(16*ROWB) + ks*32,
                                bl[0], bl[1], bl[2], bl[3]);
                        mma_bf16(s[2*p],   aH4, bh);
                        mma_bf16(s[2*p],   aH4, bl);
                        mma_bf16(s[2*p],   aL4, bh);
                        mma_bf16(s[2*p+1], aH4, bh + 2);
                        mma_bf16(s[2*p+1], aH4, bl + 2);
                        mma_bf16(s[2*p+1], aL4, bh + 2);
                    }
                }
            } else {
                if (sub == 4) {
                    // ---- online softmax over this key tile ----
                    float mtA = -1e30f, mtB = -1e30f;
                    #pragma unroll
                    for (int nt = 0; nt < 16; nt++) {
                        mtA = fmaxf(mtA, fmaxf(s[nt][0], s[nt][1]));
                        mtB = fmaxf(mtB, fmaxf(s[nt][2], s[nt][3]));
                    }
                    mtA = fmaxf(mtA, __shfl_xor_sync(~0u, mtA, 1));
                    mtA = fmaxf(mtA, __shfl_xor_sync(~0u, mtA, 2));
                    mtB = fmaxf(mtB, __shfl_xor_sync(~0u, mtB, 1));
                    mtB = fmaxf(mtB, __shfl_xor_sync(~0u, mtB, 2));
                    const float mnA = fmaxf(mA, mtA);
                    const float mnB = fmaxf(mB, mtB);
                    const float fA = __expf(ALPHA * (mA - mnA));
                    const float fB = __expf(ALPHA * (mB - mnB));
                    #pragma unroll
                    for (int nt = 0; nt < 16; nt++) {
                        o[nt][0] *= fA; o[nt][1] *= fA;
                        o[nt][2] *= fB; o[nt][3] *= fB;
                    }
                    float sA = 0.f, sB = 0.f;
                    #pragma unroll
                    for (int nt = 0; nt < 16; nt++) {
                        const float p0 = __expf(ALPHA * (s[nt][0] - mnA));
                        const float p1 = __expf(ALPHA * (s[nt][1] - mnA));
                        const float p2 = __expf(ALPHA * (s[nt][2] - mnB));
                        const float p3 = __expf(ALPHA * (s[nt][3] - mnB));
                        sA += p0 + p1; sB += p2 + p3;
                        uint32_t h01, l01, h23, l23;
                        split2(p0, p1, h01, l01);
                        split2(p2, p3, h23, l23);
                        const int kf = nt >> 1;
                        if ((nt & 1) == 0) {
                            pfH[kf][0] = h01; pfH[kf][1] = h23;
                            pfL[kf][0] = l01; pfL[kf][1] = l23;
                        } else {
                            pfH[kf][2] = h01; pfH[kf][3] = h23;
                            pfL[kf][2] = l01; pfL[kf][3] = l23;
                        }
                    }
                    sA += __shfl_xor_sync(~0u, sA, 1);
                    sA += __shfl_xor_sync(~0u, sA, 2);
                    sB += __shfl_xor_sync(~0u, sB, 1);
                    sB += __shfl_xor_sync(~0u, sB, 2);
                    lA = lA * fA + sA;
                    lB = lB * fB + sB;
                    mA = mnA; mB = mnB;
                }
                // ---- PV-phase: key-chunk c = sub-4, kf = 2c+ks ----
                #pragma unroll
                for (int ks = 0; ks < 2; ks++) {
                    const int kf = 2 * (sub - 4) + ks;
                    #pragma unroll
                    for (int p = 0; p < 8; p++) {
                        uint32_t bh[4], bl[4];
                        ldsm_x4(slotB + bOffB + p*(16*ROWB) + ks*32,
                                bh[0], bh[1], bh[2], bh[3]);
                        ldsm_x4(slotB + MAT_B + bOffB + p*(16*ROWB) + ks*32,
                                bl[0], bl[1], bl[2], bl[3]);
                        mma_bf16(o[2*p],   pfH[kf], bh);
                        mma_bf16(o[2*p],   pfH[kf], bl);
                        mma_bf16(o[2*p],   pfL[kf], bh);
                        mma_bf16(o[2*p+1], pfH[kf], bh + 2);
                        mma_bf16(o[2*p+1], pfH[kf], bl + 2);
                        mma_bf16(o[2*p+1], pfL[kf], bh + 2);
                    }
                }
            }
        }
    }

    // ---- normalize + store O (bf16 hi/lo, attn layout [b][s][h*128+d]) ----
    const float invA = 1.f / lA;
    const float invB = 1.f / lB;
    const size_t rowA = (size_t)b * SEQ + q0 + wid * 16 + (lane >> 2);
    const size_t baseA = rowA * DMODEL + h * 128 + (lane & 3) * 2;
    const size_t baseB = baseA + (size_t)8 * DMODEL;
    #pragma unroll
    for (int nt = 0; nt < 16; nt++) {
        uint32_t hi, lo;
        split2(o[nt][0] * invA, o[nt][1] * invA, hi, lo);
        *(uint32_t*)(oH + baseA + nt * 8) = hi;
        *(uint32_t*)(oL + baseA + nt * 8) = lo;
        split2(o[nt][2] * invB, o[nt][3] * invB, hi, lo);
        *(uint32_t*)(oH + baseB + nt * 8) = hi;
        *(uint32_t*)(oL + baseB + nt * 8) = lo;
    }
}

// ---------------------------------------------------------------------------
// fp32 -> bf16 hi/lo split (elementwise, float4)
// ---------------------------------------------------------------------------
__global__ void __launch_bounds__(256)
split_kernel(const float* __restrict__ in, __nv_bfloat16* __restrict__ hi,
             __nv_bfloat16* __restrict__ lo)
{
    const long i = (long)blockIdx.x * 256 + threadIdx.x;   // float4 index
    float4 v = ((const float4*)in)[i];
    uint32_t h0, l0, h1, l1;
    split2(v.x, v.y, h0, l0);
    split2(v.z, v.w, h1, l1);
    ((uint32_t*)hi)[i * 2]     = h0;
    ((uint32_t*)hi)[i * 2 + 1] = h1;
    ((uint32_t*)lo)[i * 2]     = l0;
    ((uint32_t*)lo)[i * 2 + 1] = l1;
}

// ---------------------------------------------------------------------------
// V transpose: qkv hi/lo (v slice) -> Vt hi/lo [z=bh][d][s]
// ---------------------------------------------------------------------------
__global__ void __launch_bounds__(256)
transpose_v(const __nv_bfloat16* __restrict__ qH, const __nv_bfloat16* __restrict__ qL,
            __nv_bfloat16* __restrict__ vH, __nv_bfloat16* __restrict__ vL)
{
    __shared__ __nv_bfloat16 tH[32][33], tL[32][33];
    const int z = blockIdx.z, b = z >> 4, h = z & 15;
    const int s0 = blockIdx.x * 32, d0 = blockIdx.y * 32;
    const int tx = threadIdx.x & 31, ty = threadIdx.x >> 5;   // 32 x 8
    const size_t ibase = (size_t)b * SEQ * QKVW + (size_t)h * 384 + 256;
    #pragma unroll
    for (int i = 0; i < 4; i++) {
        int s = s0 + ty + i * 8;
        tH[ty + i * 8][tx] = qH[ibase + (size_t)s * QKVW + d0 + tx];
        tL[ty + i * 8][tx] = qL[ibase + (size_t)s * QKVW + d0 + tx];
    }
    __syncthreads();
    const size_t obase = (size_t)z * HD * SEQ;
    #pragma unroll
    for (int i = 0; i < 4; i++) {
        int d = d0 + ty + i * 8;
        vH[obase + (size_t)d * SEQ + s0 + tx] = tH[tx][ty + i * 8];
        vL[obase + (size_t)d * SEQ + s0 + tx] = tL[tx][ty + i * 8];
    }
}

// ---------------------------------------------------------------------------
extern "C" void kernel_launch(void* const* d_in, const int* in_sizes, int n_in,
                              void* d_out, int out_size)
{
    const float* x     = (const float*)d_in[0];
    const float* w_qkv = (const float*)d_in[2];
    const float* b_qkv = (const float*)d_in[3];
    const float* w_o   = (const float*)d_in[4];
    const float* b_o   = (const float*)d_in[5];
    float* out = (float*)d_out;

    __nv_bfloat16 *xsH, *xsL, *wqH, *wqL, *woH, *woL, *qkH, *qkL;
    __nv_bfloat16 *vtH, *vtL, *atH, *atL;
    cudaGetSymbolAddress((void**)&xsH, g_xsHi);  cudaGetSymbolAddress((void**)&xsL, g_xsLo);
    cudaGetSymbolAddress((void**)&wqH, g_wqHi);  cudaGetSymbolAddress((void**)&wqL, g_wqLo);
    cudaGetSymbolAddress((void**)&woH, g_woHi);  cudaGetSymbolAddress((void**)&woL, g_woLo);
    cudaGetSymbolAddress((void**)&qkH, g_qkvHi); cudaGetSymbolAddress((void**)&qkL, g_qkvLo);
    cudaGetSymbolAddress((void**)&vtH, g_vtHi);  cudaGetSymbolAddress((void**)&vtL, g_vtLo);
    cudaGetSymbolAddress((void**)&atH, g_atHi);  cudaGetSymbolAddress((void**)&atL, g_atLo);

    cudaFuncSetAttribute(tc_gemm<true,  true >, cudaFuncAttributeMaxDynamicSharedMemorySize, SMEM_TOTAL);
    cudaFuncSetAttribute(tc_gemm<false, true >, cudaFuncAttributeMaxDynamicSharedMemorySize, SMEM_TOTAL);
    cudaFuncSetAttribute(flash_kernel, cudaFuncAttributeMaxDynamicSharedMemorySize, FSMEM);

    // 0) split inputs
    split_kernel<<<(long)BATCH*SEQ*DMODEL/1024, 256>>>(x,     xsH, xsL);
    split_kernel<<<(long)QKVW*DMODEL/1024,      256>>>(w_qkv, wqH, wqL);
    split_kernel<<<(long)DMODEL*DMODEL/1024,    256>>>(w_o,   woH, woL);

    // 1) QKV projection -> qkv hi/lo (bias fused)
    {
        dim3 grid(QKVW / 128, (BATCH * SEQ) / 128, 1);
        tc_gemm<true, true><<<grid, 256, SMEM_TOTAL>>>(
            xsH, xsL, wqH, wqL, b_qkv, nullptr, qkH, qkL,
            DMODEL, DMODEL, DMODEL, QKVW,
            0, 0, 0, 0, 0, 0, 1, 1.0f);
    }

    // 2) V transpose -> Vt hi/lo
    transpose_v<<<dim3(SEQ / 32, HD / 32, BH), 256>>>(qkH, qkL, vtH, vtL);

    // 3) fused flash attention -> attn hi/lo
    flash_kernel<<<dim3(SEQ / 128, BH), 256, FSMEM>>>(qkH, qkL, vtH, vtL, atH, atL);

    // 4) output projection (bias fused) -> out fp32
    {
        dim3 grid(DMODEL / 128, (BATCH * SEQ) / 128, 1);
        tc_gemm<false, true><<<grid, 256, SMEM_TOTAL>>>(
            atH, atL, woH, woL, b_o, out, nullptr, nullptr,
            DMODEL, DMODEL, DMODEL, DMODEL,
            0, 0, 0, 0, 0, 0, 1, 1.0f);
    }
}

// round 7
// speedup vs baseline: 3.3780x; 1.2152x over previous
#include <cuda_runtime.h>
#include <cuda_fp16.h>
#include <cstdint>

// Problem shape (fixed): B=2, S=2048, D=2048, H=16, DK=128
constexpr int BATCH  = 2;
constexpr int SEQ    = 2048;
constexpr int DMODEL = 2048;
constexpr int NH     = 16;
constexpr int HD     = 128;
constexpr int QKVW   = 3 * DMODEL;   // 6144
constexpr int BH     = BATCH * NH;   // 32

// ---------------------------------------------------------------------------
// Scratch (device globals — allocation-free per harness rules)
// ---------------------------------------------------------------------------
__device__ __half g_xsHi [(long)BATCH * SEQ * DMODEL];
__device__ __half g_wqHi [(long)QKVW * DMODEL];
__device__ __half g_wqLo [(long)QKVW * DMODEL];
__device__ __half g_woHi [(long)DMODEL * DMODEL];
__device__ __half g_woLo [(long)DMODEL * DMODEL];
__device__ __half g_qkvHi[(long)BATCH * SEQ * QKVW];
__device__ __half g_qkvLo[(long)BATCH * SEQ * QKVW];
__device__ __half g_vtHi [(long)BH * HD * SEQ];
__device__ __half g_vtLo [(long)BH * HD * SEQ];
__device__ __half g_atHi [(long)BATCH * SEQ * DMODEL];

// ---------------------------------------------------------------------------
// helpers
// ---------------------------------------------------------------------------
__device__ __forceinline__ uint32_t smem_u32(const void* p) {
    uint32_t a;
    asm("{ .reg .u64 t; cvta.to.shared.u64 t, %1; cvt.u32.u64 %0, t; }"
        : "=r"(a) : "l"(p));
    return a;
}
__device__ __forceinline__ void cp16(uint32_t saddr, const void* g) {
    asm volatile("cp.async.cg.shared.global [%0], [%1], 16;" :: "r"(saddr), "l"(g));
}
#define CP_COMMIT() asm volatile("cp.async.commit_group;" ::: "memory")
#define CP_WAIT1()  asm volatile("cp.async.wait_group 1;" ::: "memory")
#define CP_WAIT0()  asm volatile("cp.async.wait_group 0;" ::: "memory")

__device__ __forceinline__ void ldsm_x4(uint32_t addr, uint32_t& r0, uint32_t& r1,
                                        uint32_t& r2, uint32_t& r3) {
    asm volatile("ldmatrix.sync.aligned.m8n8.x4.shared.b16 {%0,%1,%2,%3}, [%4];"
                 : "=r"(r0), "=r"(r1), "=r"(r2), "=r"(r3) : "r"(addr));
}
__device__ __forceinline__ void mma_f16(float* c, const uint32_t* a, const uint32_t* b) {
    asm volatile(
        "mma.sync.aligned.m16n8k16.row.col.f32.f16.f16.f32 "
        "{%0,%1,%2,%3}, {%4,%5,%6,%7}, {%8,%9}, {%0,%1,%2,%3};"
        : "+f"(c[0]), "+f"(c[1]), "+f"(c[2]), "+f"(c[3])
        : "r"(a[0]), "r"(a[1]), "r"(a[2]), "r"(a[3]), "r"(b[0]), "r"(b[1]));
}
__device__ __forceinline__ uint32_t pack_h2(__half a, __half b) {
    __half2 t = __halves2half2(a, b);
    return *(uint32_t*)&t;
}
// fp32 pair -> fp16 hi + fp16 lo (residual)
__device__ __forceinline__ void split2h(float v0, float v1, uint32_t& hi, uint32_t& lo) {
    __half h0 = __float2half_rn(v0), h1 = __float2half_rn(v1);
    __half l0 = __float2half_rn(v0 - __half2float(h0));
    __half l1 = __float2half_rn(v1 - __half2float(h1));
    hi = pack_h2(h0, h1);
    lo = pack_h2(l0, l1);
}
__device__ __forceinline__ uint32_t trunc2h(float v0, float v1) {
    return pack_h2(__float2half_rn(v0), __float2half_rn(v1));
}

// ---------------------------------------------------------------------------
// HMMA GEMM (fp16x2): C[m,n] = sum_k Ah[m,k] * (Bh+Bl)[n,k]
// A row-major [M,K] (lda, fp16 hi only), B row-major [N,K] (ldb, hi+lo) -> NT
// CTA tile 128x128, BK=32, 2-stage cp.async double buffer, 8 warps (2x4),
// warp tile 64x32. 80B padded rows -> conflict-free ldmatrix. 2 CTAs/SM.
// ---------------------------------------------------------------------------
constexpr int ROWB    = 80;
constexpr int MAT_B   = 128 * ROWB;     // 10240
constexpr int STAGE_B = 3 * MAT_B;      // Ah, Bh, Bl = 30720
constexpr int SMEM_TOTAL = 2 * STAGE_B; // 61440 -> 2 CTAs/SM

template<bool HILO, bool BIAS>
__global__ void __launch_bounds__(256, 2)
tc_gemm(const __half* __restrict__ aHi,
        const __half* __restrict__ bHi, const __half* __restrict__ bLo,
        const float* __restrict__ bias,
        float* __restrict__ cF,
        __half* __restrict__ cHi, __half* __restrict__ cLo,
        int K, int lda, int ldb, int ldc,
        long aOut, long aIn, long bOut, long bIn, long cOut, long cIn,
        int Hdiv, float alpha)
{
    extern __shared__ __align__(128) char smem[];
    const uint32_t sb = smem_u32(smem);
    const int tid  = threadIdx.x;
    const int wid  = tid >> 5, lane = tid & 31;

    const int z  = blockIdx.z;
    const int zb = z / Hdiv, zh = z % Hdiv;
    const size_t aoff = (size_t)zb * aOut + (size_t)zh * aIn + (size_t)blockIdx.y * 128 * lda;
    const size_t boff = (size_t)zb * bOut + (size_t)zh * bIn + (size_t)blockIdx.x * 128 * ldb;
    aHi += aoff; bHi += boff; bLo += boff;

    const int l_row0 = tid >> 2;
    const int l_c0   = tid & 3;
    const int l_row1 = (tid + 256) >> 2;
    const int l_c1   = tid & 3;

    #define LOAD_STAGE(kt, slot)                                                  \
    do {                                                                          \
        const uint32_t s_ = sb + (slot) * STAGE_B;                                \
        const int kb_ = (kt) * 32;                                                \
        cp16(s_ + l_row0*ROWB + l_c0*16,           aHi + (size_t)l_row0*lda + kb_ + l_c0*8); \
        cp16(s_ + l_row1*ROWB + l_c1*16,           aHi + (size_t)l_row1*lda + kb_ + l_c1*8); \
        cp16(s_ + MAT_B + l_row0*ROWB + l_c0*16,   bHi + (size_t)l_row0*ldb + kb_ + l_c0*8); \
        cp16(s_ + MAT_B + l_row1*ROWB + l_c1*16,   bHi + (size_t)l_row1*ldb + kb_ + l_c1*8); \
        cp16(s_ + 2*MAT_B + l_row0*ROWB + l_c0*16, bLo + (size_t)l_row0*ldb + kb_ + l_c0*8); \
        cp16(s_ + 2*MAT_B + l_row1*ROWB + l_c1*16, bLo + (size_t)l_row1*ldb + kb_ + l_c1*8); \
    } while (0)

    const int wm = (wid >> 2) * 64;
    const int wn = (wid & 3) * 32;

    const int sel    = lane >> 3;
    const int within = lane & 7;
    const uint32_t aBase = (uint32_t)((wm + within + (sel & 1) * 8) * ROWB + (sel >> 1) * 16);
    const uint32_t bBase = (uint32_t)(MAT_B + (wn + within + (sel >> 1) * 8) * ROWB + (sel & 1) * 16);

    float acc[4][4][4];
    #pragma unroll
    for (int i = 0; i < 4; i++)
        #pragma unroll
        for (int j = 0; j < 4; j++)
            #pragma unroll
            for (int r = 0; r < 4; r++)
                acc[i][j][r] = 0.f;

    const int nk = K >> 5;

    LOAD_STAGE(0, 0); CP_COMMIT();
    if (nk > 1) LOAD_STAGE(1, 1);
    CP_COMMIT();
    CP_WAIT1();
    __syncthreads();

    for (int kt = 0; kt < nk; ++kt) {
        const uint32_t sS = sb + (kt & 1) * STAGE_B;
        #pragma unroll
        for (int ks = 0; ks < 2; ks++) {
            uint32_t aH[4][4], bH[4][2], bL[4][2];
            #pragma unroll
            for (int mt = 0; mt < 4; mt++) {
                uint32_t ad = sS + aBase + mt * (16 * ROWB) + ks * 32;
                ldsm_x4(ad, aH[mt][0], aH[mt][1], aH[mt][2], aH[mt][3]);
            }
            #pragma unroll
            for (int p = 0; p < 2; p++) {
                uint32_t bd = sS + bBase + p * (16 * ROWB) + ks * 32;
                ldsm_x4(bd,         bH[2*p][0], bH[2*p][1], bH[2*p+1][0], bH[2*p+1][1]);
                ldsm_x4(bd + MAT_B, bL[2*p][0], bL[2*p][1], bL[2*p+1][0], bL[2*p+1][1]);
            }
            #pragma unroll
            for (int mt = 0; mt < 4; mt++)
                #pragma unroll
                for (int nt = 0; nt < 4; nt++) {
                    mma_f16(acc[mt][nt], aH[mt], bH[nt]);
                    mma_f16(acc[mt][nt], aH[mt], bL[nt]);
                }
        }
        __syncthreads();
        if (kt + 2 < nk) LOAD_STAGE(kt + 2, kt & 1);
        CP_COMMIT();
        CP_WAIT1();
        __syncthreads();
    }

    const size_t coff = (size_t)zb * cOut + (size_t)zh * cIn;
    const int gr = blockIdx.y * 128 + wm + (lane >> 2);
    const int gc = blockIdx.x * 128 + wn + (lane & 3) * 2;

    #pragma unroll
    for (int mt = 0; mt < 4; mt++) {
        #pragma unroll
        for (int nt = 0; nt < 4; nt++) {
            const int col = gc + nt * 8;
            float b0 = 0.f, b1 = 0.f;
            if (BIAS) { b0 = bias[col]; b1 = bias[col + 1]; }
            #pragma unroll
            for (int half_ = 0; half_ < 2; half_++) {
                const int row = gr + mt * 16 + half_ * 8;
                float v0 = acc[mt][nt][half_ * 2]     * alpha + b0;
                float v1 = acc[mt][nt][half_ * 2 + 1] * alpha + b1;
                if (HILO) {
                    uint32_t hi, lo;
                    split2h(v0, v1, hi, lo);
                    *(uint32_t*)(cHi + coff + (size_t)row * ldc + col) = hi;
                    *(uint32_t*)(cLo + coff + (size_t)row * ldc + col) = lo;
                } else {
                    float2 v; v.x = v0; v.y = v1;
                    *(float2*)(cF + coff + (size_t)row * ldc + col) = v;
                }
            }
        }
    }
    #undef LOAD_STAGE
}

// ---------------------------------------------------------------------------
// Flash attention (fp16x2): per CTA = (head z, 128 q-rows). 8 warps x 16 rows.
// SMEM: Q hi (4 d-chunks) + 3-slot K/Vt (hi+lo) chunk ring.
// S,O in registers; online softmax; P truncated to fp16 in registers.
// ---------------------------------------------------------------------------
constexpr int FKV_CH  = 2 * MAT_B;                 // 20480: one K/V chunk hi+lo
constexpr int FQ_SZ   = 4 * MAT_B;                 // 40960: Q hi (4 d-chunks)
constexpr int FSMEM   = FQ_SZ + 3 * FKV_CH;        // 102400
constexpr float ALPHA = 0.08838834764831845f;      // 1/sqrt(128)

__device__ __forceinline__ void flash_issue_chunk(
    int g, uint32_t sbKV, int lr0, int lp0,
    const __half* kH, const __half* kL,
    const __half* vH, const __half* vL)
{
    const int kt = g >> 3, sub = g & 7;
    const uint32_t dst = sbKV + (g % 3) * FKV_CH;
    if (sub < 4) {
        const size_t r0 = (size_t)(kt * 128 + lr0);
        const int colb = sub * 32 + lp0 * 8;
        cp16(dst + lr0*ROWB + lp0*16,              kH + r0 * QKVW + colb);
        cp16(dst + (lr0+64)*ROWB + lp0*16,         kH + (r0+64) * QKVW + colb);
        cp16(dst + MAT_B + lr0*ROWB + lp0*16,      kL + r0 * QKVW + colb);
        cp16(dst + MAT_B + (lr0+64)*ROWB + lp0*16, kL + (r0+64) * QKVW + colb);
    } else {
        const int colb = kt * 128 + (sub - 4) * 32 + lp0 * 8;
        cp16(dst + lr0*ROWB + lp0*16,              vH + (size_t)lr0 * SEQ + colb);
        cp16(dst + (lr0+64)*ROWB + lp0*16,         vH + (size_t)(lr0+64) * SEQ + colb);
        cp16(dst + MAT_B + lr0*ROWB + lp0*16,      vL + (size_t)lr0 * SEQ + colb);
        cp16(dst + MAT_B + (lr0+64)*ROWB + lp0*16, vL + (size_t)(lr0+64) * SEQ + colb);
    }
}

__global__ void __launch_bounds__(256, 1)
flash_kernel(const __half* __restrict__ qkH, const __half* __restrict__ qkL,
             const __half* __restrict__ vtH, const __half* __restrict__ vtL,
             __half* __restrict__ oH)
{
    extern __shared__ __align__(128) char smem[];
    const uint32_t sb = smem_u32(smem);
    const int tid  = threadIdx.x;
    const int wid  = tid >> 5, lane = tid & 31;
    const int qt   = blockIdx.x;
    const int z    = blockIdx.y;
    const int b    = z >> 4, h = z & 15;

    const __half* qH = qkH + (size_t)b * SEQ * QKVW + h * 384;
    const __half* kH = qH + 128;
    const __half* kL = qkL + (size_t)b * SEQ * QKVW + h * 384 + 128;
    const __half* vH = vtH + (size_t)z * HD * SEQ;
    const __half* vL = vtL + (size_t)z * HD * SEQ;

    const int lr0 = tid >> 2;
    const int lp0 = tid & 3;

    // ---- load Q (4 d-chunks, hi only) ----
    const int q0 = qt * 128;
    #pragma unroll
    for (int c = 0; c < 4; c++) {
        const uint32_t d0 = sb + c * MAT_B;
        const int colb = c * 32 + lp0 * 8;
        cp16(d0 + lr0*ROWB + lp0*16,      qH + (size_t)(q0+lr0) * QKVW + colb);
        cp16(d0 + (lr0+64)*ROWB + lp0*16, qH + (size_t)(q0+lr0+64) * QKVW + colb);
    }
    CP_COMMIT();
    flash_issue_chunk(0, sb + FQ_SZ, lr0, lp0, kH, kL, vH, vL); CP_COMMIT();
    flash_issue_chunk(1, sb + FQ_SZ, lr0, lp0, kH, kL, vH, vL); CP_COMMIT();

    const int sel    = lane >> 3;
    const int within = lane & 7;
    const uint32_t aOff  = (uint32_t)((wid * 16 + within + (sel & 1) * 8) * ROWB + (sel >> 1) * 16);
    const uint32_t bOffB = (uint32_t)((within + (sel >> 1) * 8) * ROWB + (sel & 1) * 16);

    float o[16][4];
    #pragma unroll
    for (int i = 0; i < 16; i++)
        #pragma unroll
        for (int j = 0; j < 4; j++) o[i][j] = 0.f;
    float s[16][4];
    uint32_t pfH[8][4];
    float mA = -1e30f, mB = -1e30f, lA = 0.f, lB = 0.f;

    for (int kt = 0; kt < 16; ++kt) {
        #pragma unroll
        for (int sub = 0; sub < 8; ++sub) {
            const int g = kt * 8 + sub;
            if (g + 1 < 128) { CP_WAIT1(); } else { CP_WAIT0(); }
            __syncthreads();
            if (g + 2 < 128) {
                flash_issue_chunk(g + 2, sb + FQ_SZ, lr0, lp0, kH, kL, vH, vL);
                CP_COMMIT();
            }
            const uint32_t slotB = sb + FQ_SZ + (g % 3) * FKV_CH;

            if (sub < 4) {
                // ---- S-phase: d-chunk = sub ----
                if (sub == 0) {
                    #pragma unroll
                    for (int i = 0; i < 16; i++)
                        #pragma unroll
                        for (int j = 0; j < 4; j++) s[i][j] = 0.f;
                }
                const uint32_t qc = sb + sub * MAT_B;
                #pragma unroll
                for (int ks = 0; ks < 2; ks++) {
                    uint32_t aH4[4];
                    ldsm_x4(qc + aOff + ks*32, aH4[0], aH4[1], aH4[2], aH4[3]);
                    #pragma unroll
                    for (int p = 0; p < 8; p++) {
                        uint32_t bh[4], bl[4];
                        ldsm_x4(slotB + bOffB + p*(16*ROWB) + ks*32,
                                bh[0], bh[1], bh[2], bh[3]);
                        ldsm_x4(slotB + MAT_B + bOffB + p*(16*ROWB) + ks*32,
                                bl[0], bl[1], bl[2], bl[3]);
                        mma_f16(s[2*p],   aH4, bh);
                        mma_f16(s[2*p],   aH4, bl);
                        mma_f16(s[2*p+1], aH4, bh + 2);
                        mma_f16(s[2*p+1], aH4, bl + 2);
                    }
                }
            } else {
                if (sub == 4) {
                    // ---- online softmax over this key tile ----
                    float mtA = -1e30f, mtB = -1e30f;
                    #pragma unroll
                    for (int nt = 0; nt < 16; nt++) {
                        mtA = fmaxf(mtA, fmaxf(s[nt][0], s[nt][1]));
                        mtB = fmaxf(mtB, fmaxf(s[nt][2], s[nt][3]));
                    }
                    mtA = fmaxf(mtA, __shfl_xor_sync(~0u, mtA, 1));
                    mtA = fmaxf(mtA, __shfl_xor_sync(~0u, mtA, 2));
                    mtB = fmaxf(mtB, __shfl_xor_sync(~0u, mtB, 1));
                    mtB = fmaxf(mtB, __shfl_xor_sync(~0u, mtB, 2));
                    const float mnA = fmaxf(mA, mtA);
                    const float mnB = fmaxf(mB, mtB);
                    const float fA = __expf(ALPHA * (mA - mnA));
                    const float fB = __expf(ALPHA * (mB - mnB));
                    #pragma unroll
                    for (int nt = 0; nt < 16; nt++) {
                        o[nt][0] *= fA; o[nt][1] *= fA;
                        o[nt][2] *= fB; o[nt][3] *= fB;
                    }
                    float sA = 0.f, sB = 0.f;
                    #pragma unroll
                    for (int nt = 0; nt < 16; nt++) {
                        const float p0 = __expf(ALPHA * (s[nt][0] - mnA));
                        const float p1 = __expf(ALPHA * (s[nt][1] - mnA));
                        const float p2 = __expf(ALPHA * (s[nt][2] - mnB));
                        const float p3 = __expf(ALPHA * (s[nt][3] - mnB));
                        sA += p0 + p1; sB += p2 + p3;
                        const uint32_t h01 = trunc2h(p0, p1);
                        const uint32_t h23 = trunc2h(p2, p3);
                        const int kf = nt >> 1;
                        if ((nt & 1) == 0) {
                            pfH[kf][0] = h01; pfH[kf][1] = h23;
                        } else {
                            pfH[kf][2] = h01; pfH[kf][3] = h23;
                        }
                    }
                    sA += __shfl_xor_sync(~0u, sA, 1);
                    sA += __shfl_xor_sync(~0u, sA, 2);
                    sB += __shfl_xor_sync(~0u, sB, 1);
                    sB += __shfl_xor_sync(~0u, sB, 2);
                    lA = lA * fA + sA;
                    lB = lB * fB + sB;
                    mA = mnA; mB = mnB;
                }
                // ---- PV-phase: key-chunk c = sub-4, kf = 2c+ks ----
                #pragma unroll
                for (int ks = 0; ks < 2; ks++) {
                    const int kf = 2 * (sub - 4) + ks;
                    #pragma unroll
                    for (int p = 0; p < 8; p++) {
                        uint32_t bh[4], bl[4];
                        ldsm_x4(slotB + bOffB + p*(16*ROWB) + ks*32,
                                bh[0], bh[1], bh[2], bh[3]);
                        ldsm_x4(slotB + MAT_B + bOffB + p*(16*ROWB) + ks*32,
                                bl[0], bl[1], bl[2], bl[3]);
                        mma_f16(o[2*p],   pfH[kf], bh);
                        mma_f16(o[2*p],   pfH[kf], bl);
                        mma_f16(o[2*p+1], pfH[kf], bh + 2);
                        mma_f16(o[2*p+1], pfH[kf], bl + 2);
                    }
                }
            }
        }
    }

    // ---- normalize + store O (fp16 hi, attn layout [b][s][h*128+d]) ----
    const float invA = 1.f / lA;
    const float invB = 1.f / lB;
    const size_t rowA = (size_t)b * SEQ + q0 + wid * 16 + (lane >> 2);
    const size_t baseA = rowA * DMODEL + h * 128 + (lane & 3) * 2;
    const size_t baseB = baseA + (size_t)8 * DMODEL;
    #pragma unroll
    for (int nt = 0; nt < 16; nt++) {
        *(uint32_t*)(oH + baseA + nt * 8) = trunc2h(o[nt][0] * invA, o[nt][1] * invA);
        *(uint32_t*)(oH + baseB + nt * 8) = trunc2h(o[nt][2] * invB, o[nt][3] * invB);
    }
}

// ---------------------------------------------------------------------------
// fp32 -> fp16 hi/lo split (elementwise, float4)
// ---------------------------------------------------------------------------
__global__ void __launch_bounds__(256)
split_kernel(const float* __restrict__ in, __half* __restrict__ hi,
             __half* __restrict__ lo)
{
    const long i = (long)blockIdx.x * 256 + threadIdx.x;   // float4 index
    float4 v = ((const float4*)in)[i];
    uint32_t h0, l0, h1, l1;
    split2h(v.x, v.y, h0, l0);
    split2h(v.z, v.w, h1, l1);
    ((uint32_t*)hi)[i * 2]     = h0;
    ((uint32_t*)hi)[i * 2 + 1] = h1;
    if (lo) {
        ((uint32_t*)lo)[i * 2]     = l0;
        ((uint32_t*)lo)[i * 2 + 1] = l1;
    }
}
__global__ void __launch_bounds__(256)
trunc_kernel(const float* __restrict__ in, __half* __restrict__ hi)
{
    const long i = (long)blockIdx.x * 256 + threadIdx.x;   // float4 index
    float4 v = ((const float4*)in)[i];
    ((uint32_t*)hi)[i * 2]     = trunc2h(v.x, v.y);
    ((uint32_t*)hi)[i * 2 + 1] = trunc2h(v.z, v.w);
}

// ---------------------------------------------------------------------------
// V transpose: qkv hi/lo (v slice) -> Vt hi/lo [z=bh][d][s]
// ---------------------------------------------------------------------------
__global__ void __launch_bounds__(256)
transpose_v(const __half* __restrict__ qH, const __half* __restrict__ qL,
            __half* __restrict__ vH, __half* __restrict__ vL)
{
    __shared__ __half tH[32][33], tL[32][33];
    const int z = blockIdx.z, b = z >> 4, h = z & 15;
    const int s0 = blockIdx.x * 32, d0 = blockIdx.y * 32;
    const int tx = threadIdx.x & 31, ty = threadIdx.x >> 5;   // 32 x 8
    const size_t ibase = (size_t)b * SEQ * QKVW + (size_t)h * 384 + 256;
    #pragma unroll
    for (int i = 0; i < 4; i++) {
        int s = s0 + ty + i * 8;
        tH[ty + i * 8][tx] = qH[ibase + (size_t)s * QKVW + d0 + tx];
        tL[ty + i * 8][tx] = qL[ibase + (size_t)s * QKVW + d0 + tx];
    }
    __syncthreads();
    const size_t obase = (size_t)z * HD * SEQ;
    #pragma unroll
    for (int i = 0; i < 4; i++) {
        int d = d0 + ty + i * 8;
        vH[obase + (size_t)d * SEQ + s0 + tx] = tH[tx][ty + i * 8];
        vL[obase + (size_t)d * SEQ + s0 + tx] = tL[tx][ty + i * 8];
    }
}

// ---------------------------------------------------------------------------
extern "C" void kernel_launch(void* const* d_in, const int* in_sizes, int n_in,
                              void* d_out, int out_size)
{
    const float* x     = (const float*)d_in[0];
    const float* w_qkv = (const float*)d_in[2];
    const float* b_qkv = (const float*)d_in[3];
    const float* w_o   = (const float*)d_in[4];
    const float* b_o   = (const float*)d_in[5];
    float* out = (float*)d_out;

    __half *xsH, *wqH, *wqL, *woH, *woL, *qkH, *qkL;
    __half *vtH, *vtL, *atH;
    cudaGetSymbolAddress((void**)&xsH, g_xsHi);
    cudaGetSymbolAddress((void**)&wqH, g_wqHi);  cudaGetSymbolAddress((void**)&wqL, g_wqLo);
    cudaGetSymbolAddress((void**)&woH, g_woHi);  cudaGetSymbolAddress((void**)&woL, g_woLo);
    cudaGetSymbolAddress((void**)&qkH, g_qkvHi); cudaGetSymbolAddress((void**)&qkL, g_qkvLo);
    cudaGetSymbolAddress((void**)&vtH, g_vtHi);  cudaGetSymbolAddress((void**)&vtL, g_vtLo);
    cudaGetSymbolAddress((void**)&atH, g_atHi);

    cudaFuncSetAttribute(tc_gemm<true,  true >, cudaFuncAttributeMaxDynamicSharedMemorySize, SMEM_TOTAL);
    cudaFuncSetAttribute(tc_gemm<false, true >, cudaFuncAttributeMaxDynamicSharedMemorySize, SMEM_TOTAL);
    cudaFuncSetAttribute(flash_kernel, cudaFuncAttributeMaxDynamicSharedMemorySize, FSMEM);

    // 0) split inputs (x: hi only; weights: hi+lo)
    trunc_kernel<<<(long)BATCH*SEQ*DMODEL/1024, 256>>>(x, xsH);
    split_kernel<<<(long)QKVW*DMODEL/1024,   256>>>(w_qkv, wqH, wqL);
    split_kernel<<<(long)DMODEL*DMODEL/1024, 256>>>(w_o,   woH, woL);

    // 1) QKV projection -> qkv hi/lo (bias fused)
    {
        dim3 grid(QKVW / 128, (BATCH * SEQ) / 128, 1);
        tc_gemm<true, true><<<grid, 256, SMEM_TOTAL>>>(
            xsH, wqH, wqL, b_qkv, nullptr, qkH, qkL,
            DMODEL, DMODEL, DMODEL, QKVW,
            0, 0, 0, 0, 0, 0, 1, 1.0f);
    }

    // 2) V transpose -> Vt hi/lo
    transpose_v<<<dim3(SEQ / 32, HD / 32, BH), 256>>>(qkH, qkL, vtH, vtL);

    // 3) fused flash attention -> attn fp16
    flash_kernel<<<dim3(SEQ / 128, BH), 256, FSMEM>>>(qkH, qkL, vtH, vtL, atH);

    // 4) output projection (bias fused) -> out fp32
    {
        dim3 grid(DMODEL / 128, (BATCH * SEQ) / 128, 1);
        tc_gemm<false, true><<<grid, 256, SMEM_TOTAL>>>(
            atH, woH, woL, b_o, out, nullptr, nullptr,
            DMODEL, DMODEL, DMODEL, DMODEL,
            0, 0, 0, 0, 0, 0, 1, 1.0f);
    }
}

// round 8
// speedup vs baseline: 3.7544x; 1.1114x over previous
#include <cuda_runtime.h>
#include <cuda_fp16.h>
#include <cstdint>

// Problem shape (fixed): B=2, S=2048, D=2048, H=16, DK=128
constexpr int BATCH  = 2;
constexpr int SEQ    = 2048;
constexpr int DMODEL = 2048;
constexpr int NH     = 16;
constexpr int HD     = 128;
constexpr int QKVW   = 3 * DMODEL;   // 6144
constexpr int BH     = BATCH * NH;   // 32

// ---------------------------------------------------------------------------
// Scratch (device globals — allocation-free per harness rules)
// ---------------------------------------------------------------------------
__device__ __half g_xsHi [(long)BATCH * SEQ * DMODEL];
__device__ __half g_wqHi [(long)QKVW * DMODEL];
__device__ __half g_wqLo [(long)QKVW * DMODEL];
__device__ __half g_woHi [(long)DMODEL * DMODEL];
__device__ __half g_woLo [(long)DMODEL * DMODEL];
__device__ __half g_qkvHi[(long)BATCH * SEQ * QKVW];
__device__ __half g_qkvLo[(long)BATCH * SEQ * QKVW];
__device__ __half g_vtHi [(long)BH * HD * SEQ];
__device__ __half g_vtLo [(long)BH * HD * SEQ];
__device__ __half g_atHi [(long)BATCH * SEQ * DMODEL];

// ---------------------------------------------------------------------------
// helpers
// ---------------------------------------------------------------------------
__device__ __forceinline__ uint32_t smem_u32(const void* p) {
    uint32_t a;
    asm("{ .reg .u64 t; cvta.to.shared.u64 t, %1; cvt.u32.u64 %0, t; }"
        : "=r"(a) : "l"(p));
    return a;
}
__device__ __forceinline__ void cp16(uint32_t saddr, const void* g) {
    asm volatile("cp.async.cg.shared.global [%0], [%1], 16;" :: "r"(saddr), "l"(g));
}
#define CP_COMMIT() asm volatile("cp.async.commit_group;" ::: "memory")
#define CP_WAIT1()  asm volatile("cp.async.wait_group 1;" ::: "memory")
#define CP_WAIT0()  asm volatile("cp.async.wait_group 0;" ::: "memory")

__device__ __forceinline__ void ldsm_x4(uint32_t addr, uint32_t& r0, uint32_t& r1,
                                        uint32_t& r2, uint32_t& r3) {
    asm volatile("ldmatrix.sync.aligned.m8n8.x4.shared.b16 {%0,%1,%2,%3}, [%4];"
                 : "=r"(r0), "=r"(r1), "=r"(r2), "=r"(r3) : "r"(addr));
}
__device__ __forceinline__ void mma_f16(float* c, const uint32_t* a, const uint32_t* b) {
    asm volatile(
        "mma.sync.aligned.m16n8k16.row.col.f32.f16.f16.f32 "
        "{%0,%1,%2,%3}, {%4,%5,%6,%7}, {%8,%9}, {%0,%1,%2,%3};"
        : "+f"(c[0]), "+f"(c[1]), "+f"(c[2]), "+f"(c[3])
        : "r"(a[0]), "r"(a[1]), "r"(a[2]), "r"(a[3]), "r"(b[0]), "r"(b[1]));
}
__device__ __forceinline__ uint32_t pack_h2(__half a, __half b) {
    __half2 t = __halves2half2(a, b);
    return *(uint32_t*)&t;
}
__device__ __forceinline__ void split2h(float v0, float v1, uint32_t& hi, uint32_t& lo) {
    __half h0 = __float2half_rn(v0), h1 = __float2half_rn(v1);
    __half l0 = __float2half_rn(v0 - __half2float(h0));
    __half l1 = __float2half_rn(v1 - __half2float(h1));
    hi = pack_h2(h0, h1);
    lo = pack_h2(l0, l1);
}
__device__ __forceinline__ uint32_t trunc2h(float v0, float v1) {
    return pack_h2(__float2half_rn(v0), __float2half_rn(v1));
}

// ---------------------------------------------------------------------------
// HMMA GEMM (fp16x2): C[m,n] = sum_k Ah[m,k] * (Bh+Bl)[n,k]
// CTA tile 128x128, BK=32, 3-stage cp.async (1 sync/iter), 8 warps (2x4),
// warp tile 64x32. 80B padded rows -> conflict-free ldmatrix. 2 CTAs/SM.
// ---------------------------------------------------------------------------
constexpr int ROWB    = 80;
constexpr int MAT_B   = 128 * ROWB;     // 10240
constexpr int STAGE_B = 3 * MAT_B;      // Ah, Bh, Bl = 30720
constexpr int SMEM_TOTAL = 3 * STAGE_B; // 92160 -> 2 CTAs/SM (184320 <= 228K)

template<bool HILO, bool BIAS>
__global__ void __launch_bounds__(256, 2)
tc_gemm(const __half* __restrict__ aHi,
        const __half* __restrict__ bHi, const __half* __restrict__ bLo,
        const float* __restrict__ bias,
        float* __restrict__ cF,
        __half* __restrict__ cHi, __half* __restrict__ cLo,
        int K, int lda, int ldb, int ldc,
        long aOut, long aIn, long bOut, long bIn, long cOut, long cIn,
        int Hdiv, float alpha)
{
    extern __shared__ __align__(128) char smem[];
    const uint32_t sb = smem_u32(smem);
    const int tid  = threadIdx.x;
    const int wid  = tid >> 5, lane = tid & 31;

    const int z  = blockIdx.z;
    const int zb = z / Hdiv, zh = z % Hdiv;
    const size_t aoff = (size_t)zb * aOut + (size_t)zh * aIn + (size_t)blockIdx.y * 128 * lda;
    const size_t boff = (size_t)zb * bOut + (size_t)zh * bIn + (size_t)blockIdx.x * 128 * ldb;
    aHi += aoff; bHi += boff; bLo += boff;

    const int l_row0 = tid >> 2;
    const int l_c0   = tid & 3;
    const int l_row1 = (tid + 256) >> 2;
    const int l_c1   = tid & 3;

    #define LOAD_STAGE(kt, slot)                                                  \
    do {                                                                          \
        const uint32_t s_ = sb + (slot) * STAGE_B;                                \
        const int kb_ = (kt) * 32;                                                \
        cp16(s_ + l_row0*ROWB + l_c0*16,           aHi + (size_t)l_row0*lda + kb_ + l_c0*8); \
        cp16(s_ + l_row1*ROWB + l_c1*16,           aHi + (size_t)l_row1*lda + kb_ + l_c1*8); \
        cp16(s_ + MAT_B + l_row0*ROWB + l_c0*16,   bHi + (size_t)l_row0*ldb + kb_ + l_c0*8); \
        cp16(s_ + MAT_B + l_row1*ROWB + l_c1*16,   bHi + (size_t)l_row1*ldb + kb_ + l_c1*8); \
        cp16(s_ + 2*MAT_B + l_row0*ROWB + l_c0*16, bLo + (size_t)l_row0*ldb + kb_ + l_c0*8); \
        cp16(s_ + 2*MAT_B + l_row1*ROWB + l_c1*16, bLo + (size_t)l_row1*ldb + kb_ + l_c1*8); \
    } while (0)

    const int wm = (wid >> 2) * 64;
    const int wn = (wid & 3) * 32;

    const int sel    = lane >> 3;
    const int within = lane & 7;
    const uint32_t aBase = (uint32_t)((wm + within + (sel & 1) * 8) * ROWB + (sel >> 1) * 16);
    const uint32_t bBase = (uint32_t)(MAT_B + (wn + within + (sel >> 1) * 8) * ROWB + (sel & 1) * 16);

    float acc[4][4][4];
    #pragma unroll
    for (int i = 0; i < 4; i++)
        #pragma unroll
        for (int j = 0; j < 4; j++)
            #pragma unroll
            for (int r = 0; r < 4; r++)
                acc[i][j][r] = 0.f;

    const int nk = K >> 5;

    LOAD_STAGE(0, 0); CP_COMMIT();
    if (nk > 1) LOAD_STAGE(1, 1);
    CP_COMMIT();
    CP_WAIT1();
    __syncthreads();

    for (int kt = 0; kt < nk; ++kt) {
        const uint32_t sS = sb + (kt % 3) * STAGE_B;
        #pragma unroll
        for (int ks = 0; ks < 2; ks++) {
            uint32_t aH[4][4], bH[4][2], bL[4][2];
            #pragma unroll
            for (int mt = 0; mt < 4; mt++) {
                uint32_t ad = sS + aBase + mt * (16 * ROWB) + ks * 32;
                ldsm_x4(ad, aH[mt][0], aH[mt][1], aH[mt][2], aH[mt][3]);
            }
            #pragma unroll
            for (int p = 0; p < 2; p++) {
                uint32_t bd = sS + bBase + p * (16 * ROWB) + ks * 32;
                ldsm_x4(bd,         bH[2*p][0], bH[2*p][1], bH[2*p+1][0], bH[2*p+1][1]);
                ldsm_x4(bd + MAT_B, bL[2*p][0], bL[2*p][1], bL[2*p+1][0], bL[2*p+1][1]);
            }
            #pragma unroll
            for (int mt = 0; mt < 4; mt++)
                #pragma unroll
                for (int nt = 0; nt < 4; nt++) {
                    mma_f16(acc[mt][nt], aH[mt], bH[nt]);
                    mma_f16(acc[mt][nt], aH[mt], bL[nt]);
                }
        }
        // slot (kt+2)%3 was fully consumed at iteration kt-1 (barrier below
        // of that iteration fences its readers) -> safe to overwrite now.
        if (kt + 2 < nk) LOAD_STAGE(kt + 2, (kt + 2) % 3);
        CP_COMMIT();
        CP_WAIT1();        // stage kt+1 resident
        __syncthreads();
    }

    const size_t coff = (size_t)zb * cOut + (size_t)zh * cIn;
    const int gr = blockIdx.y * 128 + wm + (lane >> 2);
    const int gc = blockIdx.x * 128 + wn + (lane & 3) * 2;

    #pragma unroll
    for (int mt = 0; mt < 4; mt++) {
        #pragma unroll
        for (int nt = 0; nt < 4; nt++) {
            const int col = gc + nt * 8;
            float b0 = 0.f, b1 = 0.f;
            if (BIAS) { b0 = bias[col]; b1 = bias[col + 1]; }
            #pragma unroll
            for (int half_ = 0; half_ < 2; half_++) {
                const int row = gr + mt * 16 + half_ * 8;
                float v0 = acc[mt][nt][half_ * 2]     * alpha + b0;
                float v1 = acc[mt][nt][half_ * 2 + 1] * alpha + b1;
                if (HILO) {
                    uint32_t hi, lo;
                    split2h(v0, v1, hi, lo);
                    *(uint32_t*)(cHi + coff + (size_t)row * ldc + col) = hi;
                    *(uint32_t*)(cLo + coff + (size_t)row * ldc + col) = lo;
                } else {
                    float2 v; v.x = v0; v.y = v1;
                    *(float2*)(cF + coff + (size_t)row * ldc + col) = v;
                }
            }
        }
    }
    #undef LOAD_STAGE
}

// ---------------------------------------------------------------------------
// Flash attention (fp16x2): per CTA = (head z, 128 q-rows). 8 warps x 16 rows.
// SMEM: Q hi (4 d-chunks) + 3-slot K/Vt (hi+lo) chunk ring.
// ---------------------------------------------------------------------------
constexpr int FKV_CH  = 2 * MAT_B;                 // 20480
constexpr int FQ_SZ   = 4 * MAT_B;                 // 40960
constexpr int FSMEM   = FQ_SZ + 3 * FKV_CH;        // 102400
constexpr float ALPHA = 0.08838834764831845f;      // 1/sqrt(128)

__device__ __forceinline__ void flash_issue_chunk(
    int g, uint32_t sbKV, int lr0, int lp0,
    const __half* kH, const __half* kL,
    const __half* vH, const __half* vL)
{
    const int kt = g >> 3, sub = g & 7;
    const uint32_t dst = sbKV + (g % 3) * FKV_CH;
    if (sub < 4) {
        const size_t r0 = (size_t)(kt * 128 + lr0);
        const int colb = sub * 32 + lp0 * 8;
        cp16(dst + lr0*ROWB + lp0*16,              kH + r0 * QKVW + colb);
        cp16(dst + (lr0+64)*ROWB + lp0*16,         kH + (r0+64) * QKVW + colb);
        cp16(dst + MAT_B + lr0*ROWB + lp0*16,      kL + r0 * QKVW + colb);
        cp16(dst + MAT_B + (lr0+64)*ROWB + lp0*16, kL + (r0+64) * QKVW + colb);
    } else {
        const int colb = kt * 128 + (sub - 4) * 32 + lp0 * 8;
        cp16(dst + lr0*ROWB + lp0*16,              vH + (size_t)lr0 * SEQ + colb);
        cp16(dst + (lr0+64)*ROWB + lp0*16,         vH + (size_t)(lr0+64) * SEQ + colb);
        cp16(dst + MAT_B + lr0*ROWB + lp0*16,      vL + (size_t)lr0 * SEQ + colb);
        cp16(dst + MAT_B + (lr0+64)*ROWB + lp0*16, vL + (size_t)(lr0+64) * SEQ + colb);
    }
}

__global__ void __launch_bounds__(256, 1)
flash_kernel(const __half* __restrict__ qkH, const __half* __restrict__ qkL,
             const __half* __restrict__ vtH, const __half* __restrict__ vtL,
             __half* __restrict__ oH)
{
    extern __shared__ __align__(128) char smem[];
    const uint32_t sb = smem_u32(smem);
    const int tid  = threadIdx.x;
    const int wid  = tid >> 5, lane = tid & 31;
    const int qt   = blockIdx.x;
    const int z    = blockIdx.y;
    const int b    = z >> 4, h = z & 15;

    const __half* qH = qkH + (size_t)b * SEQ * QKVW + h * 384;
    const __half* kH = qH + 128;
    const __half* kL = qkL + (size_t)b * SEQ * QKVW + h * 384 + 128;
    const __half* vH = vtH + (size_t)z * HD * SEQ;
    const __half* vL = vtL + (size_t)z * HD * SEQ;

    const int lr0 = tid >> 2;
    const int lp0 = tid & 3;

    const int q0 = qt * 128;
    #pragma unroll
    for (int c = 0; c < 4; c++) {
        const uint32_t d0 = sb + c * MAT_B;
        const int colb = c * 32 + lp0 * 8;
        cp16(d0 + lr0*ROWB + lp0*16,      qH + (size_t)(q0+lr0) * QKVW + colb);
        cp16(d0 + (lr0+64)*ROWB + lp0*16, qH + (size_t)(q0+lr0+64) * QKVW + colb);
    }
    CP_COMMIT();
    flash_issue_chunk(0, sb + FQ_SZ, lr0, lp0, kH, kL, vH, vL); CP_COMMIT();
    flash_issue_chunk(1, sb + FQ_SZ, lr0, lp0, kH, kL, vH, vL); CP_COMMIT();

    const int sel    = lane >> 3;
    const int within = lane & 7;
    const uint32_t aOff  = (uint32_t)((wid * 16 + within + (sel & 1) * 8) * ROWB + (sel >> 1) * 16);
    const uint32_t bOffB = (uint32_t)((within + (sel >> 1) * 8) * ROWB + (sel & 1) * 16);

    float o[16][4];
    #pragma unroll
    for (int i = 0; i < 16; i++)
        #pragma unroll
        for (int j = 0; j < 4; j++) o[i][j] = 0.f;
    float s[16][4];
    uint32_t pfH[8][4];
    float mA = -1e30f, mB = -1e30f, lA = 0.f, lB = 0.f;

    for (int kt = 0; kt < 16; ++kt) {
        #pragma unroll
        for (int sub = 0; sub < 8; ++sub) {
            const int g = kt * 8 + sub;
            if (g + 1 < 128) { CP_WAIT1(); } else { CP_WAIT0(); }
            __syncthreads();
            if (g + 2 < 128) {
                flash_issue_chunk(g + 2, sb + FQ_SZ, lr0, lp0, kH, kL, vH, vL);
                CP_COMMIT();
            }
            const uint32_t slotB = sb + FQ_SZ + (g % 3) * FKV_CH;

            if (sub < 4) {
                if (sub == 0) {
                    #pragma unroll
                    for (int i = 0; i < 16; i++)
                        #pragma unroll
                        for (int j = 0; j < 4; j++) s[i][j] = 0.f;
                }
                const uint32_t qc = sb + sub * MAT_B;
                #pragma unroll
                for (int ks = 0; ks < 2; ks++) {
                    uint32_t aH4[4];
                    ldsm_x4(qc + aOff + ks*32, aH4[0], aH4[1], aH4[2], aH4[3]);
                    #pragma unroll
                    for (int p = 0; p < 8; p++) {
                        uint32_t bh[4], bl[4];
                        ldsm_x4(slotB + bOffB + p*(16*ROWB) + ks*32,
                                bh[0], bh[1], bh[2], bh[3]);
                        ldsm_x4(slotB + MAT_B + bOffB + p*(16*ROWB) + ks*32,
                                bl[0], bl[1], bl[2], bl[3]);
                        mma_f16(s[2*p],   aH4, bh);
                        mma_f16(s[2*p],   aH4, bl);
                        mma_f16(s[2*p+1], aH4, bh + 2);
                        mma_f16(s[2*p+1], aH4, bl + 2);
                    }
                }
            } else {
                if (sub == 4) {
                    float mtA = -1e30f, mtB = -1e30f;
                    #pragma unroll
                    for (int nt = 0; nt < 16; nt++) {
                        mtA = fmaxf(mtA, fmaxf(s[nt][0], s[nt][1]));
                        mtB = fmaxf(mtB, fmaxf(s[nt][2], s[nt][3]));
                    }
                    mtA = fmaxf(mtA, __shfl_xor_sync(~0u, mtA, 1));
                    mtA = fmaxf(mtA, __shfl_xor_sync(~0u, mtA, 2));
                    mtB = fmaxf(mtB, __shfl_xor_sync(~0u, mtB, 1));
                    mtB = fmaxf(mtB, __shfl_xor_sync(~0u, mtB, 2));
                    const float mnA = fmaxf(mA, mtA);
                    const float mnB = fmaxf(mB, mtB);
                    const float fA = __expf(ALPHA * (mA - mnA));
                    const float fB = __expf(ALPHA * (mB - mnB));
                    #pragma unroll
                    for (int nt = 0; nt < 16; nt++) {
                        o[nt][0] *= fA; o[nt][1] *= fA;
                        o[nt][2] *= fB; o[nt][3] *= fB;
                    }
                    float sA = 0.f, sB = 0.f;
                    #pragma unroll
                    for (int nt = 0; nt < 16; nt++) {
                        const float p0 = __expf(ALPHA * (s[nt][0] - mnA));
                        const float p1 = __expf(ALPHA * (s[nt][1] - mnA));
                        const float p2 = __expf(ALPHA * (s[nt][2] - mnB));
                        const float p3 = __expf(ALPHA * (s[nt][3] - mnB));
                        sA += p0 + p1; sB += p2 + p3;
                        const uint32_t h01 = trunc2h(p0, p1);
                        const uint32_t h23 = trunc2h(p2, p3);
                        const int kf = nt >> 1;
                        if ((nt & 1) == 0) {
                            pfH[kf][0] = h01; pfH[kf][1] = h23;
                        } else {
                            pfH[kf][2] = h01; pfH[kf][3] = h23;
                        }
                    }
                    sA += __shfl_xor_sync(~0u, sA, 1);
                    sA += __shfl_xor_sync(~0u, sA, 2);
                    sB += __shfl_xor_sync(~0u, sB, 1);
                    sB += __shfl_xor_sync(~0u, sB, 2);
                    lA = lA * fA + sA;
                    lB = lB * fB + sB;
                    mA = mnA; mB = mnB;
                }
                #pragma unroll
                for (int ks = 0; ks < 2; ks++) {
                    const int kf = 2 * (sub - 4) + ks;
                    #pragma unroll
                    for (int p = 0; p < 8; p++) {
                        uint32_t bh[4], bl[4];
                        ldsm_x4(slotB + bOffB + p*(16*ROWB) + ks*32,
                                bh[0], bh[1], bh[2], bh[3]);
                        ldsm_x4(slotB + MAT_B + bOffB + p*(16*ROWB) + ks*32,
                                bl[0], bl[1], bl[2], bl[3]);
                        mma_f16(o[2*p],   pfH[kf], bh);
                        mma_f16(o[2*p],   pfH[kf], bl);
                        mma_f16(o[2*p+1], pfH[kf], bh + 2);
                        mma_f16(o[2*p+1], pfH[kf], bl + 2);
                    }
                }
            }
        }
    }

    const float invA = 1.f / lA;
    const float invB = 1.f / lB;
    const size_t rowA = (size_t)b * SEQ + q0 + wid * 16 + (lane >> 2);
    const size_t baseA = rowA * DMODEL + h * 128 + (lane & 3) * 2;
    const size_t baseB = baseA + (size_t)8 * DMODEL;
    #pragma unroll
    for (int nt = 0; nt < 16; nt++) {
        *(uint32_t*)(oH + baseA + nt * 8) = trunc2h(o[nt][0] * invA, o[nt][1] * invA);
        *(uint32_t*)(oH + baseB + nt * 8) = trunc2h(o[nt][2] * invB, o[nt][3] * invB);
    }
}

// ---------------------------------------------------------------------------
// fp32 -> fp16 hi/lo split (elementwise, float4)
// ---------------------------------------------------------------------------
__global__ void __launch_bounds__(256)
split_kernel(const float* __restrict__ in, __half* __restrict__ hi,
             __half* __restrict__ lo)
{
    const long i = (long)blockIdx.x * 256 + threadIdx.x;
    float4 v = ((const float4*)in)[i];
    uint32_t h0, l0, h1, l1;
    split2h(v.x, v.y, h0, l0);
    split2h(v.z, v.w, h1, l1);
    ((uint32_t*)hi)[i * 2]     = h0;
    ((uint32_t*)hi)[i * 2 + 1] = h1;
    ((uint32_t*)lo)[i * 2]     = l0;
    ((uint32_t*)lo)[i * 2 + 1] = l1;
}
__global__ void __launch_bounds__(256)
trunc_kernel(const float* __restrict__ in, __half* __restrict__ hi)
{
    const long i = (long)blockIdx.x * 256 + threadIdx.x;
    float4 v = ((const float4*)in)[i];
    ((uint32_t*)hi)[i * 2]     = trunc2h(v.x, v.y);
    ((uint32_t*)hi)[i * 2 + 1] = trunc2h(v.z, v.w);
}

// ---------------------------------------------------------------------------
// V transpose: qkv hi/lo (v slice) -> Vt hi/lo [z=bh][d][s]
// ---------------------------------------------------------------------------
__global__ void __launch_bounds__(256)
transpose_v(const __half* __restrict__ qH, const __half* __restrict__ qL,
            __half* __restrict__ vH, __half* __restrict__ vL)
{
    __shared__ __half tH[32][33], tL[32][33];
    const int z = blockIdx.z, b = z >> 4, h = z & 15;
    const int s0 = blockIdx.x * 32, d0 = blockIdx.y * 32;
    const int tx = threadIdx.x & 31, ty = threadIdx.x >> 5;
    const size_t ibase = (size_t)b * SEQ * QKVW + (size_t)h * 384 + 256;
    #pragma unroll
    for (int i = 0; i < 4; i++) {
        int s = s0 + ty + i * 8;
        tH[ty + i * 8][tx] = qH[ibase + (size_t)s * QKVW + d0 + tx];
        tL[ty + i * 8][tx] = qL[ibase + (size_t)s * QKVW + d0 + tx];
    }
    __syncthreads();
    const size_t obase = (size_t)z * HD * SEQ;
    #pragma unroll
    for (int i = 0; i < 4; i++) {
        int d = d0 + ty + i * 8;
        vH[obase + (size_t)d * SEQ + s0 + tx] = tH[tx][ty + i * 8];
        vL[obase + (size_t)d * SEQ + s0 + tx] = tL[tx][ty + i * 8];
    }
}

// ---------------------------------------------------------------------------
extern "C" void kernel_launch(void* const* d_in, const int* in_sizes, int n_in,
                              void* d_out, int out_size)
{
    const float* x     = (const float*)d_in[0];
    const float* w_qkv = (const float*)d_in[2];
    const float* b_qkv = (const float*)d_in[3];
    const float* w_o   = (const float*)d_in[4];
    const float* b_o   = (const float*)d_in[5];
    float* out = (float*)d_out;

    __half *xsH, *wqH, *wqL, *woH, *woL, *qkH, *qkL;
    __half *vtH, *vtL, *atH;
    cudaGetSymbolAddress((void**)&xsH, g_xsHi);
    cudaGetSymbolAddress((void**)&wqH, g_wqHi);  cudaGetSymbolAddress((void**)&wqL, g_wqLo);
    cudaGetSymbolAddress((void**)&woH, g_woHi);  cudaGetSymbolAddress((void**)&woL, g_woLo);
    cudaGetSymbolAddress((void**)&qkH, g_qkvHi); cudaGetSymbolAddress((void**)&qkL, g_qkvLo);
    cudaGetSymbolAddress((void**)&vtH, g_vtHi);  cudaGetSymbolAddress((void**)&vtL, g_vtLo);
    cudaGetSymbolAddress((void**)&atH, g_atHi);

    cudaFuncSetAttribute(tc_gemm<true,  true >, cudaFuncAttributeMaxDynamicSharedMemorySize, SMEM_TOTAL);
    cudaFuncSetAttribute(tc_gemm<false, true >, cudaFuncAttributeMaxDynamicSharedMemorySize, SMEM_TOTAL);
    cudaFuncSetAttribute(flash_kernel, cudaFuncAttributeMaxDynamicSharedMemorySize, FSMEM);

    // 0) split inputs (x: hi only; weights: hi+lo)
    trunc_kernel<<<(long)BATCH*SEQ*DMODEL/1024, 256>>>(x, xsH);
    split_kernel<<<(long)QKVW*DMODEL/1024,   256>>>(w_qkv, wqH, wqL);
    split_kernel<<<(long)DMODEL*DMODEL/1024, 256>>>(w_o,   woH, woL);

    // 1) QKV projection -> qkv hi/lo (bias fused)
    {
        dim3 grid(QKVW / 128, (BATCH * SEQ) / 128, 1);
        tc_gemm<true, true><<<grid, 256, SMEM_TOTAL>>>(
            xsH, wqH, wqL, b_qkv, nullptr, qkH, qkL,
            DMODEL, DMODEL, DMODEL, QKVW,
            0, 0, 0, 0, 0, 0, 1, 1.0f);
    }

    // 2) V transpose -> Vt hi/lo
    transpose_v<<<dim3(SEQ / 32, HD / 32, BH), 256>>>(qkH, qkL, vtH, vtL);

    // 3) fused flash attention -> attn fp16
    flash_kernel<<<dim3(SEQ / 128, BH), 256, FSMEM>>>(qkH, qkL, vtH, vtL, atH);

    // 4) output projection (bias fused) -> out fp32
    {
        dim3 grid(DMODEL / 128, (BATCH * SEQ) / 128, 1);
        tc_gemm<false, true><<<grid, 256, SMEM_TOTAL>>>(
            atH, woH, woL, b_o, out, nullptr, nullptr,
            DMODEL, DMODEL, DMODEL, DMODEL,
            0, 0, 0, 0, 0, 0, 1, 1.0f);
    }
}

// round 9
// speedup vs baseline: 4.4152x; 1.1760x over previous
#include <cuda_runtime.h>
#include <cuda_fp16.h>
#include <cstdint>

// Problem shape (fixed): B=2, S=2048, D=2048, H=16, DK=128
constexpr int BATCH  = 2;
constexpr int SEQ    = 2048;
constexpr int DMODEL = 2048;
constexpr int NH     = 16;
constexpr int HD     = 128;
constexpr int QKVW   = 3 * DMODEL;   // 6144
constexpr int BH     = BATCH * NH;   // 32

// ---------------------------------------------------------------------------
// Scratch (device globals — allocation-free per harness rules)
// ---------------------------------------------------------------------------
__device__ __half g_xsHi [(long)BATCH * SEQ * DMODEL];
__device__ __half g_wqHi [(long)QKVW * DMODEL];
__device__ __half g_wqLo [(long)QKVW * DMODEL];
__device__ __half g_woHi [(long)DMODEL * DMODEL];
__device__ __half g_woLo [(long)DMODEL * DMODEL];
__device__ __half g_qkvHi[(long)BATCH * SEQ * QKVW];
__device__ __half g_qkvLo[(long)BATCH * SEQ * QKVW];
__device__ __half g_vtHi [(long)BH * HD * SEQ];
__device__ __half g_vtLo [(long)BH * HD * SEQ];
__device__ __half g_atHi [(long)BATCH * SEQ * DMODEL];

// ---------------------------------------------------------------------------
// helpers
// ---------------------------------------------------------------------------
__device__ __forceinline__ uint32_t smem_u32(const void* p) {
    uint32_t a;
    asm("{ .reg .u64 t; cvta.to.shared.u64 t, %1; cvt.u32.u64 %0, t; }"
        : "=r"(a) : "l"(p));
    return a;
}
__device__ __forceinline__ void cp16(uint32_t saddr, const void* g) {
    asm volatile("cp.async.cg.shared.global [%0], [%1], 16;" :: "r"(saddr), "l"(g));
}
#define CP_COMMIT() asm volatile("cp.async.commit_group;" ::: "memory")
#define CP_WAIT1()  asm volatile("cp.async.wait_group 1;" ::: "memory")
#define CP_WAIT0()  asm volatile("cp.async.wait_group 0;" ::: "memory")

__device__ __forceinline__ void ldsm_x4(uint32_t addr, uint32_t& r0, uint32_t& r1,
                                        uint32_t& r2, uint32_t& r3) {
    asm volatile("ldmatrix.sync.aligned.m8n8.x4.shared.b16 {%0,%1,%2,%3}, [%4];"
                 : "=r"(r0), "=r"(r1), "=r"(r2), "=r"(r3) : "r"(addr));
}
__device__ __forceinline__ void mma_f16(float* c, const uint32_t* a, const uint32_t* b) {
    asm volatile(
        "mma.sync.aligned.m16n8k16.row.col.f32.f16.f16.f32 "
        "{%0,%1,%2,%3}, {%4,%5,%6,%7}, {%8,%9}, {%0,%1,%2,%3};"
        : "+f"(c[0]), "+f"(c[1]), "+f"(c[2]), "+f"(c[3])
        : "r"(a[0]), "r"(a[1]), "r"(a[2]), "r"(a[3]), "r"(b[0]), "r"(b[1]));
}
__device__ __forceinline__ uint32_t pack_h2(__half a, __half b) {
    __half2 t = __halves2half2(a, b);
    return *(uint32_t*)&t;
}
__device__ __forceinline__ void split2h(float v0, float v1, uint32_t& hi, uint32_t& lo) {
    __half h0 = __float2half_rn(v0), h1 = __float2half_rn(v1);
    __half l0 = __float2half_rn(v0 - __half2float(h0));
    __half l1 = __float2half_rn(v1 - __half2float(h1));
    hi = pack_h2(h0, h1);
    lo = pack_h2(l0, l1);
}
__device__ __forceinline__ uint32_t trunc2h(float v0, float v1) {
    return pack_h2(__float2half_rn(v0), __float2half_rn(v1));
}

// ---------------------------------------------------------------------------
// HMMA GEMM (fp16x2): C[m,n] = sum_k Ah[m,k] * (Bh[+Bl])[n,k]
// loMode: 0 = B-lo everywhere; 1 = B-lo only on tiles with blockIdx.x%3==2
// (QKV layout: every 128-wide N-tile is purely q, k, or v; only v needs lo).
// CTA tile 128x128, BK=32, 3-stage cp.async (1 sync/iter), 8 warps (2x4),
// warp tile 64x32. 80B padded rows -> conflict-free ldmatrix. 2 CTAs/SM.
// ---------------------------------------------------------------------------
constexpr int ROWB    = 80;
constexpr int MAT_B   = 128 * ROWB;     // 10240
constexpr int STAGE_B = 3 * MAT_B;      // Ah, Bh, Bl = 30720
constexpr int SMEM_TOTAL = 3 * STAGE_B; // 92160 -> 2 CTAs/SM

template<bool HILO, bool BIAS>
__global__ void __launch_bounds__(256, 2)
tc_gemm(const __half* __restrict__ aHi,
        const __half* __restrict__ bHi, const __half* __restrict__ bLo,
        const float* __restrict__ bias,
        float* __restrict__ cF,
        __half* __restrict__ cHi, __half* __restrict__ cLo,
        int K, int lda, int ldb, int ldc,
        long aOut, long aIn, long bOut, long bIn, long cOut, long cIn,
        int Hdiv, float alpha, int loMode)
{
    extern __shared__ __align__(128) char smem[];
    const uint32_t sb = smem_u32(smem);
    const int tid  = threadIdx.x;
    const int wid  = tid >> 5, lane = tid & 31;
    const bool useLo = (loMode == 0) || ((blockIdx.x % 3) == 2);

    const int z  = blockIdx.z;
    const int zb = z / Hdiv, zh = z % Hdiv;
    const size_t aoff = (size_t)zb * aOut + (size_t)zh * aIn + (size_t)blockIdx.y * 128 * lda;
    const size_t boff = (size_t)zb * bOut + (size_t)zh * bIn + (size_t)blockIdx.x * 128 * ldb;
    aHi += aoff; bHi += boff; bLo += boff;

    const int l_row0 = tid >> 2;
    const int l_c0   = tid & 3;
    const int l_row1 = (tid + 256) >> 2;
    const int l_c1   = tid & 3;

    #define LOAD_STAGE(kt, slot)                                                  \
    do {                                                                          \
        const uint32_t s_ = sb + (slot) * STAGE_B;                                \
        const int kb_ = (kt) * 32;                                                \
        cp16(s_ + l_row0*ROWB + l_c0*16,           aHi + (size_t)l_row0*lda + kb_ + l_c0*8); \
        cp16(s_ + l_row1*ROWB + l_c1*16,           aHi + (size_t)l_row1*lda + kb_ + l_c1*8); \
        cp16(s_ + MAT_B + l_row0*ROWB + l_c0*16,   bHi + (size_t)l_row0*ldb + kb_ + l_c0*8); \
        cp16(s_ + MAT_B + l_row1*ROWB + l_c1*16,   bHi + (size_t)l_row1*ldb + kb_ + l_c1*8); \
        if (useLo) {                                                              \
            cp16(s_ + 2*MAT_B + l_row0*ROWB + l_c0*16, bLo + (size_t)l_row0*ldb + kb_ + l_c0*8); \
            cp16(s_ + 2*MAT_B + l_row1*ROWB + l_c1*16, bLo + (size_t)l_row1*ldb + kb_ + l_c1*8); \
        }                                                                         \
    } while (0)

    const int wm = (wid >> 2) * 64;
    const int wn = (wid & 3) * 32;

    const int sel    = lane >> 3;
    const int within = lane & 7;
    const uint32_t aBase = (uint32_t)((wm + within + (sel & 1) * 8) * ROWB + (sel >> 1) * 16);
    const uint32_t bBase = (uint32_t)(MAT_B + (wn + within + (sel >> 1) * 8) * ROWB + (sel & 1) * 16);

    float acc[4][4][4];
    #pragma unroll
    for (int i = 0; i < 4; i++)
        #pragma unroll
        for (int j = 0; j < 4; j++)
            #pragma unroll
            for (int r = 0; r < 4; r++)
                acc[i][j][r] = 0.f;

    const int nk = K >> 5;

    LOAD_STAGE(0, 0); CP_COMMIT();
    if (nk > 1) LOAD_STAGE(1, 1);
    CP_COMMIT();
    CP_WAIT1();
    __syncthreads();

    for (int kt = 0; kt < nk; ++kt) {
        const uint32_t sS = sb + (kt % 3) * STAGE_B;
        #pragma unroll
        for (int ks = 0; ks < 2; ks++) {
            uint32_t aH[4][4], bH[4][2], bL[4][2];
            #pragma unroll
            for (int mt = 0; mt < 4; mt++) {
                uint32_t ad = sS + aBase + mt * (16 * ROWB) + ks * 32;
                ldsm_x4(ad, aH[mt][0], aH[mt][1], aH[mt][2], aH[mt][3]);
            }
            #pragma unroll
            for (int p = 0; p < 2; p++) {
                uint32_t bd = sS + bBase + p * (16 * ROWB) + ks * 32;
                ldsm_x4(bd, bH[2*p][0], bH[2*p][1], bH[2*p+1][0], bH[2*p+1][1]);
            }
            if (useLo) {
                #pragma unroll
                for (int p = 0; p < 2; p++) {
                    uint32_t bd = sS + bBase + p * (16 * ROWB) + ks * 32;
                    ldsm_x4(bd + MAT_B, bL[2*p][0], bL[2*p][1], bL[2*p+1][0], bL[2*p+1][1]);
                }
            }
            #pragma unroll
            for (int mt = 0; mt < 4; mt++)
                #pragma unroll
                for (int nt = 0; nt < 4; nt++) {
                    mma_f16(acc[mt][nt], aH[mt], bH[nt]);
                    if (useLo) mma_f16(acc[mt][nt], aH[mt], bL[nt]);
                }
        }
        if (kt + 2 < nk) LOAD_STAGE(kt + 2, (kt + 2) % 3);
        CP_COMMIT();
        CP_WAIT1();
        __syncthreads();
    }

    const size_t coff = (size_t)zb * cOut + (size_t)zh * cIn;
    const int gr = blockIdx.y * 128 + wm + (lane >> 2);
    const int gc = blockIdx.x * 128 + wn + (lane & 3) * 2;

    #pragma unroll
    for (int mt = 0; mt < 4; mt++) {
        #pragma unroll
        for (int nt = 0; nt < 4; nt++) {
            const int col = gc + nt * 8;
            float b0 = 0.f, b1 = 0.f;
            if (BIAS) { b0 = bias[col]; b1 = bias[col + 1]; }
            #pragma unroll
            for (int half_ = 0; half_ < 2; half_++) {
                const int row = gr + mt * 16 + half_ * 8;
                float v0 = acc[mt][nt][half_ * 2]     * alpha + b0;
                float v1 = acc[mt][nt][half_ * 2 + 1] * alpha + b1;
                if (HILO) {
                    uint32_t hi, lo;
                    split2h(v0, v1, hi, lo);
                    *(uint32_t*)(cHi + coff + (size_t)row * ldc + col) = hi;
                    if (useLo)
                        *(uint32_t*)(cLo + coff + (size_t)row * ldc + col) = lo;
                } else {
                    float2 v; v.x = v0; v.y = v1;
                    *(float2*)(cF + coff + (size_t)row * ldc + col) = v;
                }
            }
        }
    }
    #undef LOAD_STAGE
}

// ---------------------------------------------------------------------------
// Flash attention (fp16): per CTA = (head z, 128 q-rows). 8 warps x 16 rows.
// Q hi-only, K hi-only, V hi+lo. SMEM: Q (4 d-chunks) + 3-slot chunk ring.
// ---------------------------------------------------------------------------
constexpr int FKV_CH  = 2 * MAT_B;                 // 20480 (V chunks use both)
constexpr int FQ_SZ   = 4 * MAT_B;                 // 40960
constexpr int FSMEM   = FQ_SZ + 3 * FKV_CH;        // 102400
constexpr float ALPHA = 0.08838834764831845f;      // 1/sqrt(128)

__device__ __forceinline__ void flash_issue_chunk(
    int g, uint32_t sbKV, int lr0, int lp0,
    const __half* kH,
    const __half* vH, const __half* vL)
{
    const int kt = g >> 3, sub = g & 7;
    const uint32_t dst = sbKV + (g % 3) * FKV_CH;
    if (sub < 4) {
        const size_t r0 = (size_t)(kt * 128 + lr0);
        const int colb = sub * 32 + lp0 * 8;
        cp16(dst + lr0*ROWB + lp0*16,              kH + r0 * QKVW + colb);
        cp16(dst + (lr0+64)*ROWB + lp0*16,         kH + (r0+64) * QKVW + colb);
    } else {
        const int colb = kt * 128 + (sub - 4) * 32 + lp0 * 8;
        cp16(dst + lr0*ROWB + lp0*16,              vH + (size_t)lr0 * SEQ + colb);
        cp16(dst + (lr0+64)*ROWB + lp0*16,         vH + (size_t)(lr0+64) * SEQ + colb);
        cp16(dst + MAT_B + lr0*ROWB + lp0*16,      vL + (size_t)lr0 * SEQ + colb);
        cp16(dst + MAT_B + (lr0+64)*ROWB + lp0*16, vL + (size_t)(lr0+64) * SEQ + colb);
    }
}

__global__ void __launch_bounds__(256, 1)
flash_kernel(const __half* __restrict__ qkH,
             const __half* __restrict__ vtH, const __half* __restrict__ vtL,
             __half* __restrict__ oH)
{
    extern __shared__ __align__(128) char smem[];
    const uint32_t sb = smem_u32(smem);
    const int tid  = threadIdx.x;
    const int wid  = tid >> 5, lane = tid & 31;
    const int qt   = blockIdx.x;
    const int z    = blockIdx.y;
    const int b    = z >> 4, h = z & 15;

    const __half* qH = qkH + (size_t)b * SEQ * QKVW + h * 384;
    const __half* kH = qH + 128;
    const __half* vH = vtH + (size_t)z * HD * SEQ;
    const __half* vL = vtL + (size_t)z * HD * SEQ;

    const int lr0 = tid >> 2;
    const int lp0 = tid & 3;

    const int q0 = qt * 128;
    #pragma unroll
    for (int c = 0; c < 4; c++) {
        const uint32_t d0 = sb + c * MAT_B;
        const int colb = c * 32 + lp0 * 8;
        cp16(d0 + lr0*ROWB + lp0*16,      qH + (size_t)(q0+lr0) * QKVW + colb);
        cp16(d0 + (lr0+64)*ROWB + lp0*16, qH + (size_t)(q0+lr0+64) * QKVW + colb);
    }
    CP_COMMIT();
    flash_issue_chunk(0, sb + FQ_SZ, lr0, lp0, kH, vH, vL); CP_COMMIT();
    flash_issue_chunk(1, sb + FQ_SZ, lr0, lp0, kH, vH, vL); CP_COMMIT();

    const int sel    = lane >> 3;
    const int within = lane & 7;
    const uint32_t aOff  = (uint32_t)((wid * 16 + within + (sel & 1) * 8) * ROWB + (sel >> 1) * 16);
    const uint32_t bOffB = (uint32_t)((within + (sel >> 1) * 8) * ROWB + (sel & 1) * 16);

    float o[16][4];
    #pragma unroll
    for (int i = 0; i < 16; i++)
        #pragma unroll
        for (int j = 0; j < 4; j++) o[i][j] = 0.f;
    float s[16][4];
    uint32_t pfH[8][4];
    float mA = -1e30f, mB = -1e30f, lA = 0.f, lB = 0.f;

    for (int kt = 0; kt < 16; ++kt) {
        #pragma unroll
        for (int sub = 0; sub < 8; ++sub) {
            const int g = kt * 8 + sub;
            if (g + 1 < 128) { CP_WAIT1(); } else { CP_WAIT0(); }
            __syncthreads();
            if (g + 2 < 128) {
                flash_issue_chunk(g + 2, sb + FQ_SZ, lr0, lp0, kH, vH, vL);
                CP_COMMIT();
            }
            const uint32_t slotB = sb + FQ_SZ + (g % 3) * FKV_CH;

            if (sub < 4) {
                // ---- S-phase (K hi-only): d-chunk = sub ----
                if (sub == 0) {
                    #pragma unroll
                    for (int i = 0; i < 16; i++)
                        #pragma unroll
                        for (int j = 0; j < 4; j++) s[i][j] = 0.f;
                }
                const uint32_t qc = sb + sub * MAT_B;
                #pragma unroll
                for (int ks = 0; ks < 2; ks++) {
                    uint32_t aH4[4];
                    ldsm_x4(qc + aOff + ks*32, aH4[0], aH4[1], aH4[2], aH4[3]);
                    #pragma unroll
                    for (int p = 0; p < 8; p++) {
                        uint32_t bh[4];
                        ldsm_x4(slotB + bOffB + p*(16*ROWB) + ks*32,
                                bh[0], bh[1], bh[2], bh[3]);
                        mma_f16(s[2*p],   aH4, bh);
                        mma_f16(s[2*p+1], aH4, bh + 2);
                    }
                }
            } else {
                if (sub == 4) {
                    float mtA = -1e30f, mtB = -1e30f;
                    #pragma unroll
                    for (int nt = 0; nt < 16; nt++) {
                        mtA = fmaxf(mtA, fmaxf(s[nt][0], s[nt][1]));
                        mtB = fmaxf(mtB, fmaxf(s[nt][2], s[nt][3]));
                    }
                    mtA = fmaxf(mtA, __shfl_xor_sync(~0u, mtA, 1));
                    mtA = fmaxf(mtA, __shfl_xor_sync(~0u, mtA, 2));
                    mtB = fmaxf(mtB, __shfl_xor_sync(~0u, mtB, 1));
                    mtB = fmaxf(mtB, __shfl_xor_sync(~0u, mtB, 2));
                    const float mnA = fmaxf(mA, mtA);
                    const float mnB = fmaxf(mB, mtB);
                    const float fA = __expf(ALPHA * (mA - mnA));
                    const float fB = __expf(ALPHA * (mB - mnB));
                    #pragma unroll
                    for (int nt = 0; nt < 16; nt++) {
                        o[nt][0] *= fA; o[nt][1] *= fA;
                        o[nt][2] *= fB; o[nt][3] *= fB;
                    }
                    float sA = 0.f, sB = 0.f;
                    #pragma unroll
                    for (int nt = 0; nt < 16; nt++) {
                        const float p0 = __expf(ALPHA * (s[nt][0] - mnA));
                        const float p1 = __expf(ALPHA * (s[nt][1] - mnA));
                        const float p2 = __expf(ALPHA * (s[nt][2] - mnB));
                        const float p3 = __expf(ALPHA * (s[nt][3] - mnB));
                        sA += p0 + p1; sB += p2 + p3;
                        const uint32_t h01 = trunc2h(p0, p1);
                        const uint32_t h23 = trunc2h(p2, p3);
                        const int kf = nt >> 1;
                        if ((nt & 1) == 0) {
                            pfH[kf][0] = h01; pfH[kf][1] = h23;
                        } else {
                            pfH[kf][2] = h01; pfH[kf][3] = h23;
                        }
                    }
                    sA += __shfl_xor_sync(~0u, sA, 1);
                    sA += __shfl_xor_sync(~0u, sA, 2);
                    sB += __shfl_xor_sync(~0u, sB, 1);
                    sB += __shfl_xor_sync(~0u, sB, 2);
                    lA = lA * fA + sA;
                    lB = lB * fB + sB;
                    mA = mnA; mB = mnB;
                }
                #pragma unroll
                for (int ks = 0; ks < 2; ks++) {
                    const int kf = 2 * (sub - 4) + ks;
                    #pragma unroll
                    for (int p = 0; p < 8; p++) {
                        uint32_t bh[4], bl[4];
                        ldsm_x4(slotB + bOffB + p*(16*ROWB) + ks*32,
                                bh[0], bh[1], bh[2], bh[3]);
                        ldsm_x4(slotB + MAT_B + bOffB + p*(16*ROWB) + ks*32,
                                bl[0], bl[1], bl[2], bl[3]);
                        mma_f16(o[2*p],   pfH[kf], bh);
                        mma_f16(o[2*p],   pfH[kf], bl);
                        mma_f16(o[2*p+1], pfH[kf], bh + 2);
                        mma_f16(o[2*p+1], pfH[kf], bl + 2);
                    }
                }
            }
        }
    }

    const float invA = 1.f / lA;
    const float invB = 1.f / lB;
    const size_t rowA = (size_t)b * SEQ + q0 + wid * 16 + (lane >> 2);
    const size_t baseA = rowA * DMODEL + h * 128 + (lane & 3) * 2;
    const size_t baseB = baseA + (size_t)8 * DMODEL;
    #pragma unroll
    for (int nt = 0; nt < 16; nt++) {
        *(uint32_t*)(oH + baseA + nt * 8) = trunc2h(o[nt][0] * invA, o[nt][1] * invA);
        *(uint32_t*)(oH + baseB + nt * 8) = trunc2h(o[nt][2] * invB, o[nt][3] * invB);
    }
}

// ---------------------------------------------------------------------------
// fp32 -> fp16 hi/lo split (elementwise, float4)
// ---------------------------------------------------------------------------
__global__ void __launch_bounds__(256)
split_kernel(const float* __restrict__ in, __half* __restrict__ hi,
             __half* __restrict__ lo)
{
    const long i = (long)blockIdx.x * 256 + threadIdx.x;
    float4 v = ((const float4*)in)[i];
    uint32_t h0, l0, h1, l1;
    split2h(v.x, v.y, h0, l0);
    split2h(v.z, v.w, h1, l1);
    ((uint32_t*)hi)[i * 2]     = h0;
    ((uint32_t*)hi)[i * 2 + 1] = h1;
    ((uint32_t*)lo)[i * 2]     = l0;
    ((uint32_t*)lo)[i * 2 + 1] = l1;
}
__global__ void __launch_bounds__(256)
trunc_kernel(const float* __restrict__ in, __half* __restrict__ hi)
{
    const long i = (long)blockIdx.x * 256 + threadIdx.x;
    float4 v = ((const float4*)in)[i];
    ((uint32_t*)hi)[i * 2]     = trunc2h(v.x, v.y);
    ((uint32_t*)hi)[i * 2 + 1] = trunc2h(v.z, v.w);
}

// ---------------------------------------------------------------------------
// V transpose: qkv hi/lo (v slice) -> Vt hi/lo [z=bh][d][s]
// ---------------------------------------------------------------------------
__global__ void __launch_bounds__(256)
transpose_v(const __half* __restrict__ qH, const __half* __restrict__ qL,
            __half* __restrict__ vH, __half* __restrict__ vL)
{
    __shared__ __half tH[32][33], tL[32][33];
    const int z = blockIdx.z, b = z >> 4, h = z & 15;
    const int s0 = blockIdx.x * 32, d0 = blockIdx.y * 32;
    const int tx = threadIdx.x & 31, ty = threadIdx.x >> 5;
    const size_t ibase = (size_t)b * SEQ * QKVW + (size_t)h * 384 + 256;
    #pragma unroll
    for (int i = 0; i < 4; i++) {
        int s = s0 + ty + i * 8;
        tH[ty + i * 8][tx] = qH[ibase + (size_t)s * QKVW + d0 + tx];
        tL[ty + i * 8][tx] = qL[ibase + (size_t)s * QKVW + d0 + tx];
    }
    __syncthreads();
    const size_t obase = (size_t)z * HD * SEQ;
    #pragma unroll
    for (int i = 0; i < 4; i++) {
        int d = d0 + ty + i * 8;
        vH[obase + (size_t)d * SEQ + s0 + tx] = tH[tx][ty + i * 8];
        vL[obase + (size_t)d * SEQ + s0 + tx] = tL[tx][ty + i * 8];
    }
}

// ---------------------------------------------------------------------------
extern "C" void kernel_launch(void* const* d_in, const int* in_sizes, int n_in,
                              void* d_out, int out_size)
{
    const float* x     = (const float*)d_in[0];
    const float* w_qkv = (const float*)d_in[2];
    const float* b_qkv = (const float*)d_in[3];
    const float* w_o   = (const float*)d_in[4];
    const float* b_o   = (const float*)d_in[5];
    float* out = (float*)d_out;

    __half *xsH, *wqH, *wqL, *woH, *woL, *qkH, *qkL;
    __half *vtH, *vtL, *atH;
    cudaGetSymbolAddress((void**)&xsH, g_xsHi);
    cudaGetSymbolAddress((void**)&wqH, g_wqHi);  cudaGetSymbolAddress((void**)&wqL, g_wqLo);
    cudaGetSymbolAddress((void**)&woH, g_woHi);  cudaGetSymbolAddress((void**)&woL, g_woLo);
    cudaGetSymbolAddress((void**)&qkH, g_qkvHi); cudaGetSymbolAddress((void**)&qkL, g_qkvLo);
    cudaGetSymbolAddress((void**)&vtH, g_vtHi);  cudaGetSymbolAddress((void**)&vtL, g_vtLo);
    cudaGetSymbolAddress((void**)&atH, g_atHi);

    cudaFuncSetAttribute(tc_gemm<true,  true >, cudaFuncAttributeMaxDynamicSharedMemorySize, SMEM_TOTAL);
    cudaFuncSetAttribute(tc_gemm<false, true >, cudaFuncAttributeMaxDynamicSharedMemorySize, SMEM_TOTAL);
    cudaFuncSetAttribute(flash_kernel, cudaFuncAttributeMaxDynamicSharedMemorySize, FSMEM);

    // 0) split inputs (x: hi only; weights: hi+lo)
    trunc_kernel<<<(long)BATCH*SEQ*DMODEL/1024, 256>>>(x, xsH);
    split_kernel<<<(long)QKVW*DMODEL/1024,   256>>>(w_qkv, wqH, wqL);
    split_kernel<<<(long)DMODEL*DMODEL/1024, 256>>>(w_o,   woH, woL);

    // 1) QKV projection -> qkv hi (+lo on v tiles); bias fused; loMode=1
    {
        dim3 grid(QKVW / 128, (BATCH * SEQ) / 128, 1);
        tc_gemm<true, true><<<grid, 256, SMEM_TOTAL>>>(
            xsH, wqH, wqL, b_qkv, nullptr, qkH, qkL,
            DMODEL, DMODEL, DMODEL, QKVW,
            0, 0, 0, 0, 0, 0, 1, 1.0f, 1);
    }

    // 2) V transpose -> Vt hi/lo
    transpose_v<<<dim3(SEQ / 32, HD / 32, BH), 256>>>(qkH, qkL, vtH, vtL);

    // 3) fused flash attention -> attn fp16
    flash_kernel<<<dim3(SEQ / 128, BH), 256, FSMEM>>>(qkH, vtH, vtL, atH);

    // 4) output projection (bias fused) -> out fp32; loMode=0 (full hi+lo)
    {
        dim3 grid(DMODEL / 128, (BATCH * SEQ) / 128, 1);
        tc_gemm<false, true><<<grid, 256, SMEM_TOTAL>>>(
            atH, woH, woL, b_o, out, nullptr, nullptr,
            DMODEL, DMODEL, DMODEL, DMODEL,
            0, 0, 0, 0, 0, 0, 1, 1.0f, 0);
    }
}

// round 10
// speedup vs baseline: 6.3972x; 1.4489x over previous
#include <cuda_runtime.h>
#include <cuda_fp16.h>
#include <cstdint>

// Problem shape (fixed): B=2, S=2048, D=2048, H=16, DK=128
constexpr int BATCH  = 2;
constexpr int SEQ    = 2048;
constexpr int DMODEL = 2048;
constexpr int NH     = 16;
constexpr int HD     = 128;
constexpr int QKVW   = 3 * DMODEL;   // 6144
constexpr int BH     = BATCH * NH;   // 32

// ---------------------------------------------------------------------------
// Scratch (device globals — allocation-free per harness rules)
// ---------------------------------------------------------------------------
__device__ __half g_xsHi [(long)BATCH * SEQ * DMODEL];
__device__ __half g_wqHi [(long)QKVW * DMODEL];
__device__ __half g_woHi [(long)DMODEL * DMODEL];
__device__ __half g_qkvHi[(long)BATCH * SEQ * QKVW];
__device__ __half g_vtHi [(long)BH * HD * SEQ];
__device__ __half g_atHi [(long)BATCH * SEQ * DMODEL];

// ---------------------------------------------------------------------------
// helpers
// ---------------------------------------------------------------------------
__device__ __forceinline__ uint32_t smem_u32(const void* p) {
    uint32_t a;
    asm("{ .reg .u64 t; cvta.to.shared.u64 t, %1; cvt.u32.u64 %0, t; }"
        : "=r"(a) : "l"(p));
    return a;
}
__device__ __forceinline__ void cp16(uint32_t saddr, const void* g) {
    asm volatile("cp.async.cg.shared.global [%0], [%1], 16;" :: "r"(saddr), "l"(g));
}
#define CP_COMMIT() asm volatile("cp.async.commit_group;" ::: "memory")
#define CP_WAIT1()  asm volatile("cp.async.wait_group 1;" ::: "memory")
#define CP_WAIT0()  asm volatile("cp.async.wait_group 0;" ::: "memory")

__device__ __forceinline__ void ldsm_x4(uint32_t addr, uint32_t& r0, uint32_t& r1,
                                        uint32_t& r2, uint32_t& r3) {
    asm volatile("ldmatrix.sync.aligned.m8n8.x4.shared.b16 {%0,%1,%2,%3}, [%4];"
                 : "=r"(r0), "=r"(r1), "=r"(r2), "=r"(r3) : "r"(addr));
}
__device__ __forceinline__ void mma_f16(float* c, const uint32_t* a, const uint32_t* b) {
    asm volatile(
        "mma.sync.aligned.m16n8k16.row.col.f32.f16.f16.f32 "
        "{%0,%1,%2,%3}, {%4,%5,%6,%7}, {%8,%9}, {%0,%1,%2,%3};"
        : "+f"(c[0]), "+f"(c[1]), "+f"(c[2]), "+f"(c[3])
        : "r"(a[0]), "r"(a[1]), "r"(a[2]), "r"(a[3]), "r"(b[0]), "r"(b[1]));
}
__device__ __forceinline__ uint32_t pack_h2(__half a, __half b) {
    __half2 t = __halves2half2(a, b);
    return *(uint32_t*)&t;
}
__device__ __forceinline__ uint32_t trunc2h(float v0, float v1) {
    return pack_h2(__float2half_rn(v0), __float2half_rn(v1));
}

// ---------------------------------------------------------------------------
// HMMA GEMM (pure fp16): C[m,n] = sum_k Ah[m,k] * Bh[n,k]  (NT)
// CTA tile 128x128, BK=32, 3-stage cp.async (1 sync/iter), 8 warps (2x4),
// warp tile 64x32. 80B padded rows -> conflict-free ldmatrix. 2 CTAs/SM.
// ---------------------------------------------------------------------------
constexpr int ROWB    = 80;
constexpr int MAT_B   = 128 * ROWB;     // 10240
constexpr int STAGE_B = 2 * MAT_B;      // Ah, Bh = 20480
constexpr int SMEM_TOTAL = 3 * STAGE_B; // 61440 -> 2 CTAs/SM easily

template<bool F16OUT, bool BIAS>
__global__ void __launch_bounds__(256, 2)
tc_gemm(const __half* __restrict__ aHi,
        const __half* __restrict__ bHi,
        const float* __restrict__ bias,
        float* __restrict__ cF,
        __half* __restrict__ cH,
        int K, int lda, int ldb, int ldc,
        long aOut, long aIn, long bOut, long bIn, long cOut, long cIn,
        int Hdiv, float alpha)
{
    extern __shared__ __align__(128) char smem[];
    const uint32_t sb = smem_u32(smem);
    const int tid  = threadIdx.x;
    const int wid  = tid >> 5, lane = tid & 31;

    const int z  = blockIdx.z;
    const int zb = z / Hdiv, zh = z % Hdiv;
    const size_t aoff = (size_t)zb * aOut + (size_t)zh * aIn + (size_t)blockIdx.y * 128 * lda;
    const size_t boff = (size_t)zb * bOut + (size_t)zh * bIn + (size_t)blockIdx.x * 128 * ldb;
    aHi += aoff; bHi += boff;

    const int l_row0 = tid >> 2;
    const int l_c0   = tid & 3;
    const int l_row1 = (tid + 256) >> 2;
    const int l_c1   = tid & 3;

    #define LOAD_STAGE(kt, slot)                                                  \
    do {                                                                          \
        const uint32_t s_ = sb + (slot) * STAGE_B;                                \
        const int kb_ = (kt) * 32;                                                \
        cp16(s_ + l_row0*ROWB + l_c0*16,         aHi + (size_t)l_row0*lda + kb_ + l_c0*8); \
        cp16(s_ + l_row1*ROWB + l_c1*16,         aHi + (size_t)l_row1*lda + kb_ + l_c1*8); \
        cp16(s_ + MAT_B + l_row0*ROWB + l_c0*16, bHi + (size_t)l_row0*ldb + kb_ + l_c0*8); \
        cp16(s_ + MAT_B + l_row1*ROWB + l_c1*16, bHi + (size_t)l_row1*ldb + kb_ + l_c1*8); \
    } while (0)

    const int wm = (wid >> 2) * 64;
    const int wn = (wid & 3) * 32;

    const int sel    = lane >> 3;
    const int within = lane & 7;
    const uint32_t aBase = (uint32_t)((wm + within + (sel & 1) * 8) * ROWB + (sel >> 1) * 16);
    const uint32_t bBase = (uint32_t)(MAT_B + (wn + within + (sel >> 1) * 8) * ROWB + (sel & 1) * 16);

    float acc[4][4][4];
    #pragma unroll
    for (int i = 0; i < 4; i++)
        #pragma unroll
        for (int j = 0; j < 4; j++)
            #pragma unroll
            for (int r = 0; r < 4; r++)
                acc[i][j][r] = 0.f;

    const int nk = K >> 5;

    LOAD_STAGE(0, 0); CP_COMMIT();
    if (nk > 1) LOAD_STAGE(1, 1);
    CP_COMMIT();
    CP_WAIT1();
    __syncthreads();

    for (int kt = 0; kt < nk; ++kt) {
        const uint32_t sS = sb + (kt % 3) * STAGE_B;
        #pragma unroll
        for (int ks = 0; ks < 2; ks++) {
            uint32_t aH[4][4], bH[4][2];
            #pragma unroll
            for (int mt = 0; mt < 4; mt++) {
                uint32_t ad = sS + aBase + mt * (16 * ROWB) + ks * 32;
                ldsm_x4(ad, aH[mt][0], aH[mt][1], aH[mt][2], aH[mt][3]);
            }
            #pragma unroll
            for (int p = 0; p < 2; p++) {
                uint32_t bd = sS + bBase + p * (16 * ROWB) + ks * 32;
                ldsm_x4(bd, bH[2*p][0], bH[2*p][1], bH[2*p+1][0], bH[2*p+1][1]);
            }
            #pragma unroll
            for (int mt = 0; mt < 4; mt++)
                #pragma unroll
                for (int nt = 0; nt < 4; nt++)
                    mma_f16(acc[mt][nt], aH[mt], bH[nt]);
        }
        if (kt + 2 < nk) LOAD_STAGE(kt + 2, (kt + 2) % 3);
        CP_COMMIT();
        CP_WAIT1();
        __syncthreads();
    }

    const size_t coff = (size_t)zb * cOut + (size_t)zh * cIn;
    const int gr = blockIdx.y * 128 + wm + (lane >> 2);
    const int gc = blockIdx.x * 128 + wn + (lane & 3) * 2;

    #pragma unroll
    for (int mt = 0; mt < 4; mt++) {
        #pragma unroll
        for (int nt = 0; nt < 4; nt++) {
            const int col = gc + nt * 8;
            float b0 = 0.f, b1 = 0.f;
            if (BIAS) { b0 = bias[col]; b1 = bias[col + 1]; }
            #pragma unroll
            for (int half_ = 0; half_ < 2; half_++) {
                const int row = gr + mt * 16 + half_ * 8;
                float v0 = acc[mt][nt][half_ * 2]     * alpha + b0;
                float v1 = acc[mt][nt][half_ * 2 + 1] * alpha + b1;
                if (F16OUT) {
                    *(uint32_t*)(cH + coff + (size_t)row * ldc + col) = trunc2h(v0, v1);
                } else {
                    float2 v; v.x = v0; v.y = v1;
                    *(float2*)(cF + coff + (size_t)row * ldc + col) = v;
                }
            }
        }
    }
    #undef LOAD_STAGE
}

// ---------------------------------------------------------------------------
// Flash attention (pure fp16): per CTA = (head z, 128 q-rows). 8 warps x 16 rows.
// SMEM: Q (4 d-chunks) + 3-slot single-tile K/V chunk ring.
// ---------------------------------------------------------------------------
constexpr int FKV_CH  = MAT_B;                     // 10240: one K or V tile
constexpr int FQ_SZ   = 4 * MAT_B;                 // 40960
constexpr int FSMEM   = FQ_SZ + 3 * FKV_CH;        // 71680
constexpr float ALPHA = 0.08838834764831845f;      // 1/sqrt(128)

__device__ __forceinline__ void flash_issue_chunk(
    int g, uint32_t sbKV, int lr0, int lp0,
    const __half* kH, const __half* vH)
{
    const int kt = g >> 3, sub = g & 7;
    const uint32_t dst = sbKV + (g % 3) * FKV_CH;
    if (sub < 4) {
        const size_t r0 = (size_t)(kt * 128 + lr0);
        const int colb = sub * 32 + lp0 * 8;
        cp16(dst + lr0*ROWB + lp0*16,      kH + r0 * QKVW + colb);
        cp16(dst + (lr0+64)*ROWB + lp0*16, kH + (r0+64) * QKVW + colb);
    } else {
        const int colb = kt * 128 + (sub - 4) * 32 + lp0 * 8;
        cp16(dst + lr0*ROWB + lp0*16,      vH + (size_t)lr0 * SEQ + colb);
        cp16(dst + (lr0+64)*ROWB + lp0*16, vH + (size_t)(lr0+64) * SEQ + colb);
    }
}

__global__ void __launch_bounds__(256, 1)
flash_kernel(const __half* __restrict__ qkH,
             const __half* __restrict__ vtH,
             __half* __restrict__ oH)
{
    extern __shared__ __align__(128) char smem[];
    const uint32_t sb = smem_u32(smem);
    const int tid  = threadIdx.x;
    const int wid  = tid >> 5, lane = tid & 31;
    const int qt   = blockIdx.x;
    const int z    = blockIdx.y;
    const int b    = z >> 4, h = z & 15;

    const __half* qH = qkH + (size_t)b * SEQ * QKVW + h * 384;
    const __half* kH = qH + 128;
    const __half* vH = vtH + (size_t)z * HD * SEQ;

    const int lr0 = tid >> 2;
    const int lp0 = tid & 3;

    const int q0 = qt * 128;
    #pragma unroll
    for (int c = 0; c < 4; c++) {
        const uint32_t d0 = sb + c * MAT_B;
        const int colb = c * 32 + lp0 * 8;
        cp16(d0 + lr0*ROWB + lp0*16,      qH + (size_t)(q0+lr0) * QKVW + colb);
        cp16(d0 + (lr0+64)*ROWB + lp0*16, qH + (size_t)(q0+lr0+64) * QKVW + colb);
    }
    CP_COMMIT();
    flash_issue_chunk(0, sb + FQ_SZ, lr0, lp0, kH, vH); CP_COMMIT();
    flash_issue_chunk(1, sb + FQ_SZ, lr0, lp0, kH, vH); CP_COMMIT();

    const int sel    = lane >> 3;
    const int within = lane & 7;
    const uint32_t aOff  = (uint32_t)((wid * 16 + within + (sel & 1) * 8) * ROWB + (sel >> 1) * 16);
    const uint32_t bOffB = (uint32_t)((within + (sel >> 1) * 8) * ROWB + (sel & 1) * 16);

    float o[16][4];
    #pragma unroll
    for (int i = 0; i < 16; i++)
        #pragma unroll
        for (int j = 0; j < 4; j++) o[i][j] = 0.f;
    float s[16][4];
    uint32_t pfH[8][4];
    float mA = -1e30f, mB = -1e30f, lA = 0.f, lB = 0.f;

    for (int kt = 0; kt < 16; ++kt) {
        #pragma unroll
        for (int sub = 0; sub < 8; ++sub) {
            const int g = kt * 8 + sub;
            if (g + 1 < 128) { CP_WAIT1(); } else { CP_WAIT0(); }
            __syncthreads();
            if (g + 2 < 128) {
                flash_issue_chunk(g + 2, sb + FQ_SZ, lr0, lp0, kH, vH);
                CP_COMMIT();
            }
            const uint32_t slotB = sb + FQ_SZ + (g % 3) * FKV_CH;

            if (sub < 4) {
                // ---- S-phase: d-chunk = sub ----
                if (sub == 0) {
                    #pragma unroll
                    for (int i = 0; i < 16; i++)
                        #pragma unroll
                        for (int j = 0; j < 4; j++) s[i][j] = 0.f;
                }
                const uint32_t qc = sb + sub * MAT_B;
                #pragma unroll
                for (int ks = 0; ks < 2; ks++) {
                    uint32_t aH4[4];
                    ldsm_x4(qc + aOff + ks*32, aH4[0], aH4[1], aH4[2], aH4[3]);
                    #pragma unroll
                    for (int p = 0; p < 8; p++) {
                        uint32_t bh[4];
                        ldsm_x4(slotB + bOffB + p*(16*ROWB) + ks*32,
                                bh[0], bh[1], bh[2], bh[3]);
                        mma_f16(s[2*p],   aH4, bh);
                        mma_f16(s[2*p+1], aH4, bh + 2);
                    }
                }
            } else {
                if (sub == 4) {
                    // ---- online softmax over this key tile ----
                    float mtA = -1e30f, mtB = -1e30f;
                    #pragma unroll
                    for (int nt = 0; nt < 16; nt++) {
                        mtA = fmaxf(mtA, fmaxf(s[nt][0], s[nt][1]));
                        mtB = fmaxf(mtB, fmaxf(s[nt][2], s[nt][3]));
                    }
                    mtA = fmaxf(mtA, __shfl_xor_sync(~0u, mtA, 1));
                    mtA = fmaxf(mtA, __shfl_xor_sync(~0u, mtA, 2));
                    mtB = fmaxf(mtB, __shfl_xor_sync(~0u, mtB, 1));
                    mtB = fmaxf(mtB, __shfl_xor_sync(~0u, mtB, 2));
                    const float mnA = fmaxf(mA, mtA);
                    const float mnB = fmaxf(mB, mtB);
                    const float fA = __expf(ALPHA * (mA - mnA));
                    const float fB = __expf(ALPHA * (mB - mnB));
                    #pragma unroll
                    for (int nt = 0; nt < 16; nt++) {
                        o[nt][0] *= fA; o[nt][1] *= fA;
                        o[nt][2] *= fB; o[nt][3] *= fB;
                    }
                    float sA = 0.f, sB = 0.f;
                    #pragma unroll
                    for (int nt = 0; nt < 16; nt++) {
                        const float p0 = __expf(ALPHA * (s[nt][0] - mnA));
                        const float p1 = __expf(ALPHA * (s[nt][1] - mnA));
                        const float p2 = __expf(ALPHA * (s[nt][2] - mnB));
                        const float p3 = __expf(ALPHA * (s[nt][3] - mnB));
                        sA += p0 + p1; sB += p2 + p3;
                        const uint32_t h01 = trunc2h(p0, p1);
                        const uint32_t h23 = trunc2h(p2, p3);
                        const int kf = nt >> 1;
                        if ((nt & 1) == 0) {
                            pfH[kf][0] = h01; pfH[kf][1] = h23;
                        } else {
                            pfH[kf][2] = h01; pfH[kf][3] = h23;
                        }
                    }
                    sA += __shfl_xor_sync(~0u, sA, 1);
                    sA += __shfl_xor_sync(~0u, sA, 2);
                    sB += __shfl_xor_sync(~0u, sB, 1);
                    sB += __shfl_xor_sync(~0u, sB, 2);
                    lA = lA * fA + sA;
                    lB = lB * fB + sB;
                    mA = mnA; mB = mnB;
                }
                // ---- PV-phase: key-chunk c = sub-4, kf = 2c+ks ----
                #pragma unroll
                for (int ks = 0; ks < 2; ks++) {
                    const int kf = 2 * (sub - 4) + ks;
                    #pragma unroll
                    for (int p = 0; p < 8; p++) {
                        uint32_t bh[4];
                        ldsm_x4(slotB + bOffB + p*(16*ROWB) + ks*32,
                                bh[0], bh[1], bh[2], bh[3]);
                        mma_f16(o[2*p],   pfH[kf], bh);
                        mma_f16(o[2*p+1], pfH[kf], bh + 2);
                    }
                }
            }
        }
    }

    const float invA = 1.f / lA;
    const float invB = 1.f / lB;
    const size_t rowA = (size_t)b * SEQ + q0 + wid * 16 + (lane >> 2);
    const size_t baseA = rowA * DMODEL + h * 128 + (lane & 3) * 2;
    const size_t baseB = baseA + (size_t)8 * DMODEL;
    #pragma unroll
    for (int nt = 0; nt < 16; nt++) {
        *(uint32_t*)(oH + baseA + nt * 8) = trunc2h(o[nt][0] * invA, o[nt][1] * invA);
        *(uint32_t*)(oH + baseB + nt * 8) = trunc2h(o[nt][2] * invB, o[nt][3] * invB);
    }
}

// ---------------------------------------------------------------------------
// fp32 -> fp16 truncate (elementwise, float4)
// ---------------------------------------------------------------------------
__global__ void __launch_bounds__(256)
trunc_kernel(const float* __restrict__ in, __half* __restrict__ hi)
{
    const long i = (long)blockIdx.x * 256 + threadIdx.x;
    float4 v = ((const float4*)in)[i];
    ((uint32_t*)hi)[i * 2]     = trunc2h(v.x, v.y);
    ((uint32_t*)hi)[i * 2 + 1] = trunc2h(v.z, v.w);
}

// ---------------------------------------------------------------------------
// V transpose: qkv (v slice) -> Vt [z=bh][d][s]
// ---------------------------------------------------------------------------
__global__ void __launch_bounds__(256)
transpose_v(const __half* __restrict__ qH, __half* __restrict__ vH)
{
    __shared__ __half tH[32][33];
    const int z = blockIdx.z, b = z >> 4, h = z & 15;
    const int s0 = blockIdx.x * 32, d0 = blockIdx.y * 32;
    const int tx = threadIdx.x & 31, ty = threadIdx.x >> 5;
    const size_t ibase = (size_t)b * SEQ * QKVW + (size_t)h * 384 + 256;
    #pragma unroll
    for (int i = 0; i < 4; i++) {
        int s = s0 + ty + i * 8;
        tH[ty + i * 8][tx] = qH[ibase + (size_t)s * QKVW + d0 + tx];
    }
    __syncthreads();
    const size_t obase = (size_t)z * HD * SEQ;
    #pragma unroll
    for (int i = 0; i < 4; i++) {
        int d = d0 + ty + i * 8;
        vH[obase + (size_t)d * SEQ + s0 + tx] = tH[tx][ty + i * 8];
    }
}

// ---------------------------------------------------------------------------
extern "C" void kernel_launch(void* const* d_in, const int* in_sizes, int n_in,
                              void* d_out, int out_size)
{
    const float* x     = (const float*)d_in[0];
    const float* w_qkv = (const float*)d_in[2];
    const float* b_qkv = (const float*)d_in[3];
    const float* w_o   = (const float*)d_in[4];
    const float* b_o   = (const float*)d_in[5];
    float* out = (float*)d_out;

    __half *xsH, *wqH, *woH, *qkH, *vtH, *atH;
    cudaGetSymbolAddress((void**)&xsH, g_xsHi);
    cudaGetSymbolAddress((void**)&wqH, g_wqHi);
    cudaGetSymbolAddress((void**)&woH, g_woHi);
    cudaGetSymbolAddress((void**)&qkH, g_qkvHi);
    cudaGetSymbolAddress((void**)&vtH, g_vtHi);
    cudaGetSymbolAddress((void**)&atH, g_atHi);

    cudaFuncSetAttribute(tc_gemm<true,  true >, cudaFuncAttributeMaxDynamicSharedMemorySize, SMEM_TOTAL);
    cudaFuncSetAttribute(tc_gemm<false, true >, cudaFuncAttributeMaxDynamicSharedMemorySize, SMEM_TOTAL);
    cudaFuncSetAttribute(flash_kernel, cudaFuncAttributeMaxDynamicSharedMemorySize, FSMEM);

    // 0) truncate inputs to fp16
    trunc_kernel<<<(long)BATCH*SEQ*DMODEL/1024, 256>>>(x,     xsH);
    trunc_kernel<<<(long)QKVW*DMODEL/1024,      256>>>(w_qkv, wqH);
    trunc_kernel<<<(long)DMODEL*DMODEL/1024,    256>>>(w_o,   woH);

    // 1) QKV projection -> qkv fp16 (bias fused)
    {
        dim3 grid(QKVW / 128, (BATCH * SEQ) / 128, 1);
        tc_gemm<true, true><<<grid, 256, SMEM_TOTAL>>>(
            xsH, wqH, b_qkv, nullptr, qkH,
            DMODEL, DMODEL, DMODEL, QKVW,
            0, 0, 0, 0, 0, 0, 1, 1.0f);
    }

    // 2) V transpose -> Vt fp16
    transpose_v<<<dim3(SEQ / 32, HD / 32, BH), 256>>>(qkH, vtH);

    // 3) fused flash attention -> attn fp16
    flash_kernel<<<dim3(SEQ / 128, BH), 256, FSMEM>>>(qkH, vtH, atH);

    // 4) output projection (bias fused) -> out fp32
    {
        dim3 grid(DMODEL / 128, (BATCH * SEQ) / 128, 1);
        tc_gemm<false, true><<<grid, 256, SMEM_TOTAL>>>(
            atH, woH, b_o, out, nullptr,
            DMODEL, DMODEL, DMODEL, DMODEL,
            0, 0, 0, 0, 0, 0, 1, 1.0f);
    }
}

// round 11
// speedup vs baseline: 7.0361x; 1.0999x over previous
#include <cuda_runtime.h>
#include <cuda_fp16.h>
#include <cstdint>

// Problem shape (fixed): B=2, S=2048, D=2048, H=16, DK=128
constexpr int BATCH  = 2;
constexpr int SEQ    = 2048;
constexpr int DMODEL = 2048;
constexpr int NH     = 16;
constexpr int HD     = 128;
constexpr int QKVW   = 3 * DMODEL;   // 6144
constexpr int BH     = BATCH * NH;   // 32

// ---------------------------------------------------------------------------
// Scratch (device globals — allocation-free per harness rules)
// ---------------------------------------------------------------------------
__device__ __half g_xsHi [(long)BATCH * SEQ * DMODEL];
__device__ __half g_wqHi [(long)QKVW * DMODEL];
__device__ __half g_woHi [(long)DMODEL * DMODEL];
__device__ __half g_qkvHi[(long)BATCH * SEQ * QKVW];
__device__ __half g_vtHi [(long)BH * HD * SEQ];
__device__ __half g_atHi [(long)BATCH * SEQ * DMODEL];

// ---------------------------------------------------------------------------
// helpers
// ---------------------------------------------------------------------------
__device__ __forceinline__ uint32_t smem_u32(const void* p) {
    uint32_t a;
    asm("{ .reg .u64 t; cvta.to.shared.u64 t, %1; cvt.u32.u64 %0, t; }"
        : "=r"(a) : "l"(p));
    return a;
}
__device__ __forceinline__ void cp16(uint32_t saddr, const void* g) {
    asm volatile("cp.async.cg.shared.global [%0], [%1], 16;" :: "r"(saddr), "l"(g));
}
#define CP_COMMIT() asm volatile("cp.async.commit_group;" ::: "memory")
#define CP_WAIT1()  asm volatile("cp.async.wait_group 1;" ::: "memory")
#define CP_WAIT0()  asm volatile("cp.async.wait_group 0;" ::: "memory")

__device__ __forceinline__ void ldsm_x4(uint32_t addr, uint32_t& r0, uint32_t& r1,
                                        uint32_t& r2, uint32_t& r3) {
    asm volatile("ldmatrix.sync.aligned.m8n8.x4.shared.b16 {%0,%1,%2,%3}, [%4];"
                 : "=r"(r0), "=r"(r1), "=r"(r2), "=r"(r3) : "r"(addr));
}
__device__ __forceinline__ void mma_f16(float* c, const uint32_t* a, const uint32_t* b) {
    asm volatile(
        "mma.sync.aligned.m16n8k16.row.col.f32.f16.f16.f32 "
        "{%0,%1,%2,%3}, {%4,%5,%6,%7}, {%8,%9}, {%0,%1,%2,%3};"
        : "+f"(c[0]), "+f"(c[1]), "+f"(c[2]), "+f"(c[3])
        : "r"(a[0]), "r"(a[1]), "r"(a[2]), "r"(a[3]), "r"(b[0]), "r"(b[1]));
}
__device__ __forceinline__ uint32_t pack_h2(__half a, __half b) {
    __half2 t = __halves2half2(a, b);
    return *(uint32_t*)&t;
}
__device__ __forceinline__ uint32_t trunc2h(float v0, float v1) {
    return pack_h2(__float2half_rn(v0), __float2half_rn(v1));
}

// ---------------------------------------------------------------------------
// HMMA GEMM (pure fp16): C[m,n] = sum_k Ah[m,k] * Bh[n,k]  (NT)
// CTA tile 128x128, BK=64, 3-stage cp.async (1 sync/iter), 8 warps (2x4),
// warp tile 64x32. 144B padded rows (conflict-free: 144 mod 128 = 16).
// 2 CTAs/SM (2x110592 = 221184 <= 228K).
// ---------------------------------------------------------------------------
constexpr int ROWB_G  = 144;              // 64 fp16 = 128B data + 16B pad
constexpr int MAT_G   = 128 * ROWB_G;     // 18432
constexpr int STAGE_G = 2 * MAT_G;        // Ah, Bh = 36864
constexpr int SMEM_G  = 3 * STAGE_G;      // 110592

template<bool F16OUT, bool BIAS>
__global__ void __launch_bounds__(256, 2)
tc_gemm(const __half* __restrict__ aHi,
        const __half* __restrict__ bHi,
        const float* __restrict__ bias,
        float* __restrict__ cF,
        __half* __restrict__ cH,
        int K, int lda, int ldb, int ldc,
        long aOut, long aIn, long bOut, long bIn, long cOut, long cIn,
        int Hdiv, float alpha)
{
    extern __shared__ __align__(128) char smem[];
    const uint32_t sb = smem_u32(smem);
    const int tid  = threadIdx.x;
    const int wid  = tid >> 5, lane = tid & 31;

    const int z  = blockIdx.z;
    const int zb = z / Hdiv, zh = z % Hdiv;
    const size_t aoff = (size_t)zb * aOut + (size_t)zh * aIn + (size_t)blockIdx.y * 128 * lda;
    const size_t boff = (size_t)zb * bOut + (size_t)zh * bIn + (size_t)blockIdx.x * 128 * ldb;
    aHi += aoff; bHi += boff;

    const int l_piece = tid & 7;        // 16B piece within 128B row
    const int l_rbase = tid >> 3;       // row base; +32 per rep

    #define LOAD_STAGE(kt, slot)                                                  \
    do {                                                                          \
        const uint32_t s_ = sb + (slot) * STAGE_G;                                \
        const int kb_ = (kt) * 64;                                                \
        _Pragma("unroll")                                                         \
        for (int i_ = 0; i_ < 4; i_++) {                                          \
            const int row_ = l_rbase + i_ * 32;                                   \
            cp16(s_ + row_*ROWB_G + l_piece*16,                                   \
                 aHi + (size_t)row_*lda + kb_ + l_piece*8);                       \
            cp16(s_ + MAT_G + row_*ROWB_G + l_piece*16,                           \
                 bHi + (size_t)row_*ldb + kb_ + l_piece*8);                       \
        }                                                                         \
    } while (0)

    const int wm = (wid >> 2) * 64;
    const int wn = (wid & 3) * 32;

    const int sel    = lane >> 3;
    const int within = lane & 7;
    const uint32_t aBase = (uint32_t)((wm + within + (sel & 1) * 8) * ROWB_G + (sel >> 1) * 16);
    const uint32_t bBase = (uint32_t)(MAT_G + (wn + within + (sel >> 1) * 8) * ROWB_G + (sel & 1) * 16);

    float acc[4][4][4];
    #pragma unroll
    for (int i = 0; i < 4; i++)
        #pragma unroll
        for (int j = 0; j < 4; j++)
            #pragma unroll
            for (int r = 0; r < 4; r++)
                acc[i][j][r] = 0.f;

    const int nk = K >> 6;

    LOAD_STAGE(0, 0); CP_COMMIT();
    if (nk > 1) LOAD_STAGE(1, 1);
    CP_COMMIT();
    CP_WAIT1();
    __syncthreads();

    for (int kt = 0; kt < nk; ++kt) {
        const uint32_t sS = sb + (kt % 3) * STAGE_G;
        #pragma unroll
        for (int ks = 0; ks < 4; ks++) {
            uint32_t aH[4][4], bH[4][2];
            #pragma unroll
            for (int mt = 0; mt < 4; mt++) {
                uint32_t ad = sS + aBase + mt * (16 * ROWB_G) + ks * 32;
                ldsm_x4(ad, aH[mt][0], aH[mt][1], aH[mt][2], aH[mt][3]);
            }
            #pragma unroll
            for (int p = 0; p < 2; p++) {
                uint32_t bd = sS + bBase + p * (16 * ROWB_G) + ks * 32;
                ldsm_x4(bd, bH[2*p][0], bH[2*p][1], bH[2*p+1][0], bH[2*p+1][1]);
            }
            #pragma unroll
            for (int mt = 0; mt < 4; mt++)
                #pragma unroll
                for (int nt = 0; nt < 4; nt++)
                    mma_f16(acc[mt][nt], aH[mt], bH[nt]);
        }
        if (kt + 2 < nk) LOAD_STAGE(kt + 2, (kt + 2) % 3);
        CP_COMMIT();
        CP_WAIT1();
        __syncthreads();
    }

    const size_t coff = (size_t)zb * cOut + (size_t)zh * cIn;
    const int gr = blockIdx.y * 128 + wm + (lane >> 2);
    const int gc = blockIdx.x * 128 + wn + (lane & 3) * 2;

    #pragma unroll
    for (int mt = 0; mt < 4; mt++) {
        #pragma unroll
        for (int nt = 0; nt < 4; nt++) {
            const int col = gc + nt * 8;
            float b0 = 0.f, b1 = 0.f;
            if (BIAS) { b0 = bias[col]; b1 = bias[col + 1]; }
            #pragma unroll
            for (int half_ = 0; half_ < 2; half_++) {
                const int row = gr + mt * 16 + half_ * 8;
                float v0 = acc[mt][nt][half_ * 2]     * alpha + b0;
                float v1 = acc[mt][nt][half_ * 2 + 1] * alpha + b1;
                if (F16OUT) {
                    *(uint32_t*)(cH + coff + (size_t)row * ldc + col) = trunc2h(v0, v1);
                } else {
                    float2 v; v.x = v0; v.y = v1;
                    *(float2*)(cF + coff + (size_t)row * ldc + col) = v;
                }
            }
        }
    }
    #undef LOAD_STAGE
}

// ---------------------------------------------------------------------------
// Flash attention (pure fp16): per CTA = (head z, 128 q-rows). 8 warps x 16 rows.
// SMEM: Q (4 d-chunks, 80B rows) + 3-slot PAIR ring (each pair = 2 chunks).
// Barrier per 64-wide pair instead of per 32-wide chunk.
// ---------------------------------------------------------------------------
constexpr int ROWB    = 80;
constexpr int MAT_B   = 128 * ROWB;                // 10240: one 128x32 chunk
constexpr int PAIR_B  = 2 * MAT_B;                 // 20480
constexpr int FQ_SZ   = 4 * MAT_B;                 // 40960
constexpr int FSMEM   = FQ_SZ + 3 * PAIR_B;        // 102400
constexpr float ALPHA = 0.08838834764831845f;      // 1/sqrt(128)

// pair g: kt = g>>2, pr = g&3.  pr 0-1: K halves (d 0-63 / 64-127).
//                               pr 2-3: V key-chunk halves.
__device__ __forceinline__ void flash_issue_pair(
    int g, uint32_t sbKV, int lr0, int lp0,
    const __half* kH, const __half* vH)
{
    const int kt = g >> 2, pr = g & 3;
    const uint32_t dst = sbKV + (g % 3) * PAIR_B;
    if (pr < 2) {
        const size_t r0 = (size_t)(kt * 128 + lr0);
        #pragma unroll
        for (int half = 0; half < 2; half++) {
            const int colb = (2 * pr + half) * 32 + lp0 * 8;
            const uint32_t d0 = dst + half * MAT_B;
            cp16(d0 + lr0*ROWB + lp0*16,      kH + r0 * QKVW + colb);
            cp16(d0 + (lr0+64)*ROWB + lp0*16, kH + (r0+64) * QKVW + colb);
        }
    } else {
        #pragma unroll
        for (int half = 0; half < 2; half++) {
            const int colb = kt * 128 + (2 * (pr - 2) + half) * 32 + lp0 * 8;
            const uint32_t d0 = dst + half * MAT_B;
            cp16(d0 + lr0*ROWB + lp0*16,      vH + (size_t)lr0 * SEQ + colb);
            cp16(d0 + (lr0+64)*ROWB + lp0*16, vH + (size_t)(lr0+64) * SEQ + colb);
        }
    }
}

__global__ void __launch_bounds__(256, 1)
flash_kernel(const __half* __restrict__ qkH,
             const __half* __restrict__ vtH,
             __half* __restrict__ oH)
{
    extern __shared__ __align__(128) char smem[];
    const uint32_t sb = smem_u32(smem);
    const int tid  = threadIdx.x;
    const int wid  = tid >> 5, lane = tid & 31;
    const int qt   = blockIdx.x;
    const int z    = blockIdx.y;
    const int b    = z >> 4, h = z & 15;

    const __half* qH = qkH + (size_t)b * SEQ * QKVW + h * 384;
    const __half* kH = qH + 128;
    const __half* vH = vtH + (size_t)z * HD * SEQ;

    const int lr0 = tid >> 2;
    const int lp0 = tid & 3;

    const int q0 = qt * 128;
    #pragma unroll
    for (int c = 0; c < 4; c++) {
        const uint32_t d0 = sb + c * MAT_B;
        const int colb = c * 32 + lp0 * 8;
        cp16(d0 + lr0*ROWB + lp0*16,      qH + (size_t)(q0+lr0) * QKVW + colb);
        cp16(d0 + (lr0+64)*ROWB + lp0*16, qH + (size_t)(q0+lr0+64) * QKVW + colb);
    }
    CP_COMMIT();
    flash_issue_pair(0, sb + FQ_SZ, lr0, lp0, kH, vH); CP_COMMIT();
    flash_issue_pair(1, sb + FQ_SZ, lr0, lp0, kH, vH); CP_COMMIT();

    const int sel    = lane >> 3;
    const int within = lane & 7;
    const uint32_t aOff  = (uint32_t)((wid * 16 + within + (sel & 1) * 8) * ROWB + (sel >> 1) * 16);
    const uint32_t bOffB = (uint32_t)((within + (sel >> 1) * 8) * ROWB + (sel & 1) * 16);

    float o[16][4];
    #pragma unroll
    for (int i = 0; i < 16; i++)
        #pragma unroll
        for (int j = 0; j < 4; j++) o[i][j] = 0.f;
    float s[16][4];
    uint32_t pfH[8][4];
    float mA = -1e30f, mB = -1e30f, lA = 0.f, lB = 0.f;

    for (int kt = 0; kt < 16; ++kt) {
        #pragma unroll
        for (int pr = 0; pr < 4; ++pr) {
            const int g = kt * 4 + pr;
            if (g + 1 < 64) { CP_WAIT1(); } else { CP_WAIT0(); }
            __syncthreads();
            if (g + 2 < 64) {
                flash_issue_pair(g + 2, sb + FQ_SZ, lr0, lp0, kH, vH);
                CP_COMMIT();
            }
            const uint32_t slotB = sb + FQ_SZ + (g % 3) * PAIR_B;

            if (pr < 2) {
                // ---- S-phase: d-chunks 2*pr, 2*pr+1 ----
                if (pr == 0) {
                    #pragma unroll
                    for (int i = 0; i < 16; i++)
                        #pragma unroll
                        for (int j = 0; j < 4; j++) s[i][j] = 0.f;
                }
                #pragma unroll
                for (int half = 0; half < 2; half++) {
                    const uint32_t qc  = sb + (2 * pr + half) * MAT_B;
                    const uint32_t kvc = slotB + half * MAT_B;
                    #pragma unroll
                    for (int ks = 0; ks < 2; ks++) {
                        uint32_t aH4[4];
                        ldsm_x4(qc + aOff + ks*32, aH4[0], aH4[1], aH4[2], aH4[3]);
                        #pragma unroll
                        for (int p = 0; p < 8; p++) {
                            uint32_t bh[4];
                            ldsm_x4(kvc + bOffB + p*(16*ROWB) + ks*32,
                                    bh[0], bh[1], bh[2], bh[3]);
                            mma_f16(s[2*p],   aH4, bh);
                            mma_f16(s[2*p+1], aH4, bh + 2);
                        }
                    }
                }
            } else {
                if (pr == 2) {
                    // ---- online softmax over this key tile ----
                    float mtA = -1e30f, mtB = -1e30f;
                    #pragma unroll
                    for (int nt = 0; nt < 16; nt++) {
                        mtA = fmaxf(mtA, fmaxf(s[nt][0], s[nt][1]));
                        mtB = fmaxf(mtB, fmaxf(s[nt][2], s[nt][3]));
                    }
                    mtA = fmaxf(mtA, __shfl_xor_sync(~0u, mtA, 1));
                    mtA = fmaxf(mtA, __shfl_xor_sync(~0u, mtA, 2));
                    mtB = fmaxf(mtB, __shfl_xor_sync(~0u, mtB, 1));
                    mtB = fmaxf(mtB, __shfl_xor_sync(~0u, mtB, 2));
                    const float mnA = fmaxf(mA, mtA);
                    const float mnB = fmaxf(mB, mtB);
                    const float fA = __expf(ALPHA * (mA - mnA));
                    const float fB = __expf(ALPHA * (mB - mnB));
                    #pragma unroll
                    for (int nt = 0; nt < 16; nt++) {
                        o[nt][0] *= fA; o[nt][1] *= fA;
                        o[nt][2] *= fB; o[nt][3] *= fB;
                    }
                    float sA = 0.f, sB = 0.f;
                    #pragma unroll
                    for (int nt = 0; nt < 16; nt++) {
                        const float p0 = __expf(ALPHA * (s[nt][0] - mnA));
                        const float p1 = __expf(ALPHA * (s[nt][1] - mnA));
                        const float p2 = __expf(ALPHA * (s[nt][2] - mnB));
                        const float p3 = __expf(ALPHA * (s[nt][3] - mnB));
                        sA += p0 + p1; sB += p2 + p3;
                        const uint32_t h01 = trunc2h(p0, p1);
                        const uint32_t h23 = trunc2h(p2, p3);
                        const int kf = nt >> 1;
                        if ((nt & 1) == 0) {
                            pfH[kf][0] = h01; pfH[kf][1] = h23;
                        } else {
                            pfH[kf][2] = h01; pfH[kf][3] = h23;
                        }
                    }
                    sA += __shfl_xor_sync(~0u, sA, 1);
                    sA += __shfl_xor_sync(~0u, sA, 2);
                    sB += __shfl_xor_sync(~0u, sB, 1);
                    sB += __shfl_xor_sync(~0u, sB, 2);
                    lA = lA * fA + sA;
                    lB = lB * fB + sB;
                    mA = mnA; mB = mnB;
                }
                // ---- PV-phase: V key-chunks 2*(pr-2), 2*(pr-2)+1 ----
                #pragma unroll
                for (int half = 0; half < 2; half++) {
                    const int c = 2 * (pr - 2) + half;
                    const uint32_t kvc = slotB + half * MAT_B;
                    #pragma unroll
                    for (int ks = 0; ks < 2; ks++) {
                        const int kf = 2 * c + ks;
                        #pragma unroll
                        for (int p = 0; p < 8; p++) {
                            uint32_t bh[4];
                            ldsm_x4(kvc + bOffB + p*(16*ROWB) + ks*32,
                                    bh[0], bh[1], bh[2], bh[3]);
                            mma_f16(o[2*p],   pfH[kf], bh);
                            mma_f16(o[2*p+1], pfH[kf], bh + 2);
                        }
                    }
                }
            }
        }
    }

    const float invA = 1.f / lA;
    const float invB = 1.f / lB;
    const size_t rowA = (size_t)b * SEQ + q0 + wid * 16 + (lane >> 2);
    const size_t baseA = rowA * DMODEL + h * 128 + (lane & 3) * 2;
    const size_t baseB = baseA + (size_t)8 * DMODEL;
    #pragma unroll
    for (int nt = 0; nt < 16; nt++) {
        *(uint32_t*)(oH + baseA + nt * 8) = trunc2h(o[nt][0] * invA, o[nt][1] * invA);
        *(uint32_t*)(oH + baseB + nt * 8) = trunc2h(o[nt][2] * invB, o[nt][3] * invB);
    }
}

// ---------------------------------------------------------------------------
// fp32 -> fp16 truncate (elementwise, float4)
// ---------------------------------------------------------------------------
__global__ void __launch_bounds__(256)
trunc_kernel(const float* __restrict__ in, __half* __restrict__ hi)
{
    const long i = (long)blockIdx.x * 256 + threadIdx.x;
    float4 v = ((const float4*)in)[i];
    ((uint32_t*)hi)[i * 2]     = trunc2h(v.x, v.y);
    ((uint32_t*)hi)[i * 2 + 1] = trunc2h(v.z, v.w);
}

// ---------------------------------------------------------------------------
// V transpose: qkv (v slice) -> Vt [z=bh][d][s]
// ---------------------------------------------------------------------------
__global__ void __launch_bounds__(256)
transpose_v(const __half* __restrict__ qH, __half* __restrict__ vH)
{
    __shared__ __half tH[32][33];
    const int z = blockIdx.z, b = z >> 4, h = z & 15;
    const int s0 = blockIdx.x * 32, d0 = blockIdx.y * 32;
    const int tx = threadIdx.x & 31, ty = threadIdx.x >> 5;
    const size_t ibase = (size_t)b * SEQ * QKVW + (size_t)h * 384 + 256;
    #pragma unroll
    for (int i = 0; i < 4; i++) {
        int s = s0 + ty + i * 8;
        tH[ty + i * 8][tx] = qH[ibase + (size_t)s * QKVW + d0 + tx];
    }
    __syncthreads();
    const size_t obase = (size_t)z * HD * SEQ;
    #pragma unroll
    for (int i = 0; i < 4; i++) {
        int d = d0 + ty + i * 8;
        vH[obase + (size_t)d * SEQ + s0 + tx] = tH[tx][ty + i * 8];
    }
}

// ---------------------------------------------------------------------------
extern "C" void kernel_launch(void* const* d_in, const int* in_sizes, int n_in,
                              void* d_out, int out_size)
{
    const float* x     = (const float*)d_in[0];
    const float* w_qkv = (const float*)d_in[2];
    const float* b_qkv = (const float*)d_in[3];
    const float* w_o   = (const float*)d_in[4];
    const float* b_o   = (const float*)d_in[5];
    float* out = (float*)d_out;

    __half *xsH, *wqH, *woH, *qkH, *vtH, *atH;
    cudaGetSymbolAddress((void**)&xsH, g_xsHi);
    cudaGetSymbolAddress((void**)&wqH, g_wqHi);
    cudaGetSymbolAddress((void**)&woH, g_woHi);
    cudaGetSymbolAddress((void**)&qkH, g_qkvHi);
    cudaGetSymbolAddress((void**)&vtH, g_vtHi);
    cudaGetSymbolAddress((void**)&atH, g_atHi);

    cudaFuncSetAttribute(tc_gemm<true,  true >, cudaFuncAttributeMaxDynamicSharedMemorySize, SMEM_G);
    cudaFuncSetAttribute(tc_gemm<false, true >, cudaFuncAttributeMaxDynamicSharedMemorySize, SMEM_G);
    cudaFuncSetAttribute(flash_kernel, cudaFuncAttributeMaxDynamicSharedMemorySize, FSMEM);

    // 0) truncate inputs to fp16
    trunc_kernel<<<(long)BATCH*SEQ*DMODEL/1024, 256>>>(x,     xsH);
    trunc_kernel<<<(long)QKVW*DMODEL/1024,      256>>>(w_qkv, wqH);
    trunc_kernel<<<(long)DMODEL*DMODEL/1024,    256>>>(w_o,   woH);

    // 1) QKV projection -> qkv fp16 (bias fused)
    {
        dim3 grid(QKVW / 128, (BATCH * SEQ) / 128, 1);
        tc_gemm<true, true><<<grid, 256, SMEM_G>>>(
            xsH, wqH, b_qkv, nullptr, qkH,
            DMODEL, DMODEL, DMODEL, QKVW,
            0, 0, 0, 0, 0, 0, 1, 1.0f);
    }

    // 2) V transpose -> Vt fp16
    transpose_v<<<dim3(SEQ / 32, HD / 32, BH), 256>>>(qkH, vtH);

    // 3) fused flash attention -> attn fp16
    flash_kernel<<<dim3(SEQ / 128, BH), 256, FSMEM>>>(qkH, vtH, atH);

    // 4) output projection (bias fused) -> out fp32
    {
        dim3 grid(DMODEL / 128, (BATCH * SEQ) / 128, 1);
        tc_gemm<false, true><<<grid, 256, SMEM_G>>>(
            atH, woH, b_o, out, nullptr,
            DMODEL, DMODEL, DMODEL, DMODEL,
            0, 0, 0, 0, 0, 0, 1, 1.0f);
    }
}